// round 1
// baseline (speedup 1.0000x reference)
#include <cuda_runtime.h>
#include <cuda_bf16.h>
#include <cstdint>

// Problem constants
#define Bc   256
#define Nn   196
#define Cc   256
#define Hh   8
#define KDc  32
#define VDc  64
#define Qq   49
#define EPSc 1e-5f
#define SCALEc 0.17677669529663689f  // 32^-0.5

// Scratch (device globals; no runtime allocation allowed)
__device__ float g_k[Bc * Hh * KDc * Nn];     // [b,h,d,n]
__device__ float g_v[Bc * Hh * Nn * VDc];     // [b,h,n,d]
__device__ float g_q[Bc * Hh * Qq * KDc];     // [b,h,q,d]
__device__ float g_aout[Bc * Qq * (Hh*VDc)];  // [b,q, h*64+vc] (hardswish applied)

typedef unsigned long long u64;

__device__ __forceinline__ u64 pack2(float lo, float hi) {
    u64 r; asm("mov.b64 %0, {%1,%2};" : "=l"(r) : "f"(lo), "f"(hi)); return r;
}
__device__ __forceinline__ void fma2(u64 &acc, u64 a, u64 b) {
    asm("fma.rn.f32x2 %0, %1, %2, %0;" : "+l"(acc) : "l"(a), "l"(b));
}
__device__ __forceinline__ float2 unpack2(u64 v) {
    float2 r; asm("mov.b64 {%0,%1}, %2;" : "=f"(r.x), "=f"(r.y) : "l"(v)); return r;
}

// ---------------------------------------------------------------------------
// Fused GEMM + linear_norm epilogue.
//  out[m,j] = dot(A[m,:], W[j,:]) * inv[j] + (b[j] - m[j]*inv[j])
// MODE 0: A = x rows direct, scatter to g_k / g_v
// MODE 1: A = x rows gathered (::2,::2 subsample), scatter to g_q
// MODE 2: A = g_aout direct, write d_out [m*384 + j]
// Tiles: BM=BN=128, BK=16, 256 threads, 8x8 per thread, f32x2 accumulators.
// All dims divide exactly (M: 50176/12544, N: 768/256/384, K: 256/512).
// ---------------------------------------------------------------------------
template <int KDIM, int MODE>
__global__ __launch_bounds__(256)
void gemm_norm_kernel(const float* __restrict__ A,
                      const float* __restrict__ W,
                      const float* __restrict__ gg,
                      const float* __restrict__ bb,
                      const float* __restrict__ mm,
                      const float* __restrict__ vv,
                      float* __restrict__ Out)
{
    __shared__ float As[16][136];
    __shared__ float Bs[16][136];
    __shared__ int rowoff[128];

    const int tid = threadIdx.x;
    const int tx = tid & 15;
    const int ty = tid >> 4;
    const int m0 = blockIdx.x * 128;
    const int n0 = blockIdx.y * 128;

    const float* Abase = (MODE == 2) ? (const float*)g_aout : A;

    if (tid < 128) {
        int m = m0 + tid;
        int off;
        if (MODE == 1) {
            int b = m / Qq, qq = m % Qq;
            int n = (qq / 7) * 28 + (qq % 7) * 2;   // (2*qi)*14 + 2*qj
            off = (b * Nn + n) * KDIM;
        } else {
            off = m * KDIM;
        }
        rowoff[tid] = off;
    }
    __syncthreads();

    u64 acc2[8][4];
#pragma unroll
    for (int i = 0; i < 8; i++)
#pragma unroll
        for (int jp = 0; jp < 4; jp++) acc2[i][jp] = 0ull;

    for (int k0 = 0; k0 < KDIM; k0 += 16) {
        // Load A tile (128 rows x 16 k) -> As[k][row]
#pragma unroll
        for (int l = 0; l < 2; l++) {
            int v = tid + l * 256;
            int row = v >> 2, kq = v & 3;
            float4 t = *reinterpret_cast<const float4*>(Abase + rowoff[row] + k0 + kq * 4);
            As[kq * 4 + 0][row] = t.x;
            As[kq * 4 + 1][row] = t.y;
            As[kq * 4 + 2][row] = t.z;
            As[kq * 4 + 3][row] = t.w;
        }
        // Load W tile (128 n-rows x 16 k) -> Bs[k][n]
#pragma unroll
        for (int l = 0; l < 2; l++) {
            int v = tid + l * 256;
            int row = v >> 2, kq = v & 3;
            float4 t = *reinterpret_cast<const float4*>(W + (size_t)(n0 + row) * KDIM + k0 + kq * 4);
            Bs[kq * 4 + 0][row] = t.x;
            Bs[kq * 4 + 1][row] = t.y;
            Bs[kq * 4 + 2][row] = t.z;
            Bs[kq * 4 + 3][row] = t.w;
        }
        __syncthreads();

#pragma unroll
        for (int kk = 0; kk < 16; kk++) {
            float4 a0 = *reinterpret_cast<const float4*>(&As[kk][ty * 8]);
            float4 a1 = *reinterpret_cast<const float4*>(&As[kk][ty * 8 + 4]);
            float4 b0 = *reinterpret_cast<const float4*>(&Bs[kk][tx * 8]);
            float4 b1 = *reinterpret_cast<const float4*>(&Bs[kk][tx * 8 + 4]);
            u64 bbp[4];
            bbp[0] = pack2(b0.x, b0.y);
            bbp[1] = pack2(b0.z, b0.w);
            bbp[2] = pack2(b1.x, b1.y);
            bbp[3] = pack2(b1.z, b1.w);
            float av[8] = {a0.x, a0.y, a0.z, a0.w, a1.x, a1.y, a1.z, a1.w};
#pragma unroll
            for (int i = 0; i < 8; i++) {
                u64 aa = pack2(av[i], av[i]);
#pragma unroll
                for (int jp = 0; jp < 4; jp++) fma2(acc2[i][jp], aa, bbp[jp]);
            }
        }
        __syncthreads();
    }

    // Epilogue: linear_norm per output column + scatter
    float invj[8], shj[8];
#pragma unroll
    for (int j = 0; j < 8; j++) {
        int jj = n0 + tx * 8 + j;
        float inv = gg[jj] * rsqrtf(vv[jj] + EPSc);
        invj[j] = inv;
        shj[j]  = bb[jj] - mm[jj] * inv;
    }

#pragma unroll
    for (int i = 0; i < 8; i++) {
        int m = m0 + ty * 8 + i;
#pragma unroll
        for (int jp = 0; jp < 4; jp++) {
            float2 vpair = unpack2(acc2[i][jp]);
#pragma unroll
            for (int c = 0; c < 2; c++) {
                int j = jp * 2 + c;
                int jj = n0 + tx * 8 + j;
                float val = (c == 0 ? vpair.x : vpair.y) * invj[j] + shj[j];
                if (MODE == 0) {
                    int b = m / Nn, n = m % Nn;
                    int h = jj / 96, cch = jj % 96;
                    if (cch < KDc)
                        g_k[((b * Hh + h) * KDc + cch) * Nn + n] = val;
                    else
                        g_v[((b * Hh + h) * Nn + n) * VDc + (cch - KDc)] = val;
                } else if (MODE == 1) {
                    int b = m / Qq, qq = m % Qq;
                    int h = jj >> 5, d = jj & 31;
                    g_q[((b * Hh + h) * Qq + qq) * KDc + d] = val;
                } else {
                    Out[(size_t)m * 384 + jj] = val;
                }
            }
        }
    }
}

// ---------------------------------------------------------------------------
// Attention: one block per (b,h). 512 threads.
// smem: qs[49*32] ks[32*196] vs[196*64] sc[196*52] (transposed, padded) bs[196]
// ---------------------------------------------------------------------------
#define SC_PAD 52
#define ATTN_SMEM_FLOATS (1568 + 6272 + 12544 + 196*SC_PAD + 196)

__global__ __launch_bounds__(512)
void attn_kernel(const float* __restrict__ attn_bias)
{
    extern __shared__ float sm[];
    float* qs = sm;                    // 1568
    float* ks = qs + 1568;             // 6272
    float* vs = ks + 6272;             // 12544
    float* sc = vs + 12544;            // 196*52 = 10192, layout sc[kc*52 + qr]
    float* bs = sc + 196 * SC_PAD;     // 196

    const int blk = blockIdx.x;
    const int b = blk >> 3, h = blk & 7;
    const int tid = threadIdx.x;

    const float* qg = g_q + (size_t)(b * Hh + h) * (Qq * KDc);
    const float* kg = g_k + (size_t)(b * Hh + h) * (KDc * Nn);
    const float* vg = g_v + (size_t)(b * Hh + h) * (Nn * VDc);

    for (int i = tid; i < 1568;  i += 512) qs[i] = qg[i];
    for (int i = tid; i < 6272;  i += 512) ks[i] = kg[i];
    for (int i = tid; i < 12544; i += 512) vs[i] = vg[i];
    for (int i = tid; i < 196;   i += 512) bs[i] = attn_bias[h * Nn + i];
    for (int i = tid; i < 196 * SC_PAD; i += 512) sc[i] = 0.0f;
    __syncthreads();

    // ---- scores: tile 2 q-rows x 4 k-cols per work item (25 x 49 = 1225 items)
    for (int gi = tid; gi < 1225; gi += 512) {
        int qr2 = gi / 49;
        int kc4 = gi - qr2 * 49;
        int qr0 = qr2 * 2;
        bool has2 = (qr0 + 1) < Qq;
        const float* q0p = qs + qr0 * KDc;
        const float* q1p = qs + (has2 ? (qr0 + 1) : qr0) * KDc;
        float acc0x = 0, acc0y = 0, acc0z = 0, acc0w = 0;
        float acc1x = 0, acc1y = 0, acc1z = 0, acc1w = 0;
#pragma unroll
        for (int d = 0; d < KDc; d++) {
            float4 k4 = *reinterpret_cast<const float4*>(ks + d * Nn + kc4 * 4);
            float q0 = q0p[d], q1 = q1p[d];
            acc0x += q0 * k4.x; acc0y += q0 * k4.y; acc0z += q0 * k4.z; acc0w += q0 * k4.w;
            acc1x += q1 * k4.x; acc1y += q1 * k4.y; acc1z += q1 * k4.z; acc1w += q1 * k4.w;
        }
        int qi0 = qr0 / 7, qj0 = qr0 % 7;
        int qi1 = (qr0 + 1) / 7, qj1 = (qr0 + 1) % 7;
        float a0[4] = {acc0x, acc0y, acc0z, acc0w};
        float a1[4] = {acc1x, acc1y, acc1z, acc1w};
#pragma unroll
        for (int c = 0; c < 4; c++) {
            int kc = kc4 * 4 + c;
            int ki = kc / 14, kj = kc % 14;
            int r00 = abs(2 * qi0 - ki), r01 = abs(2 * qj0 - kj);
            sc[kc * SC_PAD + qr0] = a0[c] * SCALEc + bs[r00 * 14 + r01];
            if (has2) {
                int r10 = abs(2 * qi1 - ki), r11 = abs(2 * qj1 - kj);
                sc[kc * SC_PAD + qr0 + 1] = a1[c] * SCALEc + bs[r10 * 14 + r11];
            }
        }
    }
    __syncthreads();

    // ---- softmax over kc (stride SC_PAD), one warp per row
    const int wid = tid >> 5, lane = tid & 31;
    for (int row = wid; row < Qq; row += 16) {
        float mx = -1e30f;
        for (int c = lane; c < Nn; c += 32)
            mx = fmaxf(mx, sc[c * SC_PAD + row]);
#pragma unroll
        for (int o = 16; o > 0; o >>= 1)
            mx = fmaxf(mx, __shfl_xor_sync(0xffffffffu, mx, o));
        float sum = 0.0f;
        for (int c = lane; c < Nn; c += 32) {
            float e = __expf(sc[c * SC_PAD + row] - mx);
            sc[c * SC_PAD + row] = e;
            sum += e;
        }
#pragma unroll
        for (int o = 16; o > 0; o >>= 1)
            sum += __shfl_xor_sync(0xffffffffu, sum, o);
        float rinv = 1.0f / sum;
        for (int c = lane; c < Nn; c += 32)
            sc[c * SC_PAD + row] *= rinv;
    }
    __syncthreads();

    // ---- out = attn @ v, hardswish, store. 4 rows x 2 vc per item (13*32=416 items)
    if (tid < 416) {
        int r4 = tid >> 5;       // 0..12 -> rows 4*r4 .. 4*r4+3
        int vc2 = tid & 31;      // float2 column pair
        float acc00 = 0, acc01 = 0, acc10 = 0, acc11 = 0;
        float acc20 = 0, acc21 = 0, acc30 = 0, acc31 = 0;
        for (int n = 0; n < Nn; n++) {
            float4 s4 = *reinterpret_cast<const float4*>(sc + n * SC_PAD + r4 * 4);
            float2 v2 = *reinterpret_cast<const float2*>(vs + n * VDc + vc2 * 2);
            acc00 += s4.x * v2.x; acc01 += s4.x * v2.y;
            acc10 += s4.y * v2.x; acc11 += s4.y * v2.y;
            acc20 += s4.z * v2.x; acc21 += s4.z * v2.y;
            acc30 += s4.w * v2.x; acc31 += s4.w * v2.y;
        }
        float accs[4][2] = {{acc00, acc01}, {acc10, acc11}, {acc20, acc21}, {acc30, acc31}};
#pragma unroll
        for (int rr = 0; rr < 4; rr++) {
            int qr = r4 * 4 + rr;
            if (qr < Qq) {
#pragma unroll
                for (int cc = 0; cc < 2; cc++) {
                    float o = accs[rr][cc];
                    float hs = o * fminf(fmaxf(o + 3.0f, 0.0f), 6.0f) * (1.0f / 6.0f);
                    g_aout[((size_t)(b * Qq + qr)) * 512 + h * VDc + vc2 * 2 + cc] = hs;
                }
            }
        }
    }
}

// ---------------------------------------------------------------------------
extern "C" void kernel_launch(void* const* d_in, const int* in_sizes, int n_in,
                              void* d_out, int out_size)
{
    const float* x      = (const float*)d_in[0];
    const float* kv_w   = (const float*)d_in[1];
    const float* kv_g   = (const float*)d_in[2];
    const float* kv_b   = (const float*)d_in[3];
    const float* kv_m   = (const float*)d_in[4];
    const float* kv_v   = (const float*)d_in[5];
    const float* q_w    = (const float*)d_in[6];
    const float* q_g    = (const float*)d_in[7];
    const float* q_b    = (const float*)d_in[8];
    const float* q_m    = (const float*)d_in[9];
    const float* q_v    = (const float*)d_in[10];
    const float* proj_w = (const float*)d_in[11];
    const float* proj_g = (const float*)d_in[12];
    const float* proj_b = (const float*)d_in[13];
    const float* proj_m = (const float*)d_in[14];
    const float* proj_v = (const float*)d_in[15];
    const float* attn_bias = (const float*)d_in[16];
    float* out = (float*)d_out;

    // kv GEMM: M=50176, N=768, K=256
    gemm_norm_kernel<256, 0><<<dim3(392, 6), 256>>>(x, kv_w, kv_g, kv_b, kv_m, kv_v, nullptr);
    // q GEMM (gathered): M=12544, N=256, K=256
    gemm_norm_kernel<256, 1><<<dim3(98, 2), 256>>>(x, q_w, q_g, q_b, q_m, q_v, nullptr);

    // attention: 2048 blocks, ~120 KB dynamic smem
    size_t shmem = (size_t)ATTN_SMEM_FLOATS * sizeof(float);
    cudaFuncSetAttribute(attn_kernel, cudaFuncAttributeMaxDynamicSharedMemorySize, (int)shmem);
    attn_kernel<<<Bc * Hh, 512, shmem>>>(attn_bias);

    // proj GEMM: M=12544, N=384, K=512
    gemm_norm_kernel<512, 2><<<dim3(98, 3), 256>>>(nullptr, proj_w, proj_g, proj_b, proj_m, proj_v, out);
}

// round 3
// speedup vs baseline: 1.3387x; 1.3387x over previous
#include <cuda_runtime.h>
#include <cuda_bf16.h>
#include <mma.h>
#include <cstdint>

using namespace nvcuda;

// ---------------- problem constants ----------------
#define Bc   256
#define Nn   196
#define Hh   8
#define KDc  32
#define VDc  64
#define Qq   49
#define EPSc 1e-5f
#define SCALEc 0.17677669529663689f  // 32^-0.5

// ---------------- device scratch (no runtime alloc allowed) ----------------
__device__ float g_k[Bc * Hh * KDc * Nn];     // [b,h,d,n]
__device__ float g_v[Bc * Hh * Nn * VDc];     // [b,h,n,d]
__device__ float g_q[Bc * Hh * Qq * KDc];     // [b,h,q,d]
__device__ float g_aout[Bc * Qq * (Hh*VDc)];  // [b,q, h*64+vc], hardswish applied

// ---------------- smem layout (bytes) ----------------
#define TSTRIDE 40                     // bf16 elements per tile row (32 + 8 pad)
#define OFF_ROW   64                   // int rowoff[128]
#define OFF_INV   576                  // float sInv[128]
#define OFF_SH    1088                 // float sShift[128]
#define OFF_AHI   2048
#define OFF_ALO   (OFF_AHI + 128*TSTRIDE*2)     // +10240
#define OFF_BHI   (OFF_ALO + 128*TSTRIDE*2)
#define OFF_BLO   (OFF_BHI + 128*TSTRIDE*2)
#define OFF_STAGE 2048                 // float S[128][132] overlays tiles
#define SSTRIDE   132
#define GEMM_SMEM_BYTES (2048 + 128*SSTRIDE*4)  // 69632 >= 2048+4*10240=43008

// split fp32 -> bf16 hi/lo, store 4 consecutive elements (as two uint2 halves)
__device__ __forceinline__ void cvt_split_store4(__nv_bfloat16* hi, __nv_bfloat16* lo,
                                                 int row, int k, float4 t) {
    int e = row * TSTRIDE + k;
    float hx = __bfloat162float(__float2bfloat16_rn(t.x));
    float hy = __bfloat162float(__float2bfloat16_rn(t.y));
    float hz = __bfloat162float(__float2bfloat16_rn(t.z));
    float hw = __bfloat162float(__float2bfloat16_rn(t.w));
    __nv_bfloat162 h01 = __floats2bfloat162_rn(hx, hy);
    __nv_bfloat162 h23 = __floats2bfloat162_rn(hz, hw);
    __nv_bfloat162 l01 = __floats2bfloat162_rn(t.x - hx, t.y - hy);
    __nv_bfloat162 l23 = __floats2bfloat162_rn(t.z - hz, t.w - hw);
    *reinterpret_cast<__nv_bfloat162*>(hi + e)     = h01;
    *reinterpret_cast<__nv_bfloat162*>(hi + e + 2) = h23;
    *reinterpret_cast<__nv_bfloat162*>(lo + e)     = l01;
    *reinterpret_cast<__nv_bfloat162*>(lo + e + 2) = l23;
}

// ---------------------------------------------------------------------------
// wmma bf16 split GEMM + linear_norm epilogue.
//  out[m,j] = dot(A[m,:], W[j,:]) * inv[j] + (b[j] - m[j]*inv[j])
// MODE 0: A = x direct, scatter to g_k/g_v.  MODE 1: A = x gathered -> g_q.
// MODE 2: A = g_aout -> Out.
// ---------------------------------------------------------------------------
template <int KDIM, int MODE>
__global__ __launch_bounds__(256)
void tgemm_kernel(const float* __restrict__ A,
                  const float* __restrict__ W,
                  const float* __restrict__ gg,
                  const float* __restrict__ bb,
                  const float* __restrict__ mm,
                  const float* __restrict__ vv,
                  float* __restrict__ Out)
{
    extern __shared__ char sm[];
    int*   rowoff = (int*)(sm + OFF_ROW);
    float* sInv   = (float*)(sm + OFF_INV);
    float* sSh    = (float*)(sm + OFF_SH);
    float* S      = (float*)(sm + OFF_STAGE);
    __nv_bfloat16* Ah = (__nv_bfloat16*)(sm + OFF_AHI);
    __nv_bfloat16* Al = (__nv_bfloat16*)(sm + OFF_ALO);
    __nv_bfloat16* Bh = (__nv_bfloat16*)(sm + OFF_BHI);
    __nv_bfloat16* Bl = (__nv_bfloat16*)(sm + OFF_BLO);

    const int tid = threadIdx.x;
    const int wid = tid >> 5;
    const int m0 = blockIdx.x * 128;
    const int n0 = blockIdx.y * 128;

    const float* Abase = (MODE == 2) ? (const float*)g_aout : A;

    if (tid < 128) {
        int m = m0 + tid;
        int off;
        if (MODE == 1) {
            int b = m / Qq, qq = m % Qq;
            int n = (qq / 7) * 28 + (qq % 7) * 2;   // (2*qi)*14 + 2*qj
            off = (b * Nn + n) * KDIM;
        } else {
            off = m * KDIM;
        }
        rowoff[tid] = off;
        int jj = n0 + tid;
        float inv = gg[jj] * rsqrtf(vv[jj] + EPSc);
        sInv[tid] = inv;
        sSh[tid]  = bb[jj] - mm[jj] * inv;
    }
    __syncthreads();

    // warp tiling: 4 (M) x 2 (N); warp tile 32 x 64
    const int wm0 = (wid & 3) * 32;
    const int wn0 = (wid >> 2) * 64;

    wmma::fragment<wmma::accumulator, 16, 16, 16, float> acc[2][4];
#pragma unroll
    for (int i = 0; i < 2; i++)
#pragma unroll
        for (int j = 0; j < 4; j++) wmma::fill_fragment(acc[i][j], 0.0f);

    const int ldrow = tid >> 1;            // 0..127
    const int ldk0  = (tid & 1) * 16;      // 0 or 16

    for (int k0 = 0; k0 < KDIM; k0 += 32) {
        // load + split-convert A and B tiles (128 x 32 fp32 each)
#pragma unroll
        for (int j = 0; j < 4; j++) {
            int k = ldk0 + j * 4;
            float4 ta = *reinterpret_cast<const float4*>(Abase + rowoff[ldrow] + k0 + k);
            cvt_split_store4(Ah, Al, ldrow, k, ta);
            float4 tb = *reinterpret_cast<const float4*>(W + (size_t)(n0 + ldrow) * KDIM + k0 + k);
            cvt_split_store4(Bh, Bl, ldrow, k, tb);
        }
        __syncthreads();

#pragma unroll
        for (int kk = 0; kk < 32; kk += 16) {
            wmma::fragment<wmma::matrix_a, 16, 16, 16, __nv_bfloat16, wmma::row_major> ah[2], al[2];
            wmma::fragment<wmma::matrix_b, 16, 16, 16, __nv_bfloat16, wmma::col_major> bh[4], bl[4];
#pragma unroll
            for (int i = 0; i < 2; i++) {
                wmma::load_matrix_sync(ah[i], Ah + (wm0 + i * 16) * TSTRIDE + kk, TSTRIDE);
                wmma::load_matrix_sync(al[i], Al + (wm0 + i * 16) * TSTRIDE + kk, TSTRIDE);
            }
#pragma unroll
            for (int j = 0; j < 4; j++) {
                wmma::load_matrix_sync(bh[j], Bh + (wn0 + j * 16) * TSTRIDE + kk, TSTRIDE);
                wmma::load_matrix_sync(bl[j], Bl + (wn0 + j * 16) * TSTRIDE + kk, TSTRIDE);
            }
#pragma unroll
            for (int i = 0; i < 2; i++)
#pragma unroll
                for (int j = 0; j < 4; j++) {
                    wmma::mma_sync(acc[i][j], ah[i], bh[j], acc[i][j]);
                    wmma::mma_sync(acc[i][j], ah[i], bl[j], acc[i][j]);
                    wmma::mma_sync(acc[i][j], al[i], bh[j], acc[i][j]);
                }
        }
        __syncthreads();
    }

    // stage raw accumulators to smem (overlays tiles; synced above)
#pragma unroll
    for (int i = 0; i < 2; i++)
#pragma unroll
        for (int j = 0; j < 4; j++)
            wmma::store_matrix_sync(S + (wm0 + i * 16) * SSTRIDE + wn0 + j * 16,
                                    acc[i][j], SSTRIDE, wmma::mem_row_major);
    __syncthreads();

    // coalesced scatter with linear_norm applied
    if (MODE == 0) {
        // pass K: lanes sweep m (n-contiguous in g_k)
        for (int idx = tid; idx < 16384; idx += 256) {
            int col = idx >> 7, mrow = idx & 127;
            int jj = n0 + col, cch = jj % 96;
            if (cch < KDc) {
                int m = m0 + mrow;
                int b = m / Nn, n = m % Nn;
                int h = jj / 96;
                g_k[((b * Hh + h) * KDc + cch) * Nn + n] =
                    S[mrow * SSTRIDE + col] * sInv[col] + sSh[col];
            }
        }
        // pass V: lanes sweep jj (d-contiguous in g_v)
        for (int idx = tid; idx < 16384; idx += 256) {
            int mrow = idx >> 7, col = idx & 127;
            int jj = n0 + col, cch = jj % 96;
            if (cch >= KDc) {
                int m = m0 + mrow;
                int b = m / Nn, n = m % Nn;
                int h = jj / 96;
                g_v[((b * Hh + h) * Nn + n) * VDc + (cch - KDc)] =
                    S[mrow * SSTRIDE + col] * sInv[col] + sSh[col];
            }
        }
    } else if (MODE == 1) {
        for (int idx = tid; idx < 16384; idx += 256) {
            int mrow = idx >> 7, col = idx & 127;
            int jj = n0 + col;
            int m = m0 + mrow;
            int b = m / Qq, qq = m % Qq;
            int h = jj >> 5, d = jj & 31;
            g_q[((b * Hh + h) * Qq + qq) * KDc + d] =
                S[mrow * SSTRIDE + col] * sInv[col] + sSh[col];
        }
    } else {
        for (int idx = tid; idx < 16384; idx += 256) {
            int mrow = idx >> 7, col = idx & 127;
            Out[(size_t)(m0 + mrow) * 384 + n0 + col] =
                S[mrow * SSTRIDE + col] * sInv[col] + sSh[col];
        }
    }
}

// ---------------------------------------------------------------------------
// Attention: one block per (b,h), 512 threads.
// ---------------------------------------------------------------------------
#define SC_PAD 52
#define ATTN_SMEM_FLOATS (1568 + 6272 + 12544 + 196*SC_PAD + 196)

__global__ __launch_bounds__(512)
void attn_kernel(const float* __restrict__ attn_bias)
{
    extern __shared__ float smf[];
    float* qs = smf;                   // 49*32
    float* ks = qs + 1568;             // 32*196
    float* vs = ks + 6272;             // 196*64
    float* sc = vs + 12544;            // [kc][qr] padded to 52
    float* bs = sc + 196 * SC_PAD;     // 196

    const int blk = blockIdx.x;
    const int b = blk >> 3, h = blk & 7;
    const int tid = threadIdx.x;

    const float* qg = g_q + (size_t)(b * Hh + h) * (Qq * KDc);
    const float* kg = g_k + (size_t)(b * Hh + h) * (KDc * Nn);
    const float* vg = g_v + (size_t)(b * Hh + h) * (Nn * VDc);

    for (int i = tid; i < 1568;  i += 512) qs[i] = qg[i];
    for (int i = tid; i < 6272;  i += 512) ks[i] = kg[i];
    for (int i = tid; i < 12544; i += 512) vs[i] = vg[i];
    for (int i = tid; i < 196;   i += 512) bs[i] = attn_bias[h * Nn + i];
    for (int i = tid; i < 196 * SC_PAD; i += 512) sc[i] = 0.0f;
    __syncthreads();

    // scores: 4 q-rows x 4 k-cols per item; 13*49 = 637 items
    for (int gi = tid; gi < 637; gi += 512) {
        int qg4 = gi / 49;
        int kc4 = gi - qg4 * 49;
        int qr0 = qg4 * 4;
        int r1 = min(qr0 + 1, Qq - 1);
        int r2 = min(qr0 + 2, Qq - 1);
        int r3 = min(qr0 + 3, Qq - 1);
        float acc[4][4];
#pragma unroll
        for (int i = 0; i < 4; i++)
#pragma unroll
            for (int j = 0; j < 4; j++) acc[i][j] = 0.0f;
#pragma unroll
        for (int d = 0; d < KDc; d++) {
            float4 k4 = *reinterpret_cast<const float4*>(ks + d * Nn + kc4 * 4);
            float q0 = qs[qr0 * KDc + d];
            float q1 = qs[r1 * KDc + d];
            float q2 = qs[r2 * KDc + d];
            float q3 = qs[r3 * KDc + d];
            acc[0][0] += q0 * k4.x; acc[0][1] += q0 * k4.y; acc[0][2] += q0 * k4.z; acc[0][3] += q0 * k4.w;
            acc[1][0] += q1 * k4.x; acc[1][1] += q1 * k4.y; acc[1][2] += q1 * k4.z; acc[1][3] += q1 * k4.w;
            acc[2][0] += q2 * k4.x; acc[2][1] += q2 * k4.y; acc[2][2] += q2 * k4.z; acc[2][3] += q2 * k4.w;
            acc[3][0] += q3 * k4.x; acc[3][1] += q3 * k4.y; acc[3][2] += q3 * k4.z; acc[3][3] += q3 * k4.w;
        }
#pragma unroll
        for (int i = 0; i < 4; i++) {
            int qr = qr0 + i;
            if (qr < Qq) {
                int qi = qr / 7, qj = qr % 7;
#pragma unroll
                for (int cc = 0; cc < 4; cc++) {
                    int kc = kc4 * 4 + cc;
                    int ki = kc / 14, kj = kc % 14;
                    int r0 = abs(2 * qi - ki), rr1 = abs(2 * qj - kj);
                    sc[kc * SC_PAD + qr] = acc[i][cc] * SCALEc + bs[r0 * 14 + rr1];
                }
            }
        }
    }
    __syncthreads();

    // softmax over kc, one warp per q-row
    const int wid = tid >> 5, lane = tid & 31;
    for (int row = wid; row < Qq; row += 16) {
        float mx = -1e30f;
        for (int c = lane; c < Nn; c += 32)
            mx = fmaxf(mx, sc[c * SC_PAD + row]);
#pragma unroll
        for (int o = 16; o > 0; o >>= 1)
            mx = fmaxf(mx, __shfl_xor_sync(0xffffffffu, mx, o));
        float sum = 0.0f;
        for (int c = lane; c < Nn; c += 32) {
            float e = __expf(sc[c * SC_PAD + row] - mx);
            sc[c * SC_PAD + row] = e;
            sum += e;
        }
#pragma unroll
        for (int o = 16; o > 0; o >>= 1)
            sum += __shfl_xor_sync(0xffffffffu, sum, o);
        float rinv = 1.0f / sum;
        for (int c = lane; c < Nn; c += 32)
            sc[c * SC_PAD + row] *= rinv;
    }
    __syncthreads();

    // out = attn @ v: 4 q-rows x 4 v-cols per thread; 13*16 = 208 threads
    if (tid < 208) {
        int r4 = tid >> 4;     // 0..12
        int vq = tid & 15;     // float4 col group
        float a[4][4];
#pragma unroll
        for (int i = 0; i < 4; i++)
#pragma unroll
            for (int j = 0; j < 4; j++) a[i][j] = 0.0f;
        for (int n = 0; n < Nn; n++) {
            float4 s4 = *reinterpret_cast<const float4*>(sc + n * SC_PAD + r4 * 4);
            float4 v4 = *reinterpret_cast<const float4*>(vs + n * VDc + vq * 4);
            a[0][0] += s4.x * v4.x; a[0][1] += s4.x * v4.y; a[0][2] += s4.x * v4.z; a[0][3] += s4.x * v4.w;
            a[1][0] += s4.y * v4.x; a[1][1] += s4.y * v4.y; a[1][2] += s4.y * v4.z; a[1][3] += s4.y * v4.w;
            a[2][0] += s4.z * v4.x; a[2][1] += s4.z * v4.y; a[2][2] += s4.z * v4.z; a[2][3] += s4.z * v4.w;
            a[3][0] += s4.w * v4.x; a[3][1] += s4.w * v4.y; a[3][2] += s4.w * v4.z; a[3][3] += s4.w * v4.w;
        }
#pragma unroll
        for (int i = 0; i < 4; i++) {
            int qr = r4 * 4 + i;
            if (qr < Qq) {
                float4 o;
                float t0 = a[i][0], t1 = a[i][1], t2 = a[i][2], t3 = a[i][3];
                o.x = t0 * fminf(fmaxf(t0 + 3.0f, 0.0f), 6.0f) * (1.0f / 6.0f);
                o.y = t1 * fminf(fmaxf(t1 + 3.0f, 0.0f), 6.0f) * (1.0f / 6.0f);
                o.z = t2 * fminf(fmaxf(t2 + 3.0f, 0.0f), 6.0f) * (1.0f / 6.0f);
                o.w = t3 * fminf(fmaxf(t3 + 3.0f, 0.0f), 6.0f) * (1.0f / 6.0f);
                *reinterpret_cast<float4*>(g_aout + ((size_t)(b * Qq + qr)) * 512 + h * VDc + vq * 4) = o;
            }
        }
    }
}

// ---------------------------------------------------------------------------
extern "C" void kernel_launch(void* const* d_in, const int* in_sizes, int n_in,
                              void* d_out, int out_size)
{
    const float* x      = (const float*)d_in[0];
    const float* kv_w   = (const float*)d_in[1];
    const float* kv_g   = (const float*)d_in[2];
    const float* kv_b   = (const float*)d_in[3];
    const float* kv_m   = (const float*)d_in[4];
    const float* kv_v   = (const float*)d_in[5];
    const float* q_w    = (const float*)d_in[6];
    const float* q_g    = (const float*)d_in[7];
    const float* q_b    = (const float*)d_in[8];
    const float* q_m    = (const float*)d_in[9];
    const float* q_v    = (const float*)d_in[10];
    const float* proj_w = (const float*)d_in[11];
    const float* proj_g = (const float*)d_in[12];
    const float* proj_b = (const float*)d_in[13];
    const float* proj_m = (const float*)d_in[14];
    const float* proj_v = (const float*)d_in[15];
    const float* attn_bias = (const float*)d_in[16];
    float* out = (float*)d_out;

    cudaFuncSetAttribute(tgemm_kernel<256, 0>, cudaFuncAttributeMaxDynamicSharedMemorySize, GEMM_SMEM_BYTES);
    cudaFuncSetAttribute(tgemm_kernel<256, 1>, cudaFuncAttributeMaxDynamicSharedMemorySize, GEMM_SMEM_BYTES);
    cudaFuncSetAttribute(tgemm_kernel<512, 2>, cudaFuncAttributeMaxDynamicSharedMemorySize, GEMM_SMEM_BYTES);

    // kv GEMM: M=50176, N=768, K=256
    tgemm_kernel<256, 0><<<dim3(392, 6), 256, GEMM_SMEM_BYTES>>>(x, kv_w, kv_g, kv_b, kv_m, kv_v, nullptr);
    // q GEMM (gathered rows): M=12544, N=256, K=256
    tgemm_kernel<256, 1><<<dim3(98, 2), 256, GEMM_SMEM_BYTES>>>(x, q_w, q_g, q_b, q_m, q_v, nullptr);

    // attention
    size_t shmem = (size_t)ATTN_SMEM_FLOATS * sizeof(float);
    cudaFuncSetAttribute(attn_kernel, cudaFuncAttributeMaxDynamicSharedMemorySize, (int)shmem);
    attn_kernel<<<Bc * Hh, 512, shmem>>>(attn_bias);

    // proj GEMM: M=12544, N=384, K=512
    tgemm_kernel<512, 2><<<dim3(98, 3), 256, GEMM_SMEM_BYTES>>>(nullptr, proj_w, proj_g, proj_b, proj_m, proj_v, out);
}

// round 4
// speedup vs baseline: 2.0524x; 1.5332x over previous
#include <cuda_runtime.h>
#include <cuda_bf16.h>
#include <mma.h>
#include <cstdint>

using namespace nvcuda;

// ---------------- problem constants ----------------
#define Bc   256
#define Nn   196
#define Hh   8
#define KDc  32
#define VDc  64
#define Qq   49
#define EPSc 1e-5f
#define SCALEc 0.17677669529663689f  // 32^-0.5

// ---------------- device scratch (no runtime alloc allowed) ----------------
__device__ float g_k[Bc * Hh * KDc * Nn];     // [b,h,d,n]
__device__ float g_v[Bc * Hh * Nn * VDc];     // [b,h,n,d]
__device__ float g_q[Bc * Hh * Qq * KDc];     // [b,h,q,d]

// pre-split bf16 operands
__device__ __nv_bfloat16 g_xh[Bc*Nn*256],  g_xl[Bc*Nn*256];
__device__ __nv_bfloat16 g_kvwh[768*256],  g_kvwl[768*256];
__device__ __nv_bfloat16 g_qwh[256*256],   g_qwl[256*256];
__device__ __nv_bfloat16 g_pwh[384*512],   g_pwl[384*512];
__device__ __nv_bfloat16 g_ah[Bc*Qq*512],  g_al[Bc*Qq*512];   // attn out, hardswished

// ---------------- split precompute ----------------
// DST: 0=x 1=kv_w 2=q_w 3=proj_w
template <int DST>
__global__ void split_kernel(const float* __restrict__ src, int n4)
{
    int i = blockIdx.x * blockDim.x + threadIdx.x;
    if (i >= n4) return;
    __nv_bfloat16* hi; __nv_bfloat16* lo;
    if (DST == 0)      { hi = g_xh;   lo = g_xl;   }
    else if (DST == 1) { hi = g_kvwh; lo = g_kvwl; }
    else if (DST == 2) { hi = g_qwh;  lo = g_qwl;  }
    else               { hi = g_pwh;  lo = g_pwl;  }
    float4 t = reinterpret_cast<const float4*>(src)[i];
    float hx = __bfloat162float(__float2bfloat16_rn(t.x));
    float hy = __bfloat162float(__float2bfloat16_rn(t.y));
    float hz = __bfloat162float(__float2bfloat16_rn(t.z));
    float hw = __bfloat162float(__float2bfloat16_rn(t.w));
    __nv_bfloat162 h01 = __floats2bfloat162_rn(hx, hy);
    __nv_bfloat162 h23 = __floats2bfloat162_rn(hz, hw);
    __nv_bfloat162 l01 = __floats2bfloat162_rn(t.x - hx, t.y - hy);
    __nv_bfloat162 l23 = __floats2bfloat162_rn(t.z - hz, t.w - hw);
    reinterpret_cast<__nv_bfloat162*>(hi)[i*2]   = h01;
    reinterpret_cast<__nv_bfloat162*>(hi)[i*2+1] = h23;
    reinterpret_cast<__nv_bfloat162*>(lo)[i*2]   = l01;
    reinterpret_cast<__nv_bfloat162*>(lo)[i*2+1] = l23;
}

// ---------------- GEMM smem layout ----------------
#define TSTRIDE 40
#define OFF_ROW   64
#define OFF_INV   576
#define OFF_SH    1088
#define OFF_AHI   2048
#define OFF_ALO   (OFF_AHI + 128*TSTRIDE*2)
#define OFF_BHI   (OFF_ALO + 128*TSTRIDE*2)
#define OFF_BLO   (OFF_BHI + 128*TSTRIDE*2)
#define OFF_STAGE 2048
#define SSTRIDE   132
#define GEMM_SMEM_BYTES (2048 + 128*SSTRIDE*4)   // 69632

// ---------------------------------------------------------------------------
// wmma bf16 split GEMM + linear_norm epilogue, pre-split operands.
// MODE 0: A=x split, scatter g_k/g_v.  MODE 1: A=x split gathered -> g_q.
// MODE 2: A=g_ah/g_al -> Out.
// ---------------------------------------------------------------------------
template <int KDIM, int MODE>
__global__ __launch_bounds__(256, 2)
void tgemm_kernel(const float* __restrict__ gg,
                  const float* __restrict__ bb,
                  const float* __restrict__ mm,
                  const float* __restrict__ vv,
                  float* __restrict__ Out)
{
    extern __shared__ char sm[];
    int*   rowoff = (int*)(sm + OFF_ROW);
    float* sInv   = (float*)(sm + OFF_INV);
    float* sSh    = (float*)(sm + OFF_SH);
    float* S      = (float*)(sm + OFF_STAGE);
    __nv_bfloat16* Ahs = (__nv_bfloat16*)(sm + OFF_AHI);
    __nv_bfloat16* Als = (__nv_bfloat16*)(sm + OFF_ALO);
    __nv_bfloat16* Bhs = (__nv_bfloat16*)(sm + OFF_BHI);
    __nv_bfloat16* Bls = (__nv_bfloat16*)(sm + OFF_BLO);

    const __nv_bfloat16 *Agh, *Agl, *Wgh, *Wgl;
    if (MODE == 0)      { Agh = g_xh; Agl = g_xl; Wgh = g_kvwh; Wgl = g_kvwl; }
    else if (MODE == 1) { Agh = g_xh; Agl = g_xl; Wgh = g_qwh;  Wgl = g_qwl;  }
    else                { Agh = g_ah; Agl = g_al; Wgh = g_pwh;  Wgl = g_pwl;  }

    const int tid = threadIdx.x;
    const int wid = tid >> 5;
    const int m0 = blockIdx.x * 128;
    const int n0 = blockIdx.y * 128;

    if (tid < 128) {
        int m = m0 + tid;
        int off;
        if (MODE == 1) {
            int b = m / Qq, qq = m % Qq;
            int n = (qq / 7) * 28 + (qq % 7) * 2;
            off = (b * Nn + n) * KDIM;
        } else {
            off = m * KDIM;
        }
        rowoff[tid] = off;
        int jj = n0 + tid;
        float inv = gg[jj] * rsqrtf(vv[jj] + EPSc);
        sInv[tid] = inv;
        sSh[tid]  = bb[jj] - mm[jj] * inv;
    }
    __syncthreads();

    const int wm0 = (wid & 3) * 32;
    const int wn0 = (wid >> 2) * 64;

    wmma::fragment<wmma::accumulator, 16, 16, 16, float> acc[2][4];
#pragma unroll
    for (int i = 0; i < 2; i++)
#pragma unroll
        for (int j = 0; j < 4; j++) wmma::fill_fragment(acc[i][j], 0.0f);

    for (int k0 = 0; k0 < KDIM; k0 += 32) {
        // pure-copy smem fill: 8 bf16 per seg, 512 segs/matrix
#pragma unroll
        for (int l = 0; l < 2; l++) {
            int seg = tid + l * 256;
            int row = seg >> 2;
            int k8  = (seg & 3) * 8;
            int go  = rowoff[row] + k0 + k8;
            int wo  = (n0 + row) * KDIM + k0 + k8;
            int so  = row * TSTRIDE + k8;
            *reinterpret_cast<uint4*>(Ahs + so) = *reinterpret_cast<const uint4*>(Agh + go);
            *reinterpret_cast<uint4*>(Als + so) = *reinterpret_cast<const uint4*>(Agl + go);
            *reinterpret_cast<uint4*>(Bhs + so) = *reinterpret_cast<const uint4*>(Wgh + wo);
            *reinterpret_cast<uint4*>(Bls + so) = *reinterpret_cast<const uint4*>(Wgl + wo);
        }
        __syncthreads();

#pragma unroll
        for (int kk = 0; kk < 32; kk += 16) {
            wmma::fragment<wmma::matrix_a, 16, 16, 16, __nv_bfloat16, wmma::row_major> ah[2], al[2];
#pragma unroll
            for (int i = 0; i < 2; i++) {
                wmma::load_matrix_sync(ah[i], Ahs + (wm0 + i * 16) * TSTRIDE + kk, TSTRIDE);
                wmma::load_matrix_sync(al[i], Als + (wm0 + i * 16) * TSTRIDE + kk, TSTRIDE);
            }
#pragma unroll
            for (int j = 0; j < 4; j++) {
                wmma::fragment<wmma::matrix_b, 16, 16, 16, __nv_bfloat16, wmma::col_major> bh, bl;
                wmma::load_matrix_sync(bh, Bhs + (wn0 + j * 16) * TSTRIDE + kk, TSTRIDE);
                wmma::load_matrix_sync(bl, Bls + (wn0 + j * 16) * TSTRIDE + kk, TSTRIDE);
#pragma unroll
                for (int i = 0; i < 2; i++) {
                    wmma::mma_sync(acc[i][j], ah[i], bh, acc[i][j]);
                    wmma::mma_sync(acc[i][j], ah[i], bl, acc[i][j]);
                    wmma::mma_sync(acc[i][j], al[i], bh, acc[i][j]);
                }
            }
        }
        __syncthreads();
    }

    // stage raw accumulators (overlays tiles)
#pragma unroll
    for (int i = 0; i < 2; i++)
#pragma unroll
        for (int j = 0; j < 4; j++)
            wmma::store_matrix_sync(S + (wm0 + i * 16) * SSTRIDE + wn0 + j * 16,
                                    acc[i][j], SSTRIDE, wmma::mem_row_major);
    __syncthreads();

    // scatter with linear_norm
    if (MODE == 0) {
        // K pass: lanes sweep m (n-contiguous)
        for (int idx = tid; idx < 16384; idx += 256) {
            int col = idx >> 7, mrow = idx & 127;
            int jj = n0 + col, cch = jj % 96;
            if (cch < KDc) {
                int m = m0 + mrow;
                int b = m / Nn, n = m % Nn;
                int h = jj / 96;
                g_k[((b * Hh + h) * KDc + cch) * Nn + n] =
                    S[mrow * SSTRIDE + col] * sInv[col] + sSh[col];
            }
        }
        // V pass: float4 groups over columns
        for (int idx = tid; idx < 4096; idx += 256) {
            int mrow = idx >> 5, col = (idx & 31) * 4;
            int jj = n0 + col, cch = jj % 96;
            if (cch >= KDc) {
                int m = m0 + mrow;
                int b = m / Nn, n = m % Nn;
                int h = jj / 96;
                float4 o;
                o.x = S[mrow * SSTRIDE + col + 0] * sInv[col + 0] + sSh[col + 0];
                o.y = S[mrow * SSTRIDE + col + 1] * sInv[col + 1] + sSh[col + 1];
                o.z = S[mrow * SSTRIDE + col + 2] * sInv[col + 2] + sSh[col + 2];
                o.w = S[mrow * SSTRIDE + col + 3] * sInv[col + 3] + sSh[col + 3];
                *reinterpret_cast<float4*>(g_v + ((b * Hh + h) * Nn + n) * VDc + (cch - KDc)) = o;
            }
        }
    } else if (MODE == 1) {
        for (int idx = tid; idx < 4096; idx += 256) {
            int mrow = idx >> 5, col = (idx & 31) * 4;
            int jj = n0 + col;
            int m = m0 + mrow;
            int b = m / Qq, qq = m % Qq;
            int h = jj >> 5, d = jj & 31;
            float4 o;
            o.x = S[mrow * SSTRIDE + col + 0] * sInv[col + 0] + sSh[col + 0];
            o.y = S[mrow * SSTRIDE + col + 1] * sInv[col + 1] + sSh[col + 1];
            o.z = S[mrow * SSTRIDE + col + 2] * sInv[col + 2] + sSh[col + 2];
            o.w = S[mrow * SSTRIDE + col + 3] * sInv[col + 3] + sSh[col + 3];
            *reinterpret_cast<float4*>(g_q + ((b * Hh + h) * Qq + qq) * KDc + d) = o;
        }
    } else {
        for (int idx = tid; idx < 4096; idx += 256) {
            int mrow = idx >> 5, col = (idx & 31) * 4;
            float4 o;
            o.x = S[mrow * SSTRIDE + col + 0] * sInv[col + 0] + sSh[col + 0];
            o.y = S[mrow * SSTRIDE + col + 1] * sInv[col + 1] + sSh[col + 1];
            o.z = S[mrow * SSTRIDE + col + 2] * sInv[col + 2] + sSh[col + 2];
            o.w = S[mrow * SSTRIDE + col + 3] * sInv[col + 3] + sSh[col + 3];
            *reinterpret_cast<float4*>(Out + (size_t)(m0 + mrow) * 384 + n0 + col) = o;
        }
    }
}

// ---------------------------------------------------------------------------
// Attention: one block per (b,h), 512 threads, phase-overlaid smem (91.7 KB)
//   region layout (floats): sc[196*52] | union{ qsT[32*52]+ks[32*196] | vs[196*64] } | bs[196]
// ---------------------------------------------------------------------------
#define SC_STRIDE 52
#define ATTN_SC_FLOATS   (196*SC_STRIDE)          // 10192
#define ATTN_UNION_FLOATS 12544
#define ATTN_SMEM_FLOATS (ATTN_SC_FLOATS + ATTN_UNION_FLOATS + 196)

__global__ __launch_bounds__(512)
void attn_kernel(const float* __restrict__ attn_bias)
{
    extern __shared__ float smf[];
    float* sc  = smf;
    float* un  = smf + ATTN_SC_FLOATS;
    float* qsT = un;                 // 32 x 52 (d-major, padded rows)
    float* ks  = un + 32 * SC_STRIDE;
    float* vs  = un;                 // overlays qsT+ks in phase 2
    float* bs  = smf + ATTN_SC_FLOATS + ATTN_UNION_FLOATS;

    const int blk = blockIdx.x;
    const int b = blk >> 3, h = blk & 7;
    const int tid = threadIdx.x;

    const float* qg = g_q + (size_t)(b * Hh + h) * (Qq * KDc);
    const float* kg = g_k + (size_t)(b * Hh + h) * (KDc * Nn);
    const float* vg = g_v + (size_t)(b * Hh + h) * (Nn * VDc);

    // phase 0: load q (transposed), k, bias
    for (int i = tid; i < 1568; i += 512) {
        int qr = i >> 5, d = i & 31;
        qsT[d * SC_STRIDE + qr] = qg[i];
    }
    for (int i = tid; i < 1568; i += 512)
        reinterpret_cast<float4*>(ks)[i] = reinterpret_cast<const float4*>(kg)[i];
    for (int i = tid; i < 196; i += 512) bs[i] = attn_bias[h * Nn + i];
    __syncthreads();

    // phase 1: scores, 4 q-rows x 4 k-cols per item (13*49 = 637 items)
    for (int gi = tid; gi < 637; gi += 512) {
        int qg4 = gi / 49;
        int kc4 = gi - qg4 * 49;
        int qr0 = qg4 * 4;
        float acc[4][4];
#pragma unroll
        for (int i = 0; i < 4; i++)
#pragma unroll
            for (int j = 0; j < 4; j++) acc[i][j] = 0.0f;
#pragma unroll
        for (int d = 0; d < KDc; d++) {
            float4 k4 = *reinterpret_cast<const float4*>(ks + d * Nn + kc4 * 4);
            float4 q4 = *reinterpret_cast<const float4*>(qsT + d * SC_STRIDE + qr0);
            acc[0][0] += q4.x * k4.x; acc[0][1] += q4.x * k4.y; acc[0][2] += q4.x * k4.z; acc[0][3] += q4.x * k4.w;
            acc[1][0] += q4.y * k4.x; acc[1][1] += q4.y * k4.y; acc[1][2] += q4.y * k4.z; acc[1][3] += q4.y * k4.w;
            acc[2][0] += q4.z * k4.x; acc[2][1] += q4.z * k4.y; acc[2][2] += q4.z * k4.z; acc[2][3] += q4.z * k4.w;
            acc[3][0] += q4.w * k4.x; acc[3][1] += q4.w * k4.y; acc[3][2] += q4.w * k4.z; acc[3][3] += q4.w * k4.w;
        }
#pragma unroll
        for (int i = 0; i < 4; i++) {
            int qr = qr0 + i;
            if (qr < Qq) {
                int qi = qr / 7, qj = qr % 7;
#pragma unroll
                for (int cc = 0; cc < 4; cc++) {
                    int kc = kc4 * 4 + cc;
                    int ki = kc / 14, kj = kc % 14;
                    int r0 = abs(2 * qi - ki), r1 = abs(2 * qj - kj);
                    sc[kc * SC_STRIDE + qr] = acc[i][cc] * SCALEc + bs[r0 * 14 + r1];
                }
            }
        }
    }
    __syncthreads();

    // phase 2: load v (overlays q/k region)
    for (int i = tid; i < 3136; i += 512)
        reinterpret_cast<float4*>(vs)[i] = reinterpret_cast<const float4*>(vg)[i];
    __syncthreads();

    // phase 3: softmax, one warp per q-row
    const int wid = tid >> 5, lane = tid & 31;
    for (int row = wid; row < Qq; row += 16) {
        float mx = -1e30f;
        for (int c = lane; c < Nn; c += 32)
            mx = fmaxf(mx, sc[c * SC_STRIDE + row]);
#pragma unroll
        for (int o = 16; o > 0; o >>= 1)
            mx = fmaxf(mx, __shfl_xor_sync(0xffffffffu, mx, o));
        float sum = 0.0f;
        for (int c = lane; c < Nn; c += 32) {
            float e = __expf(sc[c * SC_STRIDE + row] - mx);
            sc[c * SC_STRIDE + row] = e;
            sum += e;
        }
#pragma unroll
        for (int o = 16; o > 0; o >>= 1)
            sum += __shfl_xor_sync(0xffffffffu, sum, o);
        float rinv = 1.0f / sum;
        for (int c = lane; c < Nn; c += 32)
            sc[c * SC_STRIDE + row] *= rinv;
    }
    __syncthreads();

    // phase 4: out = attn @ v, hardswish, split to bf16 hi/lo, store
    if (tid < 208) {
        int r4 = tid >> 4;     // 0..12
        int vq = tid & 15;
        float a[4][4];
#pragma unroll
        for (int i = 0; i < 4; i++)
#pragma unroll
            for (int j = 0; j < 4; j++) a[i][j] = 0.0f;
        for (int n = 0; n < Nn; n++) {
            float4 s4 = *reinterpret_cast<const float4*>(sc + n * SC_STRIDE + r4 * 4);
            float4 v4 = *reinterpret_cast<const float4*>(vs + n * VDc + vq * 4);
            a[0][0] += s4.x * v4.x; a[0][1] += s4.x * v4.y; a[0][2] += s4.x * v4.z; a[0][3] += s4.x * v4.w;
            a[1][0] += s4.y * v4.x; a[1][1] += s4.y * v4.y; a[1][2] += s4.y * v4.z; a[1][3] += s4.y * v4.w;
            a[2][0] += s4.z * v4.x; a[2][1] += s4.z * v4.y; a[2][2] += s4.z * v4.z; a[2][3] += s4.z * v4.w;
            a[3][0] += s4.w * v4.x; a[3][1] += s4.w * v4.y; a[3][2] += s4.w * v4.z; a[3][3] += s4.w * v4.w;
        }
#pragma unroll
        for (int i = 0; i < 4; i++) {
            int qr = r4 * 4 + i;
            if (qr < Qq) {
                float o[4];
#pragma unroll
                for (int j = 0; j < 4; j++) {
                    float t = a[i][j];
                    o[j] = t * fminf(fmaxf(t + 3.0f, 0.0f), 6.0f) * (1.0f / 6.0f);
                }
                float h0 = __bfloat162float(__float2bfloat16_rn(o[0]));
                float h1 = __bfloat162float(__float2bfloat16_rn(o[1]));
                float h2 = __bfloat162float(__float2bfloat16_rn(o[2]));
                float h3 = __bfloat162float(__float2bfloat16_rn(o[3]));
                __nv_bfloat162 hh01 = __floats2bfloat162_rn(h0, h1);
                __nv_bfloat162 hh23 = __floats2bfloat162_rn(h2, h3);
                __nv_bfloat162 ll01 = __floats2bfloat162_rn(o[0] - h0, o[1] - h1);
                __nv_bfloat162 ll23 = __floats2bfloat162_rn(o[2] - h2, o[3] - h3);
                size_t off = ((size_t)(b * Qq + qr)) * 512 + h * VDc + vq * 4;
                uint2 hv, lv;
                hv.x = *reinterpret_cast<uint32_t*>(&hh01);
                hv.y = *reinterpret_cast<uint32_t*>(&hh23);
                lv.x = *reinterpret_cast<uint32_t*>(&ll01);
                lv.y = *reinterpret_cast<uint32_t*>(&ll23);
                *reinterpret_cast<uint2*>(g_ah + off) = hv;
                *reinterpret_cast<uint2*>(g_al + off) = lv;
            }
        }
    }
}

// ---------------------------------------------------------------------------
extern "C" void kernel_launch(void* const* d_in, const int* in_sizes, int n_in,
                              void* d_out, int out_size)
{
    const float* x      = (const float*)d_in[0];
    const float* kv_g   = (const float*)d_in[2];
    const float* kv_b   = (const float*)d_in[3];
    const float* kv_m   = (const float*)d_in[4];
    const float* kv_v   = (const float*)d_in[5];
    const float* q_g    = (const float*)d_in[7];
    const float* q_b    = (const float*)d_in[8];
    const float* q_m    = (const float*)d_in[9];
    const float* q_v    = (const float*)d_in[10];
    const float* kv_w   = (const float*)d_in[1];
    const float* q_w    = (const float*)d_in[6];
    const float* proj_w = (const float*)d_in[11];
    const float* proj_g = (const float*)d_in[12];
    const float* proj_b = (const float*)d_in[13];
    const float* proj_m = (const float*)d_in[14];
    const float* proj_v = (const float*)d_in[15];
    const float* attn_bias = (const float*)d_in[16];
    float* out = (float*)d_out;

    // split precompute
    split_kernel<0><<<(Bc*Nn*256/4 + 255) / 256, 256>>>(x, Bc*Nn*256/4);
    split_kernel<1><<<(768*256/4 + 255) / 256, 256>>>(kv_w, 768*256/4);
    split_kernel<2><<<(256*256/4 + 255) / 256, 256>>>(q_w, 256*256/4);
    split_kernel<3><<<(384*512/4 + 255) / 256, 256>>>(proj_w, 384*512/4);

    cudaFuncSetAttribute(tgemm_kernel<256, 0>, cudaFuncAttributeMaxDynamicSharedMemorySize, GEMM_SMEM_BYTES);
    cudaFuncSetAttribute(tgemm_kernel<256, 1>, cudaFuncAttributeMaxDynamicSharedMemorySize, GEMM_SMEM_BYTES);
    cudaFuncSetAttribute(tgemm_kernel<512, 2>, cudaFuncAttributeMaxDynamicSharedMemorySize, GEMM_SMEM_BYTES);

    // kv GEMM: M=50176, N=768, K=256
    tgemm_kernel<256, 0><<<dim3(392, 6), 256, GEMM_SMEM_BYTES>>>(kv_g, kv_b, kv_m, kv_v, nullptr);
    // q GEMM: M=12544, N=256, K=256 (gathered rows)
    tgemm_kernel<256, 1><<<dim3(98, 2), 256, GEMM_SMEM_BYTES>>>(q_g, q_b, q_m, q_v, nullptr);

    // attention
    size_t shmem = (size_t)ATTN_SMEM_FLOATS * sizeof(float);
    cudaFuncSetAttribute(attn_kernel, cudaFuncAttributeMaxDynamicSharedMemorySize, (int)shmem);
    attn_kernel<<<Bc * Hh, 512, shmem>>>(attn_bias);

    // proj GEMM: M=12544, N=384, K=512
    tgemm_kernel<512, 2><<<dim3(98, 3), 256, GEMM_SMEM_BYTES>>>(proj_g, proj_b, proj_m, proj_v, out);
}

// round 5
// speedup vs baseline: 2.1864x; 1.0653x over previous
#include <cuda_runtime.h>
#include <cuda_bf16.h>
#include <mma.h>
#include <cstdint>

using namespace nvcuda;

// ---------------- problem constants ----------------
#define Bc   256
#define Nn   196
#define Hh   8
#define KDc  32
#define VDc  64
#define Qq   49
#define EPSc 1e-5f
#define SCALEc 0.17677669529663689f  // 32^-0.5

// ---------------- device scratch ----------------
__device__ float g_k[Bc * Hh * KDc * Nn];     // [b,h,d,n]
__device__ float g_v[Bc * Hh * Nn * VDc];     // [b,h,n,d]
__device__ float g_q[Bc * Hh * Qq * KDc];     // [b,h,q,d]

__device__ __nv_bfloat16 g_xh[Bc*Nn*256],  g_xl[Bc*Nn*256];
__device__ __nv_bfloat16 g_kvwh[768*256],  g_kvwl[768*256];
__device__ __nv_bfloat16 g_qwh[256*256],   g_qwl[256*256];
__device__ __nv_bfloat16 g_pwh[384*512],   g_pwl[384*512];
__device__ __nv_bfloat16 g_ah[Bc*Qq*512],  g_al[Bc*Qq*512];

// ---------------- cp.async helpers (sm_80 baseline ISA) ----------------
__device__ __forceinline__ void cp16(uint32_t dst, const void* src) {
    asm volatile("cp.async.cg.shared.global [%0], [%1], 16;" :: "r"(dst), "l"(src));
}
#define CP_COMMIT() asm volatile("cp.async.commit_group;" ::: "memory")
#define CP_WAIT0()  asm volatile("cp.async.wait_group 0;" ::: "memory")

__device__ __forceinline__ uint32_t smem_u32(const void* p) {
    uint32_t a;
    asm("{ .reg .u64 t; cvta.to.shared.u64 t, %1; cvt.u32.u64 %0, t; }" : "=r"(a) : "l"(p));
    return a;
}

// ---------------- split precompute ----------------
template <int DST>
__global__ void split_kernel(const float* __restrict__ src, int n4)
{
    int i = blockIdx.x * blockDim.x + threadIdx.x;
    if (i >= n4) return;
    __nv_bfloat16* hi; __nv_bfloat16* lo;
    if (DST == 0)      { hi = g_xh;   lo = g_xl;   }
    else if (DST == 1) { hi = g_kvwh; lo = g_kvwl; }
    else if (DST == 2) { hi = g_qwh;  lo = g_qwl;  }
    else               { hi = g_pwh;  lo = g_pwl;  }
    float4 t = reinterpret_cast<const float4*>(src)[i];
    float hx = __bfloat162float(__float2bfloat16_rn(t.x));
    float hy = __bfloat162float(__float2bfloat16_rn(t.y));
    float hz = __bfloat162float(__float2bfloat16_rn(t.z));
    float hw = __bfloat162float(__float2bfloat16_rn(t.w));
    __nv_bfloat162 h01 = __floats2bfloat162_rn(hx, hy);
    __nv_bfloat162 h23 = __floats2bfloat162_rn(hz, hw);
    __nv_bfloat162 l01 = __floats2bfloat162_rn(t.x - hx, t.y - hy);
    __nv_bfloat162 l23 = __floats2bfloat162_rn(t.z - hz, t.w - hw);
    reinterpret_cast<__nv_bfloat162*>(hi)[i*2]   = h01;
    reinterpret_cast<__nv_bfloat162*>(hi)[i*2+1] = h23;
    reinterpret_cast<__nv_bfloat162*>(lo)[i*2]   = l01;
    reinterpret_cast<__nv_bfloat162*>(lo)[i*2+1] = l23;
}

// ---------------- GEMM smem layout ----------------
#define TSTRIDE 40
#define OFF_ROW   64
#define OFF_INV   576
#define OFF_SH    1088
#define OFF_TILES 2048
#define STAGE_BYTES 40960                        // 4 tiles x 10240
#define OFF_STAGE 2048                           // fp32 stage S overlays tiles
#define SSTRIDE   132
#define GEMM_SMEM_BYTES (2048 + 2*STAGE_BYTES)   // 83968

// ---------------------------------------------------------------------------
// wmma bf16 split GEMM, cp.async double-buffered, linear_norm epilogue.
// MODE 0: A=x -> g_k/g_v.  MODE 1: A=x gathered -> g_q.  MODE 2: A=attn -> Out.
// ---------------------------------------------------------------------------
template <int KDIM, int MODE>
__global__ __launch_bounds__(256, 2)
void tgemm_kernel(const float* __restrict__ gg,
                  const float* __restrict__ bb,
                  const float* __restrict__ mm,
                  const float* __restrict__ vv,
                  float* __restrict__ Out)
{
    extern __shared__ char sm[];
    const uint32_t sb = smem_u32(sm);
    int*   rowoff = (int*)(sm + OFF_ROW);
    float* sInv   = (float*)(sm + OFF_INV);
    float* sSh    = (float*)(sm + OFF_SH);
    float* S      = (float*)(sm + OFF_STAGE);

    const __nv_bfloat16 *Agh, *Agl, *Wgh, *Wgl;
    if (MODE == 0)      { Agh = g_xh; Agl = g_xl; Wgh = g_kvwh; Wgl = g_kvwl; }
    else if (MODE == 1) { Agh = g_xh; Agl = g_xl; Wgh = g_qwh;  Wgl = g_qwl;  }
    else                { Agh = g_ah; Agl = g_al; Wgh = g_pwh;  Wgl = g_pwl;  }

    const int tid = threadIdx.x;
    const int wid = tid >> 5;
    const int m0 = blockIdx.x * 128;
    const int n0 = blockIdx.y * 128;

    if (tid < 128) {
        int m = m0 + tid;
        int off;
        if (MODE == 1) {
            int b = m / Qq, qq = m % Qq;
            int n = (qq / 7) * 28 + (qq % 7) * 2;
            off = (b * Nn + n) * KDIM;
        } else {
            off = m * KDIM;
        }
        rowoff[tid] = off;
        int jj = n0 + tid;
        float inv = gg[jj] * rsqrtf(vv[jj] + EPSc);
        sInv[tid] = inv;
        sSh[tid]  = bb[jj] - mm[jj] * inv;
    }
    __syncthreads();

    // per-thread load slots (2 segments of 8 bf16 per matrix per chunk)
    const int r0 = tid >> 2,        k8 = (tid & 3) * 8;
    const int r1 = (tid + 256) >> 2;
    const int aoff0 = rowoff[r0] + k8;
    const int aoff1 = rowoff[r1] + k8;
    const int woff0 = (n0 + r0) * KDIM + k8;
    const int woff1 = (n0 + r1) * KDIM + k8;
    const uint32_t so0 = (uint32_t)(r0 * TSTRIDE + k8) * 2;
    const uint32_t so1 = (uint32_t)(r1 * TSTRIDE + k8) * 2;

    const int wm0 = (wid & 3) * 32;
    const int wn0 = (wid >> 2) * 64;

    wmma::fragment<wmma::accumulator, 16, 16, 16, float> acc[2][4];
#pragma unroll
    for (int i = 0; i < 2; i++)
#pragma unroll
        for (int j = 0; j < 4; j++) wmma::fill_fragment(acc[i][j], 0.0f);

    constexpr int NCHUNK = KDIM / 32;

    auto load_chunk = [&](int c, int stage) {
        const uint32_t base = sb + OFF_TILES + stage * STAGE_BYTES;
        const int k0 = c * 32;
        cp16(base + so0,         Agh + aoff0 + k0);
        cp16(base + so1,         Agh + aoff1 + k0);
        cp16(base + 10240 + so0, Agl + aoff0 + k0);
        cp16(base + 10240 + so1, Agl + aoff1 + k0);
        cp16(base + 20480 + so0, Wgh + woff0 + k0);
        cp16(base + 20480 + so1, Wgh + woff1 + k0);
        cp16(base + 30720 + so0, Wgl + woff0 + k0);
        cp16(base + 30720 + so1, Wgl + woff1 + k0);
        CP_COMMIT();
    };

    load_chunk(0, 0);

#pragma unroll 1
    for (int c = 0; c < NCHUNK; c++) {
        CP_WAIT0();
        __syncthreads();
        if (c + 1 < NCHUNK) load_chunk(c + 1, (c + 1) & 1);

        char* st = sm + OFF_TILES + (c & 1) * STAGE_BYTES;
        __nv_bfloat16* Ahs = (__nv_bfloat16*)(st);
        __nv_bfloat16* Als = (__nv_bfloat16*)(st + 10240);
        __nv_bfloat16* Bhs = (__nv_bfloat16*)(st + 20480);
        __nv_bfloat16* Bls = (__nv_bfloat16*)(st + 30720);

#pragma unroll
        for (int kk = 0; kk < 32; kk += 16) {
            wmma::fragment<wmma::matrix_a, 16, 16, 16, __nv_bfloat16, wmma::row_major> ah[2], al[2];
#pragma unroll
            for (int i = 0; i < 2; i++) {
                wmma::load_matrix_sync(ah[i], Ahs + (wm0 + i * 16) * TSTRIDE + kk, TSTRIDE);
                wmma::load_matrix_sync(al[i], Als + (wm0 + i * 16) * TSTRIDE + kk, TSTRIDE);
            }
#pragma unroll
            for (int j = 0; j < 4; j++) {
                wmma::fragment<wmma::matrix_b, 16, 16, 16, __nv_bfloat16, wmma::col_major> bh, bl;
                wmma::load_matrix_sync(bh, Bhs + (wn0 + j * 16) * TSTRIDE + kk, TSTRIDE);
                wmma::load_matrix_sync(bl, Bls + (wn0 + j * 16) * TSTRIDE + kk, TSTRIDE);
#pragma unroll
                for (int i = 0; i < 2; i++) {
                    wmma::mma_sync(acc[i][j], ah[i], bh, acc[i][j]);
                    wmma::mma_sync(acc[i][j], ah[i], bl, acc[i][j]);
                    wmma::mma_sync(acc[i][j], al[i], bh, acc[i][j]);
                }
            }
        }
        __syncthreads();
    }

    // stage accumulators (overlays tiles; loop ends with syncthreads)
#pragma unroll
    for (int i = 0; i < 2; i++)
#pragma unroll
        for (int j = 0; j < 4; j++)
            wmma::store_matrix_sync(S + (wm0 + i * 16) * SSTRIDE + wn0 + j * 16,
                                    acc[i][j], SSTRIDE, wmma::mem_row_major);
    __syncthreads();

    if (MODE == 0) {
        for (int idx = tid; idx < 16384; idx += 256) {
            int col = idx >> 7, mrow = idx & 127;
            int jj = n0 + col, cch = jj % 96;
            if (cch < KDc) {
                int m = m0 + mrow;
                int b = m / Nn, n = m % Nn;
                int h = jj / 96;
                g_k[((b * Hh + h) * KDc + cch) * Nn + n] =
                    S[mrow * SSTRIDE + col] * sInv[col] + sSh[col];
            }
        }
        for (int idx = tid; idx < 4096; idx += 256) {
            int mrow = idx >> 5, col = (idx & 31) * 4;
            int jj = n0 + col, cch = jj % 96;
            if (cch >= KDc) {
                int m = m0 + mrow;
                int b = m / Nn, n = m % Nn;
                int h = jj / 96;
                float4 o;
                o.x = S[mrow * SSTRIDE + col + 0] * sInv[col + 0] + sSh[col + 0];
                o.y = S[mrow * SSTRIDE + col + 1] * sInv[col + 1] + sSh[col + 1];
                o.z = S[mrow * SSTRIDE + col + 2] * sInv[col + 2] + sSh[col + 2];
                o.w = S[mrow * SSTRIDE + col + 3] * sInv[col + 3] + sSh[col + 3];
                *reinterpret_cast<float4*>(g_v + ((b * Hh + h) * Nn + n) * VDc + (cch - KDc)) = o;
            }
        }
    } else if (MODE == 1) {
        for (int idx = tid; idx < 4096; idx += 256) {
            int mrow = idx >> 5, col = (idx & 31) * 4;
            int jj = n0 + col;
            int m = m0 + mrow;
            int b = m / Qq, qq = m % Qq;
            int h = jj >> 5, d = jj & 31;
            float4 o;
            o.x = S[mrow * SSTRIDE + col + 0] * sInv[col + 0] + sSh[col + 0];
            o.y = S[mrow * SSTRIDE + col + 1] * sInv[col + 1] + sSh[col + 1];
            o.z = S[mrow * SSTRIDE + col + 2] * sInv[col + 2] + sSh[col + 2];
            o.w = S[mrow * SSTRIDE + col + 3] * sInv[col + 3] + sSh[col + 3];
            *reinterpret_cast<float4*>(g_q + ((b * Hh + h) * Qq + qq) * KDc + d) = o;
        }
    } else {
        for (int idx = tid; idx < 4096; idx += 256) {
            int mrow = idx >> 5, col = (idx & 31) * 4;
            float4 o;
            o.x = S[mrow * SSTRIDE + col + 0] * sInv[col + 0] + sSh[col + 0];
            o.y = S[mrow * SSTRIDE + col + 1] * sInv[col + 1] + sSh[col + 1];
            o.z = S[mrow * SSTRIDE + col + 2] * sInv[col + 2] + sSh[col + 2];
            o.w = S[mrow * SSTRIDE + col + 3] * sInv[col + 3] + sSh[col + 3];
            *reinterpret_cast<float4*>(Out + (size_t)(m0 + mrow) * 384 + n0 + col) = o;
        }
    }
}

// ---------------------------------------------------------------------------
// Attention: one block per (b,h), 512 threads.
// smem floats: sc[196*52] | union{qsT[32*52]+ks[32*196] | vs[196*64]} | bs[196] | pr[208*20]
// ---------------------------------------------------------------------------
#define SC_STRIDE 52
#define ATTN_SC_FLOATS    (196*SC_STRIDE)
#define ATTN_UNION_FLOATS 12544
#define PR_STRIDE 20
#define ATTN_SMEM_FLOATS (ATTN_SC_FLOATS + ATTN_UNION_FLOATS + 196 + 208*PR_STRIDE)

__global__ __launch_bounds__(512)
void attn_kernel(const float* __restrict__ attn_bias)
{
    extern __shared__ float smf[];
    float* sc  = smf;
    float* un  = smf + ATTN_SC_FLOATS;
    float* qsT = un;
    float* ks  = un + 32 * SC_STRIDE;
    float* vs  = un;                              // phase-2 overlay
    float* bs  = smf + ATTN_SC_FLOATS + ATTN_UNION_FLOATS;
    float* pr  = bs + 196;

    const int blk = blockIdx.x;
    const int b = blk >> 3, h = blk & 7;
    const int tid = threadIdx.x;

    const float* qg = g_q + (size_t)(b * Hh + h) * (Qq * KDc);
    const float* kg = g_k + (size_t)(b * Hh + h) * (KDc * Nn);
    const float* vg = g_v + (size_t)(b * Hh + h) * (Nn * VDc);

    // phase 0: load q (transposed), k, bias
    for (int i = tid; i < 1568; i += 512) {
        int qr = i >> 5, d = i & 31;
        qsT[d * SC_STRIDE + qr] = qg[i];
    }
    for (int i = tid; i < 1568; i += 512)
        reinterpret_cast<float4*>(ks)[i] = reinterpret_cast<const float4*>(kg)[i];
    for (int i = tid; i < 196; i += 512) bs[i] = attn_bias[h * Nn + i];
    __syncthreads();

    // phase 1: scores (4q x 4k per item)
    for (int gi = tid; gi < 637; gi += 512) {
        int qg4 = gi / 49;
        int kc4 = gi - qg4 * 49;
        int qr0 = qg4 * 4;
        float acc[4][4];
#pragma unroll
        for (int i = 0; i < 4; i++)
#pragma unroll
            for (int j = 0; j < 4; j++) acc[i][j] = 0.0f;
#pragma unroll
        for (int d = 0; d < KDc; d++) {
            float4 k4 = *reinterpret_cast<const float4*>(ks + d * Nn + kc4 * 4);
            float4 q4 = *reinterpret_cast<const float4*>(qsT + d * SC_STRIDE + qr0);
            acc[0][0] += q4.x * k4.x; acc[0][1] += q4.x * k4.y; acc[0][2] += q4.x * k4.z; acc[0][3] += q4.x * k4.w;
            acc[1][0] += q4.y * k4.x; acc[1][1] += q4.y * k4.y; acc[1][2] += q4.y * k4.z; acc[1][3] += q4.y * k4.w;
            acc[2][0] += q4.z * k4.x; acc[2][1] += q4.z * k4.y; acc[2][2] += q4.z * k4.z; acc[2][3] += q4.z * k4.w;
            acc[3][0] += q4.w * k4.x; acc[3][1] += q4.w * k4.y; acc[3][2] += q4.w * k4.z; acc[3][3] += q4.w * k4.w;
        }
#pragma unroll
        for (int i = 0; i < 4; i++) {
            int qr = qr0 + i;
            if (qr < Qq) {
                int qi = qr / 7, qj = qr % 7;
#pragma unroll
                for (int cc = 0; cc < 4; cc++) {
                    int kc = kc4 * 4 + cc;
                    int ki = kc / 14, kj = kc % 14;
                    int rr0 = abs(2 * qi - ki), rr1 = abs(2 * qj - kj);
                    sc[kc * SC_STRIDE + qr] = acc[i][cc] * SCALEc + bs[rr0 * 14 + rr1];
                }
            }
        }
    }
    __syncthreads();

    // phase 2: prefetch v with cp.async (overlays q/k), hidden under softmax
    {
        uint32_t vs_u = smem_u32(vs);
        for (int i = tid; i < 3136; i += 512)
            cp16(vs_u + i * 16, reinterpret_cast<const float4*>(vg) + i);
        CP_COMMIT();
    }

    // phase 3: softmax (reads/writes sc only)
    const int wid = tid >> 5, lane = tid & 31;
    for (int row = wid; row < Qq; row += 16) {
        float mx = -1e30f;
        for (int c = lane; c < Nn; c += 32)
            mx = fmaxf(mx, sc[c * SC_STRIDE + row]);
#pragma unroll
        for (int o = 16; o > 0; o >>= 1)
            mx = fmaxf(mx, __shfl_xor_sync(0xffffffffu, mx, o));
        float sum = 0.0f;
        for (int c = lane; c < Nn; c += 32) {
            float e = __expf(sc[c * SC_STRIDE + row] - mx);
            sc[c * SC_STRIDE + row] = e;
            sum += e;
        }
#pragma unroll
        for (int o = 16; o > 0; o >>= 1)
            sum += __shfl_xor_sync(0xffffffffu, sum, o);
        float rinv = 1.0f / sum;
        for (int c = lane; c < Nn; c += 32)
            sc[c * SC_STRIDE + row] *= rinv;
    }
    CP_WAIT0();
    __syncthreads();

    // phase 4: out = attn @ v, split across two n-halves (warp-aligned groups)
    const int half = tid >> 8;          // 0: warps 0-7, 1: warps 8-15
    const int it   = tid & 255;         // item within group
    float a[4][4];
    if (it < 208) {
        int r4 = it >> 4;
        int vq = it & 15;
#pragma unroll
        for (int i = 0; i < 4; i++)
#pragma unroll
            for (int j = 0; j < 4; j++) a[i][j] = 0.0f;
        int nlo = half * 98, nhi = nlo + 98;
        for (int n = nlo; n < nhi; n++) {
            float4 s4 = *reinterpret_cast<const float4*>(sc + n * SC_STRIDE + r4 * 4);
            float4 v4 = *reinterpret_cast<const float4*>(vs + n * VDc + vq * 4);
            a[0][0] += s4.x * v4.x; a[0][1] += s4.x * v4.y; a[0][2] += s4.x * v4.z; a[0][3] += s4.x * v4.w;
            a[1][0] += s4.y * v4.x; a[1][1] += s4.y * v4.y; a[1][2] += s4.y * v4.z; a[1][3] += s4.y * v4.w;
            a[2][0] += s4.z * v4.x; a[2][1] += s4.z * v4.y; a[2][2] += s4.z * v4.z; a[2][3] += s4.z * v4.w;
            a[3][0] += s4.w * v4.x; a[3][1] += s4.w * v4.y; a[3][2] += s4.w * v4.z; a[3][3] += s4.w * v4.w;
        }
        if (half == 1) {
#pragma unroll
            for (int i = 0; i < 4; i++)
#pragma unroll
                for (int j = 0; j < 4; j++)
                    pr[it * PR_STRIDE + i * 4 + j] = a[i][j];
        }
    }
    __syncthreads();

    if (half == 0 && it < 208) {
        int r4 = it >> 4;
        int vq = it & 15;
#pragma unroll
        for (int i = 0; i < 4; i++)
#pragma unroll
            for (int j = 0; j < 4; j++)
                a[i][j] += pr[it * PR_STRIDE + i * 4 + j];
#pragma unroll
        for (int i = 0; i < 4; i++) {
            int qr = r4 * 4 + i;
            if (qr < Qq) {
                float o[4];
#pragma unroll
                for (int j = 0; j < 4; j++) {
                    float t = a[i][j];
                    o[j] = t * fminf(fmaxf(t + 3.0f, 0.0f), 6.0f) * (1.0f / 6.0f);
                }
                float h0 = __bfloat162float(__float2bfloat16_rn(o[0]));
                float h1 = __bfloat162float(__float2bfloat16_rn(o[1]));
                float h2 = __bfloat162float(__float2bfloat16_rn(o[2]));
                float h3 = __bfloat162float(__float2bfloat16_rn(o[3]));
                __nv_bfloat162 hh01 = __floats2bfloat162_rn(h0, h1);
                __nv_bfloat162 hh23 = __floats2bfloat162_rn(h2, h3);
                __nv_bfloat162 ll01 = __floats2bfloat162_rn(o[0] - h0, o[1] - h1);
                __nv_bfloat162 ll23 = __floats2bfloat162_rn(o[2] - h2, o[3] - h3);
                size_t off = ((size_t)(b * Qq + qr)) * 512 + h * VDc + vq * 4;
                uint2 hv, lv;
                hv.x = *reinterpret_cast<uint32_t*>(&hh01);
                hv.y = *reinterpret_cast<uint32_t*>(&hh23);
                lv.x = *reinterpret_cast<uint32_t*>(&ll01);
                lv.y = *reinterpret_cast<uint32_t*>(&ll23);
                *reinterpret_cast<uint2*>(g_ah + off) = hv;
                *reinterpret_cast<uint2*>(g_al + off) = lv;
            }
        }
    }
}

// ---------------------------------------------------------------------------
extern "C" void kernel_launch(void* const* d_in, const int* in_sizes, int n_in,
                              void* d_out, int out_size)
{
    const float* x      = (const float*)d_in[0];
    const float* kv_w   = (const float*)d_in[1];
    const float* kv_g   = (const float*)d_in[2];
    const float* kv_b   = (const float*)d_in[3];
    const float* kv_m   = (const float*)d_in[4];
    const float* kv_v   = (const float*)d_in[5];
    const float* q_w    = (const float*)d_in[6];
    const float* q_g    = (const float*)d_in[7];
    const float* q_b    = (const float*)d_in[8];
    const float* q_m    = (const float*)d_in[9];
    const float* q_v    = (const float*)d_in[10];
    const float* proj_w = (const float*)d_in[11];
    const float* proj_g = (const float*)d_in[12];
    const float* proj_b = (const float*)d_in[13];
    const float* proj_m = (const float*)d_in[14];
    const float* proj_v = (const float*)d_in[15];
    const float* attn_bias = (const float*)d_in[16];
    float* out = (float*)d_out;

    split_kernel<0><<<(Bc*Nn*256/4 + 255) / 256, 256>>>(x, Bc*Nn*256/4);
    split_kernel<1><<<(768*256/4 + 255) / 256, 256>>>(kv_w, 768*256/4);
    split_kernel<2><<<(256*256/4 + 255) / 256, 256>>>(q_w, 256*256/4);
    split_kernel<3><<<(384*512/4 + 255) / 256, 256>>>(proj_w, 384*512/4);

    cudaFuncSetAttribute(tgemm_kernel<256, 0>, cudaFuncAttributeMaxDynamicSharedMemorySize, GEMM_SMEM_BYTES);
    cudaFuncSetAttribute(tgemm_kernel<256, 1>, cudaFuncAttributeMaxDynamicSharedMemorySize, GEMM_SMEM_BYTES);
    cudaFuncSetAttribute(tgemm_kernel<512, 2>, cudaFuncAttributeMaxDynamicSharedMemorySize, GEMM_SMEM_BYTES);

    tgemm_kernel<256, 0><<<dim3(392, 6), 256, GEMM_SMEM_BYTES>>>(kv_g, kv_b, kv_m, kv_v, nullptr);
    tgemm_kernel<256, 1><<<dim3(98, 2), 256, GEMM_SMEM_BYTES>>>(q_g, q_b, q_m, q_v, nullptr);

    size_t shmem = (size_t)ATTN_SMEM_FLOATS * sizeof(float);
    cudaFuncSetAttribute(attn_kernel, cudaFuncAttributeMaxDynamicSharedMemorySize, (int)shmem);
    attn_kernel<<<Bc * Hh, 512, shmem>>>(attn_bias);

    tgemm_kernel<512, 2><<<dim3(98, 3), 256, GEMM_SMEM_BYTES>>>(proj_g, proj_b, proj_m, proj_v, out);
}

// round 6
// speedup vs baseline: 2.2625x; 1.0348x over previous
#include <cuda_runtime.h>
#include <cuda_bf16.h>
#include <mma.h>
#include <cstdint>

using namespace nvcuda;

// ---------------- problem constants ----------------
#define Bc   256
#define Nn   196
#define Hh   8
#define KDc  32
#define VDc  64
#define Qq   49
#define EPSc 1e-5f
#define SCALEc 0.17677669529663689f  // 32^-0.5

// ---------------- device scratch ----------------
__device__ __nv_bfloat16 g_xh[Bc*Nn*256],  g_xl[Bc*Nn*256];
__device__ __nv_bfloat16 g_kvwh[768*256],  g_kvwl[768*256];
__device__ __nv_bfloat16 g_qwh[256*256],   g_qwl[256*256];
__device__ __nv_bfloat16 g_pwh[384*512],   g_pwl[384*512];
__device__ __nv_bfloat16 g_ah[Bc*Qq*512],  g_al[Bc*Qq*512];
// attention operands, split bf16
__device__ __nv_bfloat16 g_kh[Bc*Hh*Nn*KDc], g_kl[Bc*Hh*Nn*KDc];   // [bh,n,d]
__device__ __nv_bfloat16 g_vh[Bc*Hh*Nn*VDc], g_vl[Bc*Hh*Nn*VDc];   // [bh,n,d]
__device__ __nv_bfloat16 g_qh[Bc*Hh*Qq*KDc], g_ql[Bc*Hh*Qq*KDc];   // [bh,q,d]

// ---------------- cp.async helpers ----------------
__device__ __forceinline__ void cp16(uint32_t dst, const void* src) {
    asm volatile("cp.async.cg.shared.global [%0], [%1], 16;" :: "r"(dst), "l"(src));
}
#define CP_COMMIT() asm volatile("cp.async.commit_group;" ::: "memory")
#define CP_WAIT0()  asm volatile("cp.async.wait_group 0;" ::: "memory")

__device__ __forceinline__ uint32_t smem_u32(const void* p) {
    uint32_t a;
    asm("{ .reg .u64 t; cvta.to.shared.u64 t, %1; cvt.u32.u64 %0, t; }" : "=r"(a) : "l"(p));
    return a;
}

__device__ __forceinline__ void split2(float v0, float v1,
                                       __nv_bfloat162& hv, __nv_bfloat162& lv) {
    __nv_bfloat16 h0 = __float2bfloat16_rn(v0);
    __nv_bfloat16 h1 = __float2bfloat16_rn(v1);
    hv.x = h0; hv.y = h1;
    lv.x = __float2bfloat16_rn(v0 - __bfloat162float(h0));
    lv.y = __float2bfloat16_rn(v1 - __bfloat162float(h1));
}

// ---------------- split precompute ----------------
template <int DST>
__global__ void split_kernel(const float* __restrict__ src, int n4)
{
    int i = blockIdx.x * blockDim.x + threadIdx.x;
    if (i >= n4) return;
    __nv_bfloat16* hi; __nv_bfloat16* lo;
    if (DST == 0)      { hi = g_xh;   lo = g_xl;   }
    else if (DST == 1) { hi = g_kvwh; lo = g_kvwl; }
    else if (DST == 2) { hi = g_qwh;  lo = g_qwl;  }
    else               { hi = g_pwh;  lo = g_pwl;  }
    float4 t = reinterpret_cast<const float4*>(src)[i];
    __nv_bfloat162 h01, l01, h23, l23;
    split2(t.x, t.y, h01, l01);
    split2(t.z, t.w, h23, l23);
    reinterpret_cast<__nv_bfloat162*>(hi)[i*2]   = h01;
    reinterpret_cast<__nv_bfloat162*>(hi)[i*2+1] = h23;
    reinterpret_cast<__nv_bfloat162*>(lo)[i*2]   = l01;
    reinterpret_cast<__nv_bfloat162*>(lo)[i*2+1] = l23;
}

// ---------------- GEMM smem layout ----------------
#define TSTRIDE 40
#define OFF_ROW   64
#define OFF_INV   576
#define OFF_SH    1088
#define OFF_TILES 2048
#define STAGE_BYTES 40960
#define OFF_STAGE 2048
#define SSTRIDE   132
#define GEMM_SMEM_BYTES (2048 + 2*STAGE_BYTES)

// ---------------------------------------------------------------------------
// wmma bf16 split GEMM, cp.async double-buffered, linear_norm epilogue.
// MODE 0: -> g_kh/g_kl/g_vh/g_vl (split bf16).  MODE 1: -> g_qh/g_ql.
// MODE 2: A=g_ah/g_al -> Out fp32.
// ---------------------------------------------------------------------------
template <int KDIM, int MODE>
__global__ __launch_bounds__(256, 2)
void tgemm_kernel(const float* __restrict__ gg,
                  const float* __restrict__ bb,
                  const float* __restrict__ mm,
                  const float* __restrict__ vv,
                  float* __restrict__ Out)
{
    extern __shared__ char sm[];
    const uint32_t sb = smem_u32(sm);
    int*   rowoff = (int*)(sm + OFF_ROW);
    float* sInv   = (float*)(sm + OFF_INV);
    float* sSh    = (float*)(sm + OFF_SH);
    float* S      = (float*)(sm + OFF_STAGE);

    const __nv_bfloat16 *Agh, *Agl, *Wgh, *Wgl;
    if (MODE == 0)      { Agh = g_xh; Agl = g_xl; Wgh = g_kvwh; Wgl = g_kvwl; }
    else if (MODE == 1) { Agh = g_xh; Agl = g_xl; Wgh = g_qwh;  Wgl = g_qwl;  }
    else                { Agh = g_ah; Agl = g_al; Wgh = g_pwh;  Wgl = g_pwl;  }

    const int tid = threadIdx.x;
    const int wid = tid >> 5;
    const int m0 = blockIdx.x * 128;
    const int n0 = blockIdx.y * 128;

    if (tid < 128) {
        int m = m0 + tid;
        int off;
        if (MODE == 1) {
            int b = m / Qq, qq = m % Qq;
            int n = (qq / 7) * 28 + (qq % 7) * 2;
            off = (b * Nn + n) * KDIM;
        } else {
            off = m * KDIM;
        }
        rowoff[tid] = off;
        int jj = n0 + tid;
        float inv = gg[jj] * rsqrtf(vv[jj] + EPSc);
        sInv[tid] = inv;
        sSh[tid]  = bb[jj] - mm[jj] * inv;
    }
    __syncthreads();

    const int r0 = tid >> 2,        k8 = (tid & 3) * 8;
    const int r1 = (tid + 256) >> 2;
    const int aoff0 = rowoff[r0] + k8;
    const int aoff1 = rowoff[r1] + k8;
    const int woff0 = (n0 + r0) * KDIM + k8;
    const int woff1 = (n0 + r1) * KDIM + k8;
    const uint32_t so0 = (uint32_t)(r0 * TSTRIDE + k8) * 2;
    const uint32_t so1 = (uint32_t)(r1 * TSTRIDE + k8) * 2;

    const int wm0 = (wid & 3) * 32;
    const int wn0 = (wid >> 2) * 64;

    wmma::fragment<wmma::accumulator, 16, 16, 16, float> acc[2][4];
#pragma unroll
    for (int i = 0; i < 2; i++)
#pragma unroll
        for (int j = 0; j < 4; j++) wmma::fill_fragment(acc[i][j], 0.0f);

    constexpr int NCHUNK = KDIM / 32;

    auto load_chunk = [&](int c, int stage) {
        const uint32_t base = sb + OFF_TILES + stage * STAGE_BYTES;
        const int k0 = c * 32;
        cp16(base + so0,         Agh + aoff0 + k0);
        cp16(base + so1,         Agh + aoff1 + k0);
        cp16(base + 10240 + so0, Agl + aoff0 + k0);
        cp16(base + 10240 + so1, Agl + aoff1 + k0);
        cp16(base + 20480 + so0, Wgh + woff0 + k0);
        cp16(base + 20480 + so1, Wgh + woff1 + k0);
        cp16(base + 30720 + so0, Wgl + woff0 + k0);
        cp16(base + 30720 + so1, Wgl + woff1 + k0);
        CP_COMMIT();
    };

    load_chunk(0, 0);

#pragma unroll 1
    for (int c = 0; c < NCHUNK; c++) {
        CP_WAIT0();
        __syncthreads();
        if (c + 1 < NCHUNK) load_chunk(c + 1, (c + 1) & 1);

        char* st = sm + OFF_TILES + (c & 1) * STAGE_BYTES;
        __nv_bfloat16* Ahs = (__nv_bfloat16*)(st);
        __nv_bfloat16* Als = (__nv_bfloat16*)(st + 10240);
        __nv_bfloat16* Bhs = (__nv_bfloat16*)(st + 20480);
        __nv_bfloat16* Bls = (__nv_bfloat16*)(st + 30720);

#pragma unroll
        for (int kk = 0; kk < 32; kk += 16) {
            wmma::fragment<wmma::matrix_a, 16, 16, 16, __nv_bfloat16, wmma::row_major> ah[2], al[2];
#pragma unroll
            for (int i = 0; i < 2; i++) {
                wmma::load_matrix_sync(ah[i], Ahs + (wm0 + i * 16) * TSTRIDE + kk, TSTRIDE);
                wmma::load_matrix_sync(al[i], Als + (wm0 + i * 16) * TSTRIDE + kk, TSTRIDE);
            }
#pragma unroll
            for (int j = 0; j < 4; j++) {
                wmma::fragment<wmma::matrix_b, 16, 16, 16, __nv_bfloat16, wmma::col_major> bh, bl;
                wmma::load_matrix_sync(bh, Bhs + (wn0 + j * 16) * TSTRIDE + kk, TSTRIDE);
                wmma::load_matrix_sync(bl, Bls + (wn0 + j * 16) * TSTRIDE + kk, TSTRIDE);
#pragma unroll
                for (int i = 0; i < 2; i++) {
                    wmma::mma_sync(acc[i][j], ah[i], bh, acc[i][j]);
                    wmma::mma_sync(acc[i][j], ah[i], bl, acc[i][j]);
                    wmma::mma_sync(acc[i][j], al[i], bh, acc[i][j]);
                }
            }
        }
        __syncthreads();
    }

#pragma unroll
    for (int i = 0; i < 2; i++)
#pragma unroll
        for (int j = 0; j < 4; j++)
            wmma::store_matrix_sync(S + (wm0 + i * 16) * SSTRIDE + wn0 + j * 16,
                                    acc[i][j], SSTRIDE, wmma::mem_row_major);
    __syncthreads();

    if (MODE == 0) {
        // split-bf16 scatter to g_kh/g_kl [bh,n,d<32] and g_vh/g_vl [bh,n,d<64]
        for (int idx = tid; idx < 8192; idx += 256) {
            int mrow = idx >> 6, pair = idx & 63, col = pair * 2;
            int jj = n0 + col;
            int h = jj / 96, cch = jj - h * 96;
            int m = m0 + mrow;
            int b = m / Nn, n = m - b * Nn;
            float v0 = S[mrow * SSTRIDE + col]     * sInv[col]     + sSh[col];
            float v1 = S[mrow * SSTRIDE + col + 1] * sInv[col + 1] + sSh[col + 1];
            __nv_bfloat162 hv, lv;
            split2(v0, v1, hv, lv);
            if (cch < KDc) {
                size_t base = ((size_t)((b * Hh + h) * Nn + n)) * KDc + cch;
                *reinterpret_cast<__nv_bfloat162*>(g_kh + base) = hv;
                *reinterpret_cast<__nv_bfloat162*>(g_kl + base) = lv;
            } else {
                size_t base = ((size_t)((b * Hh + h) * Nn + n)) * VDc + (cch - KDc);
                *reinterpret_cast<__nv_bfloat162*>(g_vh + base) = hv;
                *reinterpret_cast<__nv_bfloat162*>(g_vl + base) = lv;
            }
        }
    } else if (MODE == 1) {
        for (int idx = tid; idx < 8192; idx += 256) {
            int mrow = idx >> 6, pair = idx & 63, col = pair * 2;
            int jj = n0 + col;
            int h = jj >> 5, d = jj & 31;
            int m = m0 + mrow;
            int b = m / Qq, qq = m - b * Qq;
            float v0 = S[mrow * SSTRIDE + col]     * sInv[col]     + sSh[col];
            float v1 = S[mrow * SSTRIDE + col + 1] * sInv[col + 1] + sSh[col + 1];
            __nv_bfloat162 hv, lv;
            split2(v0, v1, hv, lv);
            size_t base = ((size_t)((b * Hh + h) * Qq + qq)) * KDc + d;
            *reinterpret_cast<__nv_bfloat162*>(g_qh + base) = hv;
            *reinterpret_cast<__nv_bfloat162*>(g_ql + base) = lv;
        }
    } else {
        for (int idx = tid; idx < 4096; idx += 256) {
            int mrow = idx >> 5, col = (idx & 31) * 4;
            float4 o;
            o.x = S[mrow * SSTRIDE + col + 0] * sInv[col + 0] + sSh[col + 0];
            o.y = S[mrow * SSTRIDE + col + 1] * sInv[col + 1] + sSh[col + 1];
            o.z = S[mrow * SSTRIDE + col + 2] * sInv[col + 2] + sSh[col + 2];
            o.w = S[mrow * SSTRIDE + col + 3] * sInv[col + 3] + sSh[col + 3];
            *reinterpret_cast<float4*>(Out + (size_t)(m0 + mrow) * 384 + n0 + col) = o;
        }
    }
}

// ---------------------------------------------------------------------------
// Attention via wmma: one block per (b,h), 512 threads / 16 warps.
// scores S[64x208] = (qh+ql)@(kh+kl)^T (3 terms); softmax fp32; P split bf16;
// out[64x64] = (Ph+Pl)@(Vh+Vl) (3 terms).
// ---------------------------------------------------------------------------
#define A_OFF_BS 0
#define A_OFF_QH 832
#define A_OFF_QL 5952
#define A_OFF_KH 11072
#define A_OFF_KL 27712
#define A_OFF_SC 44352
#define A_OFF_PH 98624
#define A_OFF_PL 126272
#define A_OFF_VH 153920
#define A_OFF_VL 183872
#define ATTN_SMEM_BYTES 213824

__global__ __launch_bounds__(512)
void attn_kernel(const float* __restrict__ attn_bias)
{
    extern __shared__ char smc[];
    const uint32_t sb = smem_u32(smc);
    float* bs = (float*)(smc + A_OFF_BS);
    __nv_bfloat16* qh = (__nv_bfloat16*)(smc + A_OFF_QH);   // [64][40]
    __nv_bfloat16* ql = (__nv_bfloat16*)(smc + A_OFF_QL);
    __nv_bfloat16* kh = (__nv_bfloat16*)(smc + A_OFF_KH);   // [208][40]
    __nv_bfloat16* kl = (__nv_bfloat16*)(smc + A_OFF_KL);
    float*         sc = (float*)(smc + A_OFF_SC);           // [64][212]
    __nv_bfloat16* Ph = (__nv_bfloat16*)(smc + A_OFF_PH);   // [64][216]
    __nv_bfloat16* Pl = (__nv_bfloat16*)(smc + A_OFF_PL);
    __nv_bfloat16* Vh = (__nv_bfloat16*)(smc + A_OFF_VH);   // [208][72]
    __nv_bfloat16* Vl = (__nv_bfloat16*)(smc + A_OFF_VL);

    const int blk = blockIdx.x;           // = b*8 + h
    const int h = blk & 7;
    const int tid = threadIdx.x;
    const int wid = tid >> 5, lane = tid & 31;

    // phase 0: load q (49x32), k (196x32) split-bf16; zero pad rows; bias
    {
        const uint4* qhg = (const uint4*)(g_qh + (size_t)blk * (Qq * KDc));
        const uint4* qlg = (const uint4*)(g_ql + (size_t)blk * (Qq * KDc));
        for (int i = tid; i < 196; i += 512) {
            uint32_t d = sb + A_OFF_QH + (i >> 2) * 80 + (i & 3) * 16;
            cp16(d, qhg + i);
            cp16(d + (A_OFF_QL - A_OFF_QH), qlg + i);
        }
        const uint4* khg = (const uint4*)(g_kh + (size_t)blk * (Nn * KDc));
        const uint4* klg = (const uint4*)(g_kl + (size_t)blk * (Nn * KDc));
        for (int i = tid; i < 784; i += 512) {
            uint32_t d = sb + A_OFF_KH + (i >> 2) * 80 + (i & 3) * 16;
            cp16(d, khg + i);
            cp16(d + (A_OFF_KL - A_OFF_KH), klg + i);
        }
        CP_COMMIT();
        uint4 z = {0u, 0u, 0u, 0u};
        for (int i = tid; i < 75; i += 512) {          // q rows 49..63
            int row = 49 + i / 5, seg = i % 5;
            *(uint4*)(smc + A_OFF_QH + row * 80 + seg * 16) = z;
            *(uint4*)(smc + A_OFF_QL + row * 80 + seg * 16) = z;
        }
        for (int i = tid; i < 60; i += 512) {          // k rows 196..207
            int row = 196 + i / 5, seg = i % 5;
            *(uint4*)(smc + A_OFF_KH + row * 80 + seg * 16) = z;
            *(uint4*)(smc + A_OFF_KL + row * 80 + seg * 16) = z;
        }
        for (int i = tid; i < 196; i += 512) bs[i] = attn_bias[h * Nn + i];
        CP_WAIT0();
    }
    __syncthreads();

    // phase 1: scores — 13 warps, one 16-col strip each
    if (wid < 13) {
        const int n0 = wid * 16;
        wmma::fragment<wmma::accumulator, 16, 16, 16, float> acc[4];
#pragma unroll
        for (int mt = 0; mt < 4; mt++) wmma::fill_fragment(acc[mt], 0.0f);
#pragma unroll
        for (int kk = 0; kk < 2; kk++) {
            wmma::fragment<wmma::matrix_b, 16, 16, 16, __nv_bfloat16, wmma::col_major> bh, bl;
            wmma::load_matrix_sync(bh, kh + n0 * 40 + kk * 16, 40);
            wmma::load_matrix_sync(bl, kl + n0 * 40 + kk * 16, 40);
#pragma unroll
            for (int mt = 0; mt < 4; mt++) {
                wmma::fragment<wmma::matrix_a, 16, 16, 16, __nv_bfloat16, wmma::row_major> ah, al;
                wmma::load_matrix_sync(ah, qh + mt * 16 * 40 + kk * 16, 40);
                wmma::load_matrix_sync(al, ql + mt * 16 * 40 + kk * 16, 40);
                wmma::mma_sync(acc[mt], ah, bh, acc[mt]);
                wmma::mma_sync(acc[mt], ah, bl, acc[mt]);
                wmma::mma_sync(acc[mt], al, bh, acc[mt]);
            }
        }
#pragma unroll
        for (int mt = 0; mt < 4; mt++)
            wmma::store_matrix_sync(sc + mt * 16 * 212 + n0, acc[mt], 212, wmma::mem_row_major);
    }
    __syncthreads();

    // phase 2: prefetch V (196x64 x2) under softmax; zero pad rows
    {
        const uint4* vhg = (const uint4*)(g_vh + (size_t)blk * (Nn * VDc));
        const uint4* vlg = (const uint4*)(g_vl + (size_t)blk * (Nn * VDc));
        for (int i = tid; i < 1568; i += 512) {
            uint32_t d = sb + A_OFF_VH + (i >> 3) * 144 + (i & 7) * 16;
            cp16(d, vhg + i);
            cp16(d + (A_OFF_VL - A_OFF_VH), vlg + i);
        }
        CP_COMMIT();
        uint4 z = {0u, 0u, 0u, 0u};
        for (int i = tid; i < 108; i += 512) {         // V rows 196..207
            int row = 196 + i / 9, seg = i % 9;
            *(uint4*)(smc + A_OFF_VH + row * 144 + seg * 16) = z;
            *(uint4*)(smc + A_OFF_VL + row * 144 + seg * 16) = z;
        }
    }

    // phase 3: softmax (fp32), emit P as split bf16
    for (int row = wid; row < Qq; row += 16) {
        int qi2 = 2 * (row / 7), qj2 = 2 * (row % 7);
        float mx = -1e30f;
        for (int n = lane; n < Nn; n += 32) {
            int ki = n / 14, kj = n - ki * 14;
            float val = sc[row * 212 + n] * SCALEc + bs[abs(qi2 - ki) * 14 + abs(qj2 - kj)];
            sc[row * 212 + n] = val;
            mx = fmaxf(mx, val);
        }
#pragma unroll
        for (int o = 16; o > 0; o >>= 1)
            mx = fmaxf(mx, __shfl_xor_sync(0xffffffffu, mx, o));
        float sum = 0.0f;
        for (int n = lane; n < Nn; n += 32) {
            float e = __expf(sc[row * 212 + n] - mx);
            sc[row * 212 + n] = e;
            sum += e;
        }
#pragma unroll
        for (int o = 16; o > 0; o >>= 1)
            sum += __shfl_xor_sync(0xffffffffu, sum, o);
        float rinv = 1.0f / sum;
        for (int n = lane; n < 208; n += 32) {
            float p = (n < Nn) ? sc[row * 212 + n] * rinv : 0.0f;
            __nv_bfloat16 ph = __float2bfloat16_rn(p);
            Ph[row * 216 + n] = ph;
            Pl[row * 216 + n] = __float2bfloat16_rn(p - __bfloat162float(ph));
        }
    }
    CP_WAIT0();
    __syncthreads();

    // phase 4: AV — 16 warps, one 16x16 tile each
    {
        const int mi = wid >> 2, ni = wid & 3;
        wmma::fragment<wmma::accumulator, 16, 16, 16, float> acc;
        wmma::fill_fragment(acc, 0.0f);
#pragma unroll
        for (int kk = 0; kk < 13; kk++) {
            wmma::fragment<wmma::matrix_a, 16, 16, 16, __nv_bfloat16, wmma::row_major> ph_f, pl_f;
            wmma::load_matrix_sync(ph_f, Ph + mi * 16 * 216 + kk * 16, 216);
            wmma::load_matrix_sync(pl_f, Pl + mi * 16 * 216 + kk * 16, 216);
            wmma::fragment<wmma::matrix_b, 16, 16, 16, __nv_bfloat16, wmma::row_major> vh_f, vl_f;
            wmma::load_matrix_sync(vh_f, Vh + kk * 16 * 72 + ni * 16, 72);
            wmma::load_matrix_sync(vl_f, Vl + kk * 16 * 72 + ni * 16, 72);
            wmma::mma_sync(acc, ph_f, vh_f, acc);
            wmma::mma_sync(acc, ph_f, vl_f, acc);
            wmma::mma_sync(acc, pl_f, vh_f, acc);
        }
        // reuse sc region as [64][68] fp32 output stage
        wmma::store_matrix_sync(sc + mi * 16 * 68 + ni * 16, acc, 68, wmma::mem_row_major);
    }
    __syncthreads();

    // phase 5: hardswish + split-bf16 store to g_ah/g_al
    {
        const int b = blk >> 3;
        for (int i = tid; i < 1568; i += 512) {
            int qr = i >> 5, vd = (i & 31) * 2;
            float t0 = sc[qr * 68 + vd];
            float t1 = sc[qr * 68 + vd + 1];
            float o0 = t0 * fminf(fmaxf(t0 + 3.0f, 0.0f), 6.0f) * (1.0f / 6.0f);
            float o1 = t1 * fminf(fmaxf(t1 + 3.0f, 0.0f), 6.0f) * (1.0f / 6.0f);
            __nv_bfloat162 hv, lv;
            split2(o0, o1, hv, lv);
            size_t off = ((size_t)(b * Qq + qr)) * 512 + h * VDc + vd;
            *reinterpret_cast<__nv_bfloat162*>(g_ah + off) = hv;
            *reinterpret_cast<__nv_bfloat162*>(g_al + off) = lv;
        }
    }
}

// ---------------------------------------------------------------------------
extern "C" void kernel_launch(void* const* d_in, const int* in_sizes, int n_in,
                              void* d_out, int out_size)
{
    const float* x      = (const float*)d_in[0];
    const float* kv_w   = (const float*)d_in[1];
    const float* kv_g   = (const float*)d_in[2];
    const float* kv_b   = (const float*)d_in[3];
    const float* kv_m   = (const float*)d_in[4];
    const float* kv_v   = (const float*)d_in[5];
    const float* q_w    = (const float*)d_in[6];
    const float* q_g    = (const float*)d_in[7];
    const float* q_b    = (const float*)d_in[8];
    const float* q_m    = (const float*)d_in[9];
    const float* q_v    = (const float*)d_in[10];
    const float* proj_w = (const float*)d_in[11];
    const float* proj_g = (const float*)d_in[12];
    const float* proj_b = (const float*)d_in[13];
    const float* proj_m = (const float*)d_in[14];
    const float* proj_v = (const float*)d_in[15];
    const float* attn_bias = (const float*)d_in[16];
    float* out = (float*)d_out;

    split_kernel<0><<<(Bc*Nn*256/4 + 255) / 256, 256>>>(x, Bc*Nn*256/4);
    split_kernel<1><<<(768*256/4 + 255) / 256, 256>>>(kv_w, 768*256/4);
    split_kernel<2><<<(256*256/4 + 255) / 256, 256>>>(q_w, 256*256/4);
    split_kernel<3><<<(384*512/4 + 255) / 256, 256>>>(proj_w, 384*512/4);

    cudaFuncSetAttribute(tgemm_kernel<256, 0>, cudaFuncAttributeMaxDynamicSharedMemorySize, GEMM_SMEM_BYTES);
    cudaFuncSetAttribute(tgemm_kernel<256, 1>, cudaFuncAttributeMaxDynamicSharedMemorySize, GEMM_SMEM_BYTES);
    cudaFuncSetAttribute(tgemm_kernel<512, 2>, cudaFuncAttributeMaxDynamicSharedMemorySize, GEMM_SMEM_BYTES);
    cudaFuncSetAttribute(attn_kernel, cudaFuncAttributeMaxDynamicSharedMemorySize, ATTN_SMEM_BYTES);

    // kv GEMM: M=50176, N=768, K=256
    tgemm_kernel<256, 0><<<dim3(392, 6), 256, GEMM_SMEM_BYTES>>>(kv_g, kv_b, kv_m, kv_v, nullptr);
    // q GEMM: M=12544, N=256, K=256 (gathered rows)
    tgemm_kernel<256, 1><<<dim3(98, 2), 256, GEMM_SMEM_BYTES>>>(q_g, q_b, q_m, q_v, nullptr);

    // attention (wmma)
    attn_kernel<<<Bc * Hh, 512, ATTN_SMEM_BYTES>>>(attn_bias);

    // proj GEMM: M=12544, N=384, K=512
    tgemm_kernel<512, 2><<<dim3(98, 3), 256, GEMM_SMEM_BYTES>>>(proj_g, proj_b, proj_m, proj_v, out);
}

// round 7
// speedup vs baseline: 2.7584x; 1.2192x over previous
#include <cuda_runtime.h>
#include <cuda_bf16.h>
#include <cuda_fp16.h>
#include <mma.h>
#include <cstdint>

using namespace nvcuda;

// ---------------- problem constants ----------------
#define Bc   256
#define Nn   196
#define Hh   8
#define KDc  32
#define VDc  64
#define Qq   49
#define EPSc 1e-5f
#define SCALEc 0.17677669529663689f  // 32^-0.5

// ---------------- device scratch ----------------
__device__ __nv_bfloat16 g_xh[Bc*Nn*256],  g_xl[Bc*Nn*256];
__device__ __nv_bfloat16 g_kvwh[768*256],  g_kvwl[768*256];
__device__ __nv_bfloat16 g_qwh[256*256],   g_qwl[256*256];
__device__ __nv_bfloat16 g_pwh[384*512],   g_pwl[384*512];
__device__ __nv_bfloat16 g_ah[Bc*Qq*512],  g_al[Bc*Qq*512];
__device__ __nv_bfloat16 g_kh[Bc*Hh*Nn*KDc], g_kl[Bc*Hh*Nn*KDc];   // [bh,n,d] split bf16
__device__ __half        g_vf[Bc*Hh*Nn*VDc];                        // [bh,n,d] single fp16
__device__ __nv_bfloat16 g_qh[Bc*Hh*Qq*KDc], g_ql[Bc*Hh*Qq*KDc];   // [bh,q,d] split bf16

// ---------------- cp.async helpers ----------------
__device__ __forceinline__ void cp16(uint32_t dst, const void* src) {
    asm volatile("cp.async.cg.shared.global [%0], [%1], 16;" :: "r"(dst), "l"(src));
}
#define CP_COMMIT() asm volatile("cp.async.commit_group;" ::: "memory")
#define CP_WAIT0()  asm volatile("cp.async.wait_group 0;" ::: "memory")

__device__ __forceinline__ uint32_t smem_u32(const void* p) {
    uint32_t a;
    asm("{ .reg .u64 t; cvta.to.shared.u64 t, %1; cvt.u32.u64 %0, t; }" : "=r"(a) : "l"(p));
    return a;
}

__device__ __forceinline__ void split2(float v0, float v1,
                                       __nv_bfloat162& hv, __nv_bfloat162& lv) {
    __nv_bfloat16 h0 = __float2bfloat16_rn(v0);
    __nv_bfloat16 h1 = __float2bfloat16_rn(v1);
    hv.x = h0; hv.y = h1;
    lv.x = __float2bfloat16_rn(v0 - __bfloat162float(h0));
    lv.y = __float2bfloat16_rn(v1 - __bfloat162float(h1));
}

// ---------------- split precompute ----------------
template <int DST>
__global__ void split_kernel(const float* __restrict__ src, int n4)
{
    int i = blockIdx.x * blockDim.x + threadIdx.x;
    if (i >= n4) return;
    __nv_bfloat16* hi; __nv_bfloat16* lo;
    if (DST == 0)      { hi = g_xh;   lo = g_xl;   }
    else if (DST == 1) { hi = g_kvwh; lo = g_kvwl; }
    else if (DST == 2) { hi = g_qwh;  lo = g_qwl;  }
    else               { hi = g_pwh;  lo = g_pwl;  }
    float4 t = reinterpret_cast<const float4*>(src)[i];
    __nv_bfloat162 h01, l01, h23, l23;
    split2(t.x, t.y, h01, l01);
    split2(t.z, t.w, h23, l23);
    reinterpret_cast<__nv_bfloat162*>(hi)[i*2]   = h01;
    reinterpret_cast<__nv_bfloat162*>(hi)[i*2+1] = h23;
    reinterpret_cast<__nv_bfloat162*>(lo)[i*2]   = l01;
    reinterpret_cast<__nv_bfloat162*>(lo)[i*2+1] = l23;
}

// ---------------- GEMM smem layout ----------------
#define TSTRIDE 40
#define OFF_ROW   64
#define OFF_INV   576
#define OFF_SH    1088
#define OFF_TILES 2048
#define STAGE_BYTES 40960
#define OFF_STAGE 2048
#define SSTRIDE   132
#define GEMM_SMEM_BYTES (2048 + 2*STAGE_BYTES)

// ---------------------------------------------------------------------------
// wmma bf16 split GEMM, cp.async double-buffered, linear_norm epilogue.
// MODE 0: -> g_kh/g_kl (split bf16) + g_vf (fp16).  MODE 1: -> g_qh/g_ql.
// MODE 2: A=g_ah/g_al -> Out fp32.
// ---------------------------------------------------------------------------
template <int KDIM, int MODE>
__global__ __launch_bounds__(256, 2)
void tgemm_kernel(const float* __restrict__ gg,
                  const float* __restrict__ bb,
                  const float* __restrict__ mm,
                  const float* __restrict__ vv,
                  float* __restrict__ Out)
{
    extern __shared__ char sm[];
    const uint32_t sb = smem_u32(sm);
    int*   rowoff = (int*)(sm + OFF_ROW);
    float* sInv   = (float*)(sm + OFF_INV);
    float* sSh    = (float*)(sm + OFF_SH);
    float* S      = (float*)(sm + OFF_STAGE);

    const __nv_bfloat16 *Agh, *Agl, *Wgh, *Wgl;
    if (MODE == 0)      { Agh = g_xh; Agl = g_xl; Wgh = g_kvwh; Wgl = g_kvwl; }
    else if (MODE == 1) { Agh = g_xh; Agl = g_xl; Wgh = g_qwh;  Wgl = g_qwl;  }
    else                { Agh = g_ah; Agl = g_al; Wgh = g_pwh;  Wgl = g_pwl;  }

    const int tid = threadIdx.x;
    const int wid = tid >> 5;
    const int m0 = blockIdx.x * 128;
    const int n0 = blockIdx.y * 128;

    if (tid < 128) {
        int m = m0 + tid;
        int off;
        if (MODE == 1) {
            int b = m / Qq, qq = m % Qq;
            int n = (qq / 7) * 28 + (qq % 7) * 2;
            off = (b * Nn + n) * KDIM;
        } else {
            off = m * KDIM;
        }
        rowoff[tid] = off;
        int jj = n0 + tid;
        float inv = gg[jj] * rsqrtf(vv[jj] + EPSc);
        sInv[tid] = inv;
        sSh[tid]  = bb[jj] - mm[jj] * inv;
    }
    __syncthreads();

    const int r0 = tid >> 2,        k8 = (tid & 3) * 8;
    const int r1 = (tid + 256) >> 2;
    const int aoff0 = rowoff[r0] + k8;
    const int aoff1 = rowoff[r1] + k8;
    const int woff0 = (n0 + r0) * KDIM + k8;
    const int woff1 = (n0 + r1) * KDIM + k8;
    const uint32_t so0 = (uint32_t)(r0 * TSTRIDE + k8) * 2;
    const uint32_t so1 = (uint32_t)(r1 * TSTRIDE + k8) * 2;

    const int wm0 = (wid & 3) * 32;
    const int wn0 = (wid >> 2) * 64;

    wmma::fragment<wmma::accumulator, 16, 16, 16, float> acc[2][4];
#pragma unroll
    for (int i = 0; i < 2; i++)
#pragma unroll
        for (int j = 0; j < 4; j++) wmma::fill_fragment(acc[i][j], 0.0f);

    constexpr int NCHUNK = KDIM / 32;

    auto load_chunk = [&](int c, int stage) {
        const uint32_t base = sb + OFF_TILES + stage * STAGE_BYTES;
        const int k0 = c * 32;
        cp16(base + so0,         Agh + aoff0 + k0);
        cp16(base + so1,         Agh + aoff1 + k0);
        cp16(base + 10240 + so0, Agl + aoff0 + k0);
        cp16(base + 10240 + so1, Agl + aoff1 + k0);
        cp16(base + 20480 + so0, Wgh + woff0 + k0);
        cp16(base + 20480 + so1, Wgh + woff1 + k0);
        cp16(base + 30720 + so0, Wgl + woff0 + k0);
        cp16(base + 30720 + so1, Wgl + woff1 + k0);
        CP_COMMIT();
    };

    load_chunk(0, 0);

#pragma unroll 1
    for (int c = 0; c < NCHUNK; c++) {
        CP_WAIT0();
        __syncthreads();
        if (c + 1 < NCHUNK) load_chunk(c + 1, (c + 1) & 1);

        char* st = sm + OFF_TILES + (c & 1) * STAGE_BYTES;
        __nv_bfloat16* Ahs = (__nv_bfloat16*)(st);
        __nv_bfloat16* Als = (__nv_bfloat16*)(st + 10240);
        __nv_bfloat16* Bhs = (__nv_bfloat16*)(st + 20480);
        __nv_bfloat16* Bls = (__nv_bfloat16*)(st + 30720);

#pragma unroll
        for (int kk = 0; kk < 32; kk += 16) {
            wmma::fragment<wmma::matrix_a, 16, 16, 16, __nv_bfloat16, wmma::row_major> ah[2], al[2];
#pragma unroll
            for (int i = 0; i < 2; i++) {
                wmma::load_matrix_sync(ah[i], Ahs + (wm0 + i * 16) * TSTRIDE + kk, TSTRIDE);
                wmma::load_matrix_sync(al[i], Als + (wm0 + i * 16) * TSTRIDE + kk, TSTRIDE);
            }
#pragma unroll
            for (int j = 0; j < 4; j++) {
                wmma::fragment<wmma::matrix_b, 16, 16, 16, __nv_bfloat16, wmma::col_major> bh, bl;
                wmma::load_matrix_sync(bh, Bhs + (wn0 + j * 16) * TSTRIDE + kk, TSTRIDE);
                wmma::load_matrix_sync(bl, Bls + (wn0 + j * 16) * TSTRIDE + kk, TSTRIDE);
#pragma unroll
                for (int i = 0; i < 2; i++) {
                    wmma::mma_sync(acc[i][j], ah[i], bh, acc[i][j]);
                    wmma::mma_sync(acc[i][j], ah[i], bl, acc[i][j]);
                    wmma::mma_sync(acc[i][j], al[i], bh, acc[i][j]);
                }
            }
        }
        __syncthreads();
    }

#pragma unroll
    for (int i = 0; i < 2; i++)
#pragma unroll
        for (int j = 0; j < 4; j++)
            wmma::store_matrix_sync(S + (wm0 + i * 16) * SSTRIDE + wn0 + j * 16,
                                    acc[i][j], SSTRIDE, wmma::mem_row_major);
    __syncthreads();

    if (MODE == 0) {
        for (int idx = tid; idx < 8192; idx += 256) {
            int mrow = idx >> 6, pair = idx & 63, col = pair * 2;
            int jj = n0 + col;
            int h = jj / 96, cch = jj - h * 96;
            int m = m0 + mrow;
            int b = m / Nn, n = m - b * Nn;
            float v0 = S[mrow * SSTRIDE + col]     * sInv[col]     + sSh[col];
            float v1 = S[mrow * SSTRIDE + col + 1] * sInv[col + 1] + sSh[col + 1];
            if (cch < KDc) {
                __nv_bfloat162 hv, lv;
                split2(v0, v1, hv, lv);
                size_t base = ((size_t)((b * Hh + h) * Nn + n)) * KDc + cch;
                *reinterpret_cast<__nv_bfloat162*>(g_kh + base) = hv;
                *reinterpret_cast<__nv_bfloat162*>(g_kl + base) = lv;
            } else {
                size_t base = ((size_t)((b * Hh + h) * Nn + n)) * VDc + (cch - KDc);
                *reinterpret_cast<__half2*>(g_vf + base) = __floats2half2_rn(v0, v1);
            }
        }
    } else if (MODE == 1) {
        for (int idx = tid; idx < 8192; idx += 256) {
            int mrow = idx >> 6, pair = idx & 63, col = pair * 2;
            int jj = n0 + col;
            int h = jj >> 5, d = jj & 31;
            int m = m0 + mrow;
            int b = m / Qq, qq = m - b * Qq;
            float v0 = S[mrow * SSTRIDE + col]     * sInv[col]     + sSh[col];
            float v1 = S[mrow * SSTRIDE + col + 1] * sInv[col + 1] + sSh[col + 1];
            __nv_bfloat162 hv, lv;
            split2(v0, v1, hv, lv);
            size_t base = ((size_t)((b * Hh + h) * Qq + qq)) * KDc + d;
            *reinterpret_cast<__nv_bfloat162*>(g_qh + base) = hv;
            *reinterpret_cast<__nv_bfloat162*>(g_ql + base) = lv;
        }
    } else {
        for (int idx = tid; idx < 4096; idx += 256) {
            int mrow = idx >> 5, col = (idx & 31) * 4;
            float4 o;
            o.x = S[mrow * SSTRIDE + col + 0] * sInv[col + 0] + sSh[col + 0];
            o.y = S[mrow * SSTRIDE + col + 1] * sInv[col + 1] + sSh[col + 1];
            o.z = S[mrow * SSTRIDE + col + 2] * sInv[col + 2] + sSh[col + 2];
            o.w = S[mrow * SSTRIDE + col + 3] * sInv[col + 3] + sSh[col + 3];
            *reinterpret_cast<float4*>(Out + (size_t)(m0 + mrow) * 384 + n0 + col) = o;
        }
    }
}

// ---------------------------------------------------------------------------
// Attention: one block per (b,h), 512 threads, 110 KB smem -> 2 CTAs/SM.
//  scores: 3-term split-bf16 wmma; softmax fp32; AV: single-term fp16 wmma.
// smem layout (bytes):
//   [0,832)        bias (196 fp32)
//   [832,55104)    sc fp32 [64][212]   (phase 4 reuses as out stage [64][68])
//   [55104,112704) region X:
//     phase A: qh[64][40] ql[64][40] kh[208][40] kl[208][40]  (43520 B)
//     phase B: Ph fp16 [64][216] (27648) | Vh fp16 [208][72] (29952)
// ---------------------------------------------------------------------------
#define AT_BIAS 0
#define AT_SC   832
#define AT_X    55104
#define AT_QH   (AT_X)
#define AT_QL   (AT_X + 5120)
#define AT_KH   (AT_X + 10240)
#define AT_KL   (AT_X + 26880)
#define AT_PH   (AT_X)
#define AT_VH   (AT_X + 27648)
#define ATTN_SMEM_BYTES 112704

__global__ __launch_bounds__(512, 2)
void attn_kernel(const float* __restrict__ attn_bias)
{
    extern __shared__ char smc[];
    const uint32_t sb = smem_u32(smc);
    float* bs = (float*)(smc + AT_BIAS);
    float* sc = (float*)(smc + AT_SC);                      // [64][212]
    __nv_bfloat16* qh = (__nv_bfloat16*)(smc + AT_QH);
    __nv_bfloat16* ql = (__nv_bfloat16*)(smc + AT_QL);
    __nv_bfloat16* kh = (__nv_bfloat16*)(smc + AT_KH);
    __nv_bfloat16* kl = (__nv_bfloat16*)(smc + AT_KL);
    __half* Ph = (__half*)(smc + AT_PH);                    // [64][216]
    __half* Vh = (__half*)(smc + AT_VH);                    // [208][72]

    const int blk = blockIdx.x;           // b*8 + h
    const int h = blk & 7;
    const int tid = threadIdx.x;
    const int wid = tid >> 5, lane = tid & 31;

    // phase 0: load q, k (split bf16); zero pads; bias
    {
        const uint4* qhg = (const uint4*)(g_qh + (size_t)blk * (Qq * KDc));
        const uint4* qlg = (const uint4*)(g_ql + (size_t)blk * (Qq * KDc));
        for (int i = tid; i < 196; i += 512) {
            uint32_t d = sb + AT_QH + (i >> 2) * 80 + (i & 3) * 16;
            cp16(d, qhg + i);
            cp16(d + (AT_QL - AT_QH), qlg + i);
        }
        const uint4* khg = (const uint4*)(g_kh + (size_t)blk * (Nn * KDc));
        const uint4* klg = (const uint4*)(g_kl + (size_t)blk * (Nn * KDc));
        for (int i = tid; i < 784; i += 512) {
            uint32_t d = sb + AT_KH + (i >> 2) * 80 + (i & 3) * 16;
            cp16(d, khg + i);
            cp16(d + (AT_KL - AT_KH), klg + i);
        }
        CP_COMMIT();
        uint4 z = {0u, 0u, 0u, 0u};
        for (int i = tid; i < 75; i += 512) {          // q rows 49..63
            int row = 49 + i / 5, seg = i % 5;
            *(uint4*)(smc + AT_QH + row * 80 + seg * 16) = z;
            *(uint4*)(smc + AT_QL + row * 80 + seg * 16) = z;
        }
        for (int i = tid; i < 60; i += 512) {          // k rows 196..207
            int row = 196 + i / 5, seg = i % 5;
            *(uint4*)(smc + AT_KH + row * 80 + seg * 16) = z;
            *(uint4*)(smc + AT_KL + row * 80 + seg * 16) = z;
        }
        for (int i = tid; i < 196; i += 512) bs[i] = attn_bias[h * Nn + i];
        CP_WAIT0();
    }
    __syncthreads();

    // phase 1: scores = (qh+ql)@(kh+kl)^T, 3 terms; 13 warps x 16-col strip
    if (wid < 13) {
        const int n0 = wid * 16;
        wmma::fragment<wmma::accumulator, 16, 16, 16, float> acc[4];
#pragma unroll
        for (int mt = 0; mt < 4; mt++) wmma::fill_fragment(acc[mt], 0.0f);
#pragma unroll
        for (int kk = 0; kk < 2; kk++) {
            wmma::fragment<wmma::matrix_b, 16, 16, 16, __nv_bfloat16, wmma::col_major> bh, bl;
            wmma::load_matrix_sync(bh, kh + n0 * 40 + kk * 16, 40);
            wmma::load_matrix_sync(bl, kl + n0 * 40 + kk * 16, 40);
#pragma unroll
            for (int mt = 0; mt < 4; mt++) {
                wmma::fragment<wmma::matrix_a, 16, 16, 16, __nv_bfloat16, wmma::row_major> ah, al;
                wmma::load_matrix_sync(ah, qh + mt * 16 * 40 + kk * 16, 40);
                wmma::load_matrix_sync(al, ql + mt * 16 * 40 + kk * 16, 40);
                wmma::mma_sync(acc[mt], ah, bh, acc[mt]);
                wmma::mma_sync(acc[mt], ah, bl, acc[mt]);
                wmma::mma_sync(acc[mt], al, bh, acc[mt]);
            }
        }
#pragma unroll
        for (int mt = 0; mt < 4; mt++)
            wmma::store_matrix_sync(sc + mt * 16 * 212 + n0, acc[mt], 212, wmma::mem_row_major);
    }
    __syncthreads();   // after this, q/k region is dead

    // phase 2: prefetch V (fp16) into region X tail; zero pad rows + Ph pad rows
    {
        const uint4* vfg = (const uint4*)(g_vf + (size_t)blk * (Nn * VDc));
        for (int i = tid; i < 1568; i += 512) {
            uint32_t d = sb + AT_VH + (i >> 3) * 144 + (i & 7) * 16;
            cp16(d, vfg + i);
        }
        CP_COMMIT();
        uint4 z = {0u, 0u, 0u, 0u};
        for (int i = tid; i < 108; i += 512) {          // V rows 196..207
            int row = 196 + i / 9, seg = i % 9;
            *(uint4*)(smc + AT_VH + row * 144 + seg * 16) = z;
        }
        for (int i = tid; i < 405; i += 512) {          // Ph rows 49..63
            int row = 49 + i / 27, seg = i % 27;
            *(uint4*)(smc + AT_PH + row * 432 + seg * 16) = z;
        }
    }

    // phase 3: softmax (fp32) -> Ph fp16
    for (int row = wid; row < Qq; row += 16) {
        int qi2 = 2 * (row / 7), qj2 = 2 * (row % 7);
        float mx = -1e30f;
        for (int n = lane; n < Nn; n += 32) {
            int ki = n / 14, kj = n - ki * 14;
            float val = sc[row * 212 + n] * SCALEc + bs[abs(qi2 - ki) * 14 + abs(qj2 - kj)];
            sc[row * 212 + n] = val;
            mx = fmaxf(mx, val);
        }
#pragma unroll
        for (int o = 16; o > 0; o >>= 1)
            mx = fmaxf(mx, __shfl_xor_sync(0xffffffffu, mx, o));
        float sum = 0.0f;
        for (int n = lane; n < Nn; n += 32) {
            float e = __expf(sc[row * 212 + n] - mx);
            sc[row * 212 + n] = e;
            sum += e;
        }
#pragma unroll
        for (int o = 16; o > 0; o >>= 1)
            sum += __shfl_xor_sync(0xffffffffu, sum, o);
        float rinv = 1.0f / sum;
        for (int n = lane; n < 208; n += 32) {
            float p = (n < Nn) ? sc[row * 212 + n] * rinv : 0.0f;
            Ph[row * 216 + n] = __float2half_rn(p);
        }
    }
    CP_WAIT0();
    __syncthreads();   // sc values dead; Ph/Vh ready

    // phase 4: AV = Ph @ Vh (single-term fp16); 16 warps, one 16x16 tile each
    {
        const int mi = wid >> 2, ni = wid & 3;
        wmma::fragment<wmma::accumulator, 16, 16, 16, float> acc;
        wmma::fill_fragment(acc, 0.0f);
#pragma unroll
        for (int kk = 0; kk < 13; kk++) {
            wmma::fragment<wmma::matrix_a, 16, 16, 16, __half, wmma::row_major> pf;
            wmma::fragment<wmma::matrix_b, 16, 16, 16, __half, wmma::row_major> vf;
            wmma::load_matrix_sync(pf, Ph + mi * 16 * 216 + kk * 16, 216);
            wmma::load_matrix_sync(vf, Vh + kk * 16 * 72 + ni * 16, 72);
            wmma::mma_sync(acc, pf, vf, acc);
        }
        wmma::store_matrix_sync(sc + mi * 16 * 68 + ni * 16, acc, 68, wmma::mem_row_major);
    }
    __syncthreads();

    // phase 5: hardswish + split-bf16 store to g_ah/g_al
    {
        const int b = blk >> 3;
        for (int i = tid; i < 1568; i += 512) {
            int qr = i >> 5, vd = (i & 31) * 2;
            float t0 = sc[qr * 68 + vd];
            float t1 = sc[qr * 68 + vd + 1];
            float o0 = t0 * fminf(fmaxf(t0 + 3.0f, 0.0f), 6.0f) * (1.0f / 6.0f);
            float o1 = t1 * fminf(fmaxf(t1 + 3.0f, 0.0f), 6.0f) * (1.0f / 6.0f);
            __nv_bfloat162 hv, lv;
            split2(o0, o1, hv, lv);
            size_t off = ((size_t)(b * Qq + qr)) * 512 + h * VDc + vd;
            *reinterpret_cast<__nv_bfloat162*>(g_ah + off) = hv;
            *reinterpret_cast<__nv_bfloat162*>(g_al + off) = lv;
        }
    }
}

// ---------------------------------------------------------------------------
extern "C" void kernel_launch(void* const* d_in, const int* in_sizes, int n_in,
                              void* d_out, int out_size)
{
    const float* x      = (const float*)d_in[0];
    const float* kv_w   = (const float*)d_in[1];
    const float* kv_g   = (const float*)d_in[2];
    const float* kv_b   = (const float*)d_in[3];
    const float* kv_m   = (const float*)d_in[4];
    const float* kv_v   = (const float*)d_in[5];
    const float* q_w    = (const float*)d_in[6];
    const float* q_g    = (const float*)d_in[7];
    const float* q_b    = (const float*)d_in[8];
    const float* q_m    = (const float*)d_in[9];
    const float* q_v    = (const float*)d_in[10];
    const float* proj_w = (const float*)d_in[11];
    const float* proj_g = (const float*)d_in[12];
    const float* proj_b = (const float*)d_in[13];
    const float* proj_m = (const float*)d_in[14];
    const float* proj_v = (const float*)d_in[15];
    const float* attn_bias = (const float*)d_in[16];
    float* out = (float*)d_out;

    split_kernel<0><<<(Bc*Nn*256/4 + 255) / 256, 256>>>(x, Bc*Nn*256/4);
    split_kernel<1><<<(768*256/4 + 255) / 256, 256>>>(kv_w, 768*256/4);
    split_kernel<2><<<(256*256/4 + 255) / 256, 256>>>(q_w, 256*256/4);
    split_kernel<3><<<(384*512/4 + 255) / 256, 256>>>(proj_w, 384*512/4);

    cudaFuncSetAttribute(tgemm_kernel<256, 0>, cudaFuncAttributeMaxDynamicSharedMemorySize, GEMM_SMEM_BYTES);
    cudaFuncSetAttribute(tgemm_kernel<256, 1>, cudaFuncAttributeMaxDynamicSharedMemorySize, GEMM_SMEM_BYTES);
    cudaFuncSetAttribute(tgemm_kernel<512, 2>, cudaFuncAttributeMaxDynamicSharedMemorySize, GEMM_SMEM_BYTES);
    cudaFuncSetAttribute(attn_kernel, cudaFuncAttributeMaxDynamicSharedMemorySize, ATTN_SMEM_BYTES);

    // kv GEMM: M=50176, N=768, K=256
    tgemm_kernel<256, 0><<<dim3(392, 6), 256, GEMM_SMEM_BYTES>>>(kv_g, kv_b, kv_m, kv_v, nullptr);
    // q GEMM: M=12544, N=256, K=256 (gathered rows)
    tgemm_kernel<256, 1><<<dim3(98, 2), 256, GEMM_SMEM_BYTES>>>(q_g, q_b, q_m, q_v, nullptr);

    // attention (wmma, 2 CTAs/SM)
    attn_kernel<<<Bc * Hh, 512, ATTN_SMEM_BYTES>>>(attn_bias);

    // proj GEMM: M=12544, N=384, K=512
    tgemm_kernel<512, 2><<<dim3(98, 3), 256, GEMM_SMEM_BYTES>>>(proj_g, proj_b, proj_m, proj_v, out);
}

// round 8
// speedup vs baseline: 2.7803x; 1.0080x over previous
#include <cuda_runtime.h>
#include <cuda_bf16.h>
#include <cuda_fp16.h>
#include <mma.h>
#include <cstdint>

using namespace nvcuda;

// ---------------- problem constants ----------------
#define Bc   256
#define Nn   196
#define Hh   8
#define KDc  32
#define VDc  64
#define Qq   49
#define EPSc 1e-5f
#define SCALEc 0.17677669529663689f  // 32^-0.5

// ---------------- device scratch ----------------
__device__ __nv_bfloat16 g_xh[Bc*Nn*256],  g_xl[Bc*Nn*256];
__device__ __nv_bfloat16 g_kvwh[768*256],  g_kvwl[768*256];
__device__ __nv_bfloat16 g_qwh[256*256],   g_qwl[256*256];
__device__ __nv_bfloat16 g_pwh[384*512],   g_pwl[384*512];
__device__ __nv_bfloat16 g_ah[Bc*Qq*512],  g_al[Bc*Qq*512];
__device__ __nv_bfloat16 g_kh[Bc*Hh*Nn*KDc], g_kl[Bc*Hh*Nn*KDc];   // [bh,n,d] split bf16
__device__ __half        g_vf[Bc*Hh*Nn*VDc];                        // [bh,n,d] single fp16
__device__ __nv_bfloat16 g_qh[Bc*Hh*Qq*KDc], g_ql[Bc*Hh*Qq*KDc];   // [bh,q,d] split bf16

// ---------------- cp.async helpers ----------------
__device__ __forceinline__ void cp16(uint32_t dst, const void* src) {
    asm volatile("cp.async.cg.shared.global [%0], [%1], 16;" :: "r"(dst), "l"(src));
}
#define CP_COMMIT() asm volatile("cp.async.commit_group;" ::: "memory")
#define CP_WAIT0()  asm volatile("cp.async.wait_group 0;" ::: "memory")

__device__ __forceinline__ uint32_t smem_u32(const void* p) {
    uint32_t a;
    asm("{ .reg .u64 t; cvta.to.shared.u64 t, %1; cvt.u32.u64 %0, t; }" : "=r"(a) : "l"(p));
    return a;
}

__device__ __forceinline__ void split2(float v0, float v1,
                                       __nv_bfloat162& hv, __nv_bfloat162& lv) {
    __nv_bfloat16 h0 = __float2bfloat16_rn(v0);
    __nv_bfloat16 h1 = __float2bfloat16_rn(v1);
    hv.x = h0; hv.y = h1;
    lv.x = __float2bfloat16_rn(v0 - __bfloat162float(h0));
    lv.y = __float2bfloat16_rn(v1 - __bfloat162float(h1));
}

// ---------------- split precompute ----------------
template <int DST>
__global__ void split_kernel(const float* __restrict__ src, int n4)
{
    int i = blockIdx.x * blockDim.x + threadIdx.x;
    if (i >= n4) return;
    __nv_bfloat16* hi; __nv_bfloat16* lo;
    if (DST == 0)      { hi = g_xh;   lo = g_xl;   }
    else if (DST == 1) { hi = g_kvwh; lo = g_kvwl; }
    else if (DST == 2) { hi = g_qwh;  lo = g_qwl;  }
    else               { hi = g_pwh;  lo = g_pwl;  }
    float4 t = reinterpret_cast<const float4*>(src)[i];
    __nv_bfloat162 h01, l01, h23, l23;
    split2(t.x, t.y, h01, l01);
    split2(t.z, t.w, h23, l23);
    reinterpret_cast<__nv_bfloat162*>(hi)[i*2]   = h01;
    reinterpret_cast<__nv_bfloat162*>(hi)[i*2+1] = h23;
    reinterpret_cast<__nv_bfloat162*>(lo)[i*2]   = l01;
    reinterpret_cast<__nv_bfloat162*>(lo)[i*2+1] = l23;
}

// ---------------- GEMM smem layout ----------------
#define TSTRIDE 40
#define OFF_ROW   64
#define OFF_INV   576
#define OFF_SH    1088
#define OFF_TILES 2048
#define STAGE_BYTES 40960
#define OFF_STAGE 2048
#define SSTRIDE   132
#define GEMM_SMEM_BYTES (2048 + 2*STAGE_BYTES)

// ---------------------------------------------------------------------------
// wmma bf16 split GEMM, cp.async double-buffered, linear_norm epilogue.
// Grid: (N-blocks, M-blocks) — N-major wave order so each A tile is fetched
// into L2 once and reused across all N-blocks within a wave.
// MODE 0: -> g_kh/g_kl (split bf16) + g_vf (fp16).  MODE 1: -> g_qh/g_ql.
// MODE 2: A=g_ah/g_al -> Out fp32.
// ---------------------------------------------------------------------------
template <int KDIM, int MODE>
__global__ __launch_bounds__(256, 2)
void tgemm_kernel(const float* __restrict__ gg,
                  const float* __restrict__ bb,
                  const float* __restrict__ mm,
                  const float* __restrict__ vv,
                  float* __restrict__ Out)
{
    extern __shared__ char sm[];
    const uint32_t sb = smem_u32(sm);
    int*   rowoff = (int*)(sm + OFF_ROW);
    float* sInv   = (float*)(sm + OFF_INV);
    float* sSh    = (float*)(sm + OFF_SH);
    float* S      = (float*)(sm + OFF_STAGE);

    const __nv_bfloat16 *Agh, *Agl, *Wgh, *Wgl;
    if (MODE == 0)      { Agh = g_xh; Agl = g_xl; Wgh = g_kvwh; Wgl = g_kvwl; }
    else if (MODE == 1) { Agh = g_xh; Agl = g_xl; Wgh = g_qwh;  Wgl = g_qwl;  }
    else                { Agh = g_ah; Agl = g_al; Wgh = g_pwh;  Wgl = g_pwl;  }

    const int tid = threadIdx.x;
    const int wid = tid >> 5;
    const int m0 = blockIdx.y * 128;      // M from y (N-major wave order)
    const int n0 = blockIdx.x * 128;      // N from x

    if (tid < 128) {
        int m = m0 + tid;
        int off;
        if (MODE == 1) {
            int b = m / Qq, qq = m % Qq;
            int n = (qq / 7) * 28 + (qq % 7) * 2;
            off = (b * Nn + n) * KDIM;
        } else {
            off = m * KDIM;
        }
        rowoff[tid] = off;
        int jj = n0 + tid;
        float inv = gg[jj] * rsqrtf(vv[jj] + EPSc);
        sInv[tid] = inv;
        sSh[tid]  = bb[jj] - mm[jj] * inv;
    }
    __syncthreads();

    const int r0 = tid >> 2,        k8 = (tid & 3) * 8;
    const int r1 = (tid + 256) >> 2;
    const int aoff0 = rowoff[r0] + k8;
    const int aoff1 = rowoff[r1] + k8;
    const int woff0 = (n0 + r0) * KDIM + k8;
    const int woff1 = (n0 + r1) * KDIM + k8;
    const uint32_t so0 = (uint32_t)(r0 * TSTRIDE + k8) * 2;
    const uint32_t so1 = (uint32_t)(r1 * TSTRIDE + k8) * 2;

    const int wm0 = (wid & 3) * 32;
    const int wn0 = (wid >> 2) * 64;

    wmma::fragment<wmma::accumulator, 16, 16, 16, float> acc[2][4];
#pragma unroll
    for (int i = 0; i < 2; i++)
#pragma unroll
        for (int j = 0; j < 4; j++) wmma::fill_fragment(acc[i][j], 0.0f);

    constexpr int NCHUNK = KDIM / 32;

    auto load_chunk = [&](int c, int stage) {
        const uint32_t base = sb + OFF_TILES + stage * STAGE_BYTES;
        const int k0 = c * 32;
        cp16(base + so0,         Agh + aoff0 + k0);
        cp16(base + so1,         Agh + aoff1 + k0);
        cp16(base + 10240 + so0, Agl + aoff0 + k0);
        cp16(base + 10240 + so1, Agl + aoff1 + k0);
        cp16(base + 20480 + so0, Wgh + woff0 + k0);
        cp16(base + 20480 + so1, Wgh + woff1 + k0);
        cp16(base + 30720 + so0, Wgl + woff0 + k0);
        cp16(base + 30720 + so1, Wgl + woff1 + k0);
        CP_COMMIT();
    };

    load_chunk(0, 0);

#pragma unroll 1
    for (int c = 0; c < NCHUNK; c++) {
        CP_WAIT0();
        __syncthreads();
        if (c + 1 < NCHUNK) load_chunk(c + 1, (c + 1) & 1);

        char* st = sm + OFF_TILES + (c & 1) * STAGE_BYTES;
        __nv_bfloat16* Ahs = (__nv_bfloat16*)(st);
        __nv_bfloat16* Als = (__nv_bfloat16*)(st + 10240);
        __nv_bfloat16* Bhs = (__nv_bfloat16*)(st + 20480);
        __nv_bfloat16* Bls = (__nv_bfloat16*)(st + 30720);

#pragma unroll
        for (int kk = 0; kk < 32; kk += 16) {
            wmma::fragment<wmma::matrix_a, 16, 16, 16, __nv_bfloat16, wmma::row_major> ah[2], al[2];
#pragma unroll
            for (int i = 0; i < 2; i++) {
                wmma::load_matrix_sync(ah[i], Ahs + (wm0 + i * 16) * TSTRIDE + kk, TSTRIDE);
                wmma::load_matrix_sync(al[i], Als + (wm0 + i * 16) * TSTRIDE + kk, TSTRIDE);
            }
#pragma unroll
            for (int j = 0; j < 4; j++) {
                wmma::fragment<wmma::matrix_b, 16, 16, 16, __nv_bfloat16, wmma::col_major> bh, bl;
                wmma::load_matrix_sync(bh, Bhs + (wn0 + j * 16) * TSTRIDE + kk, TSTRIDE);
                wmma::load_matrix_sync(bl, Bls + (wn0 + j * 16) * TSTRIDE + kk, TSTRIDE);
#pragma unroll
                for (int i = 0; i < 2; i++) {
                    wmma::mma_sync(acc[i][j], ah[i], bh, acc[i][j]);
                    wmma::mma_sync(acc[i][j], ah[i], bl, acc[i][j]);
                    wmma::mma_sync(acc[i][j], al[i], bh, acc[i][j]);
                }
            }
        }
        __syncthreads();
    }

#pragma unroll
    for (int i = 0; i < 2; i++)
#pragma unroll
        for (int j = 0; j < 4; j++)
            wmma::store_matrix_sync(S + (wm0 + i * 16) * SSTRIDE + wn0 + j * 16,
                                    acc[i][j], SSTRIDE, wmma::mem_row_major);
    __syncthreads();

    if (MODE == 0) {
        for (int idx = tid; idx < 8192; idx += 256) {
            int mrow = idx >> 6, pair = idx & 63, col = pair * 2;
            int jj = n0 + col;
            int h = jj / 96, cch = jj - h * 96;
            int m = m0 + mrow;
            int b = m / Nn, n = m - b * Nn;
            float v0 = S[mrow * SSTRIDE + col]     * sInv[col]     + sSh[col];
            float v1 = S[mrow * SSTRIDE + col + 1] * sInv[col + 1] + sSh[col + 1];
            if (cch < KDc) {
                __nv_bfloat162 hv, lv;
                split2(v0, v1, hv, lv);
                size_t base = ((size_t)((b * Hh + h) * Nn + n)) * KDc + cch;
                *reinterpret_cast<__nv_bfloat162*>(g_kh + base) = hv;
                *reinterpret_cast<__nv_bfloat162*>(g_kl + base) = lv;
            } else {
                size_t base = ((size_t)((b * Hh + h) * Nn + n)) * VDc + (cch - KDc);
                *reinterpret_cast<__half2*>(g_vf + base) = __floats2half2_rn(v0, v1);
            }
        }
    } else if (MODE == 1) {
        for (int idx = tid; idx < 8192; idx += 256) {
            int mrow = idx >> 6, pair = idx & 63, col = pair * 2;
            int jj = n0 + col;
            int h = jj >> 5, d = jj & 31;
            int m = m0 + mrow;
            int b = m / Qq, qq = m - b * Qq;
            float v0 = S[mrow * SSTRIDE + col]     * sInv[col]     + sSh[col];
            float v1 = S[mrow * SSTRIDE + col + 1] * sInv[col + 1] + sSh[col + 1];
            __nv_bfloat162 hv, lv;
            split2(v0, v1, hv, lv);
            size_t base = ((size_t)((b * Hh + h) * Qq + qq)) * KDc + d;
            *reinterpret_cast<__nv_bfloat162*>(g_qh + base) = hv;
            *reinterpret_cast<__nv_bfloat162*>(g_ql + base) = lv;
        }
    } else {
        for (int idx = tid; idx < 4096; idx += 256) {
            int mrow = idx >> 5, col = (idx & 31) * 4;
            float4 o;
            o.x = S[mrow * SSTRIDE + col + 0] * sInv[col + 0] + sSh[col + 0];
            o.y = S[mrow * SSTRIDE + col + 1] * sInv[col + 1] + sSh[col + 1];
            o.z = S[mrow * SSTRIDE + col + 2] * sInv[col + 2] + sSh[col + 2];
            o.w = S[mrow * SSTRIDE + col + 3] * sInv[col + 3] + sSh[col + 3];
            *reinterpret_cast<float4*>(Out + (size_t)(m0 + mrow) * 384 + n0 + col) = o;
        }
    }
}

// ---------------------------------------------------------------------------
// Attention: one block per (b,h), 512 threads, 110 KB smem -> 2 CTAs/SM.
// ---------------------------------------------------------------------------
#define AT_BIAS 0
#define AT_SC   832
#define AT_X    55104
#define AT_QH   (AT_X)
#define AT_QL   (AT_X + 5120)
#define AT_KH   (AT_X + 10240)
#define AT_KL   (AT_X + 26880)
#define AT_PH   (AT_X)
#define AT_VH   (AT_X + 27648)
#define ATTN_SMEM_BYTES 112704

__global__ __launch_bounds__(512, 2)
void attn_kernel(const float* __restrict__ attn_bias)
{
    extern __shared__ char smc[];
    const uint32_t sb = smem_u32(smc);
    float* bs = (float*)(smc + AT_BIAS);
    float* sc = (float*)(smc + AT_SC);                      // [64][212]
    __nv_bfloat16* qh = (__nv_bfloat16*)(smc + AT_QH);
    __nv_bfloat16* ql = (__nv_bfloat16*)(smc + AT_QL);
    __nv_bfloat16* kh = (__nv_bfloat16*)(smc + AT_KH);
    __nv_bfloat16* kl = (__nv_bfloat16*)(smc + AT_KL);
    __half* Ph = (__half*)(smc + AT_PH);                    // [64][216]
    __half* Vh = (__half*)(smc + AT_VH);                    // [208][72]

    const int blk = blockIdx.x;           // b*8 + h
    const int h = blk & 7;
    const int tid = threadIdx.x;
    const int wid = tid >> 5, lane = tid & 31;

    // phase 0: load q, k (split bf16); zero pads; bias
    {
        const uint4* qhg = (const uint4*)(g_qh + (size_t)blk * (Qq * KDc));
        const uint4* qlg = (const uint4*)(g_ql + (size_t)blk * (Qq * KDc));
        for (int i = tid; i < 196; i += 512) {
            uint32_t d = sb + AT_QH + (i >> 2) * 80 + (i & 3) * 16;
            cp16(d, qhg + i);
            cp16(d + (AT_QL - AT_QH), qlg + i);
        }
        const uint4* khg = (const uint4*)(g_kh + (size_t)blk * (Nn * KDc));
        const uint4* klg = (const uint4*)(g_kl + (size_t)blk * (Nn * KDc));
        for (int i = tid; i < 784; i += 512) {
            uint32_t d = sb + AT_KH + (i >> 2) * 80 + (i & 3) * 16;
            cp16(d, khg + i);
            cp16(d + (AT_KL - AT_KH), klg + i);
        }
        CP_COMMIT();
        uint4 z = {0u, 0u, 0u, 0u};
        for (int i = tid; i < 75; i += 512) {
            int row = 49 + i / 5, seg = i % 5;
            *(uint4*)(smc + AT_QH + row * 80 + seg * 16) = z;
            *(uint4*)(smc + AT_QL + row * 80 + seg * 16) = z;
        }
        for (int i = tid; i < 60; i += 512) {
            int row = 196 + i / 5, seg = i % 5;
            *(uint4*)(smc + AT_KH + row * 80 + seg * 16) = z;
            *(uint4*)(smc + AT_KL + row * 80 + seg * 16) = z;
        }
        for (int i = tid; i < 196; i += 512) bs[i] = attn_bias[h * Nn + i];
        CP_WAIT0();
    }
    __syncthreads();

    // phase 1: scores = (qh+ql)@(kh+kl)^T (3 terms); 13 warps x 16-col strip
    if (wid < 13) {
        const int n0 = wid * 16;
        wmma::fragment<wmma::accumulator, 16, 16, 16, float> acc[4];
#pragma unroll
        for (int mt = 0; mt < 4; mt++) wmma::fill_fragment(acc[mt], 0.0f);
#pragma unroll
        for (int kk = 0; kk < 2; kk++) {
            wmma::fragment<wmma::matrix_b, 16, 16, 16, __nv_bfloat16, wmma::col_major> bh, bl;
            wmma::load_matrix_sync(bh, kh + n0 * 40 + kk * 16, 40);
            wmma::load_matrix_sync(bl, kl + n0 * 40 + kk * 16, 40);
#pragma unroll
            for (int mt = 0; mt < 4; mt++) {
                wmma::fragment<wmma::matrix_a, 16, 16, 16, __nv_bfloat16, wmma::row_major> ah, al;
                wmma::load_matrix_sync(ah, qh + mt * 16 * 40 + kk * 16, 40);
                wmma::load_matrix_sync(al, ql + mt * 16 * 40 + kk * 16, 40);
                wmma::mma_sync(acc[mt], ah, bh, acc[mt]);
                wmma::mma_sync(acc[mt], ah, bl, acc[mt]);
                wmma::mma_sync(acc[mt], al, bh, acc[mt]);
            }
        }
#pragma unroll
        for (int mt = 0; mt < 4; mt++)
            wmma::store_matrix_sync(sc + mt * 16 * 212 + n0, acc[mt], 212, wmma::mem_row_major);
    }
    __syncthreads();

    // phase 2: prefetch V (fp16); zero pad rows + Ph pad rows
    {
        const uint4* vfg = (const uint4*)(g_vf + (size_t)blk * (Nn * VDc));
        for (int i = tid; i < 1568; i += 512) {
            uint32_t d = sb + AT_VH + (i >> 3) * 144 + (i & 7) * 16;
            cp16(d, vfg + i);
        }
        CP_COMMIT();
        uint4 z = {0u, 0u, 0u, 0u};
        for (int i = tid; i < 108; i += 512) {
            int row = 196 + i / 9, seg = i % 9;
            *(uint4*)(smc + AT_VH + row * 144 + seg * 16) = z;
        }
        for (int i = tid; i < 405; i += 512) {
            int row = 49 + i / 27, seg = i % 27;
            *(uint4*)(smc + AT_PH + row * 432 + seg * 16) = z;
        }
    }

    // phase 3: softmax (fp32) -> Ph fp16
    for (int row = wid; row < Qq; row += 16) {
        int qi2 = 2 * (row / 7), qj2 = 2 * (row % 7);
        float mx = -1e30f;
        for (int n = lane; n < Nn; n += 32) {
            int ki = n / 14, kj = n - ki * 14;
            float val = sc[row * 212 + n] * SCALEc + bs[abs(qi2 - ki) * 14 + abs(qj2 - kj)];
            sc[row * 212 + n] = val;
            mx = fmaxf(mx, val);
        }
#pragma unroll
        for (int o = 16; o > 0; o >>= 1)
            mx = fmaxf(mx, __shfl_xor_sync(0xffffffffu, mx, o));
        float sum = 0.0f;
        for (int n = lane; n < Nn; n += 32) {
            float e = __expf(sc[row * 212 + n] - mx);
            sc[row * 212 + n] = e;
            sum += e;
        }
#pragma unroll
        for (int o = 16; o > 0; o >>= 1)
            sum += __shfl_xor_sync(0xffffffffu, sum, o);
        float rinv = 1.0f / sum;
        for (int n = lane; n < 208; n += 32) {
            float p = (n < Nn) ? sc[row * 212 + n] * rinv : 0.0f;
            Ph[row * 216 + n] = __float2half_rn(p);
        }
    }
    CP_WAIT0();
    __syncthreads();

    // phase 4: AV = Ph @ Vh; 16 warps, one 16x16 tile each
    {
        const int mi = wid >> 2, ni = wid & 3;
        wmma::fragment<wmma::accumulator, 16, 16, 16, float> acc;
        wmma::fill_fragment(acc, 0.0f);
#pragma unroll
        for (int kk = 0; kk < 13; kk++) {
            wmma::fragment<wmma::matrix_a, 16, 16, 16, __half, wmma::row_major> pf;
            wmma::fragment<wmma::matrix_b, 16, 16, 16, __half, wmma::row_major> vf;
            wmma::load_matrix_sync(pf, Ph + mi * 16 * 216 + kk * 16, 216);
            wmma::load_matrix_sync(vf, Vh + kk * 16 * 72 + ni * 16, 72);
            wmma::mma_sync(acc, pf, vf, acc);
        }
        wmma::store_matrix_sync(sc + mi * 16 * 68 + ni * 16, acc, 68, wmma::mem_row_major);
    }
    __syncthreads();

    // phase 5: hardswish + split-bf16 store to g_ah/g_al
    {
        const int b = blk >> 3;
        for (int i = tid; i < 1568; i += 512) {
            int qr = i >> 5, vd = (i & 31) * 2;
            float t0 = sc[qr * 68 + vd];
            float t1 = sc[qr * 68 + vd + 1];
            float o0 = t0 * fminf(fmaxf(t0 + 3.0f, 0.0f), 6.0f) * (1.0f / 6.0f);
            float o1 = t1 * fminf(fmaxf(t1 + 3.0f, 0.0f), 6.0f) * (1.0f / 6.0f);
            __nv_bfloat162 hv, lv;
            split2(o0, o1, hv, lv);
            size_t off = ((size_t)(b * Qq + qr)) * 512 + h * VDc + vd;
            *reinterpret_cast<__nv_bfloat162*>(g_ah + off) = hv;
            *reinterpret_cast<__nv_bfloat162*>(g_al + off) = lv;
        }
    }
}

// ---------------------------------------------------------------------------
extern "C" void kernel_launch(void* const* d_in, const int* in_sizes, int n_in,
                              void* d_out, int out_size)
{
    const float* x      = (const float*)d_in[0];
    const float* kv_w   = (const float*)d_in[1];
    const float* kv_g   = (const float*)d_in[2];
    const float* kv_b   = (const float*)d_in[3];
    const float* kv_m   = (const float*)d_in[4];
    const float* kv_v   = (const float*)d_in[5];
    const float* q_w    = (const float*)d_in[6];
    const float* q_g    = (const float*)d_in[7];
    const float* q_b    = (const float*)d_in[8];
    const float* q_m    = (const float*)d_in[9];
    const float* q_v    = (const float*)d_in[10];
    const float* proj_w = (const float*)d_in[11];
    const float* proj_g = (const float*)d_in[12];
    const float* proj_b = (const float*)d_in[13];
    const float* proj_m = (const float*)d_in[14];
    const float* proj_v = (const float*)d_in[15];
    const float* attn_bias = (const float*)d_in[16];
    float* out = (float*)d_out;

    split_kernel<0><<<(Bc*Nn*256/4 + 255) / 256, 256>>>(x, Bc*Nn*256/4);
    split_kernel<1><<<(768*256/4 + 255) / 256, 256>>>(kv_w, 768*256/4);
    split_kernel<2><<<(256*256/4 + 255) / 256, 256>>>(q_w, 256*256/4);
    split_kernel<3><<<(384*512/4 + 255) / 256, 256>>>(proj_w, 384*512/4);

    cudaFuncSetAttribute(tgemm_kernel<256, 0>, cudaFuncAttributeMaxDynamicSharedMemorySize, GEMM_SMEM_BYTES);
    cudaFuncSetAttribute(tgemm_kernel<256, 1>, cudaFuncAttributeMaxDynamicSharedMemorySize, GEMM_SMEM_BYTES);
    cudaFuncSetAttribute(tgemm_kernel<512, 2>, cudaFuncAttributeMaxDynamicSharedMemorySize, GEMM_SMEM_BYTES);
    cudaFuncSetAttribute(attn_kernel, cudaFuncAttributeMaxDynamicSharedMemorySize, ATTN_SMEM_BYTES);

    // kv GEMM: M=50176, N=768, K=256 — grid (N, M) for L2 A-reuse
    tgemm_kernel<256, 0><<<dim3(6, 392), 256, GEMM_SMEM_BYTES>>>(kv_g, kv_b, kv_m, kv_v, nullptr);
    // q GEMM: M=12544, N=256, K=256 (gathered rows)
    tgemm_kernel<256, 1><<<dim3(2, 98), 256, GEMM_SMEM_BYTES>>>(q_g, q_b, q_m, q_v, nullptr);

    // attention (wmma, 2 CTAs/SM)
    attn_kernel<<<Bc * Hh, 512, ATTN_SMEM_BYTES>>>(attn_bias);

    // proj GEMM: M=12544, N=384, K=512 — grid (N, M)
    tgemm_kernel<512, 2><<<dim3(3, 98), 256, GEMM_SMEM_BYTES>>>(proj_g, proj_b, proj_m, proj_v, out);
}

// round 9
// speedup vs baseline: 3.0308x; 1.0901x over previous
#include <cuda_runtime.h>
#include <cuda_bf16.h>
#include <cuda_fp16.h>
#include <mma.h>
#include <cstdint>

using namespace nvcuda;

// ---------------- problem constants ----------------
#define Bc   256
#define Nn   196
#define Hh   8
#define KDc  32
#define VDc  64
#define Qq   49
#define EPSc 1e-5f
#define SCALEc 0.17677669529663689f  // 32^-0.5

// ---------------- device scratch ----------------
__device__ __nv_bfloat16 g_xh[Bc*Nn*256],  g_xl[Bc*Nn*256];
__device__ __nv_bfloat16 g_kvwh[768*256],  g_kvwl[768*256];
__device__ __nv_bfloat16 g_qwh[256*256],   g_qwl[256*256];
__device__ __half        g_pwf[384*512];                            // proj W fp16
__device__ __half        g_af[Bc*Qq*512];                           // attn out fp16
__device__ __nv_bfloat16 g_kh[Bc*Hh*Nn*KDc], g_kl[Bc*Hh*Nn*KDc];   // [bh,n,d] split bf16
__device__ __half        g_vf[Bc*Hh*Nn*VDc];                        // [bh,n,d] fp16
__device__ __nv_bfloat16 g_qh[Bc*Hh*Qq*KDc], g_ql[Bc*Hh*Qq*KDc];   // [bh,q,d] split bf16

// ---------------- cp.async helpers ----------------
__device__ __forceinline__ void cp16(uint32_t dst, const void* src) {
    asm volatile("cp.async.cg.shared.global [%0], [%1], 16;" :: "r"(dst), "l"(src));
}
#define CP_COMMIT() asm volatile("cp.async.commit_group;" ::: "memory")
#define CP_WAIT0()  asm volatile("cp.async.wait_group 0;" ::: "memory")

__device__ __forceinline__ uint32_t smem_u32(const void* p) {
    uint32_t a;
    asm("{ .reg .u64 t; cvta.to.shared.u64 t, %1; cvt.u32.u64 %0, t; }" : "=r"(a) : "l"(p));
    return a;
}

__device__ __forceinline__ void split2(float v0, float v1,
                                       __nv_bfloat162& hv, __nv_bfloat162& lv) {
    __nv_bfloat16 h0 = __float2bfloat16_rn(v0);
    __nv_bfloat16 h1 = __float2bfloat16_rn(v1);
    hv.x = h0; hv.y = h1;
    lv.x = __float2bfloat16_rn(v0 - __bfloat162float(h0));
    lv.y = __float2bfloat16_rn(v1 - __bfloat162float(h1));
}

__device__ __forceinline__ void split_store4(__nv_bfloat16* hi, __nv_bfloat16* lo,
                                             int i, float4 t) {
    __nv_bfloat162 h01, l01, h23, l23;
    split2(t.x, t.y, h01, l01);
    split2(t.z, t.w, h23, l23);
    reinterpret_cast<__nv_bfloat162*>(hi)[i*2]   = h01;
    reinterpret_cast<__nv_bfloat162*>(hi)[i*2+1] = h23;
    reinterpret_cast<__nv_bfloat162*>(lo)[i*2]   = l01;
    reinterpret_cast<__nv_bfloat162*>(lo)[i*2+1] = l23;
}

// ---------------- x split ----------------
__global__ void split_x_kernel(const float* __restrict__ src, int n4)
{
    int i = blockIdx.x * blockDim.x + threadIdx.x;
    if (i >= n4) return;
    split_store4(g_xh, g_xl, i, reinterpret_cast<const float4*>(src)[i]);
}

// ---------------- fused weight precompute: kv_w, q_w (split bf16), proj_w (fp16)
#define NW1 (768*256/4)
#define NW2 (256*256/4)
#define NW3 (384*512/4)
__global__ void split_w_kernel(const float* __restrict__ kv_w,
                               const float* __restrict__ q_w,
                               const float* __restrict__ proj_w)
{
    int i = blockIdx.x * blockDim.x + threadIdx.x;
    if (i < NW1) {
        split_store4(g_kvwh, g_kvwl, i, reinterpret_cast<const float4*>(kv_w)[i]);
    } else if (i < NW1 + NW2) {
        int j = i - NW1;
        split_store4(g_qwh, g_qwl, j, reinterpret_cast<const float4*>(q_w)[j]);
    } else if (i < NW1 + NW2 + NW3) {
        int j = i - NW1 - NW2;
        float4 t = reinterpret_cast<const float4*>(proj_w)[j];
        reinterpret_cast<__half2*>(g_pwf)[j*2]   = __floats2half2_rn(t.x, t.y);
        reinterpret_cast<__half2*>(g_pwf)[j*2+1] = __floats2half2_rn(t.z, t.w);
    }
}

// ---------------- GEMM smem layout ----------------
#define TSTRIDE 40
#define OFF_ROW   64
#define OFF_INV   576
#define OFF_SH    1088
#define OFF_TILES 2048
#define STAGE_BYTES 40960
#define OFF_STAGE 2048
#define SSTRIDE   132
#define GEMM_SMEM_BYTES (2048 + 2*STAGE_BYTES)

// ---------------------------------------------------------------------------
// wmma bf16 split GEMM (3-term), cp.async double-buffered, linear_norm epilogue.
// Grid (N, M). MODE 0: -> g_kh/g_kl + g_vf.  MODE 1: -> g_qh/g_ql.
// ---------------------------------------------------------------------------
template <int KDIM, int MODE>
__global__ __launch_bounds__(256, 2)
void tgemm_kernel(const float* __restrict__ gg,
                  const float* __restrict__ bb,
                  const float* __restrict__ mm,
                  const float* __restrict__ vv)
{
    extern __shared__ char sm[];
    const uint32_t sb = smem_u32(sm);
    int*   rowoff = (int*)(sm + OFF_ROW);
    float* sInv   = (float*)(sm + OFF_INV);
    float* sSh    = (float*)(sm + OFF_SH);
    float* S      = (float*)(sm + OFF_STAGE);

    const __nv_bfloat16 *Agh = g_xh, *Agl = g_xl;
    const __nv_bfloat16 *Wgh, *Wgl;
    if (MODE == 0) { Wgh = g_kvwh; Wgl = g_kvwl; }
    else           { Wgh = g_qwh;  Wgl = g_qwl;  }

    const int tid = threadIdx.x;
    const int wid = tid >> 5;
    const int m0 = blockIdx.y * 128;
    const int n0 = blockIdx.x * 128;

    if (tid < 128) {
        int m = m0 + tid;
        int off;
        if (MODE == 1) {
            int b = m / Qq, qq = m % Qq;
            int n = (qq / 7) * 28 + (qq % 7) * 2;
            off = (b * Nn + n) * KDIM;
        } else {
            off = m * KDIM;
        }
        rowoff[tid] = off;
        int jj = n0 + tid;
        float inv = gg[jj] * rsqrtf(vv[jj] + EPSc);
        sInv[tid] = inv;
        sSh[tid]  = bb[jj] - mm[jj] * inv;
    }
    __syncthreads();

    const int r0 = tid >> 2,        k8 = (tid & 3) * 8;
    const int r1 = (tid + 256) >> 2;
    const int aoff0 = rowoff[r0] + k8;
    const int aoff1 = rowoff[r1] + k8;
    const int woff0 = (n0 + r0) * KDIM + k8;
    const int woff1 = (n0 + r1) * KDIM + k8;
    const uint32_t so0 = (uint32_t)(r0 * TSTRIDE + k8) * 2;
    const uint32_t so1 = (uint32_t)(r1 * TSTRIDE + k8) * 2;

    const int wm0 = (wid & 3) * 32;
    const int wn0 = (wid >> 2) * 64;

    wmma::fragment<wmma::accumulator, 16, 16, 16, float> acc[2][4];
#pragma unroll
    for (int i = 0; i < 2; i++)
#pragma unroll
        for (int j = 0; j < 4; j++) wmma::fill_fragment(acc[i][j], 0.0f);

    constexpr int NCHUNK = KDIM / 32;

    auto load_chunk = [&](int c, int stage) {
        const uint32_t base = sb + OFF_TILES + stage * STAGE_BYTES;
        const int k0 = c * 32;
        cp16(base + so0,         Agh + aoff0 + k0);
        cp16(base + so1,         Agh + aoff1 + k0);
        cp16(base + 10240 + so0, Agl + aoff0 + k0);
        cp16(base + 10240 + so1, Agl + aoff1 + k0);
        cp16(base + 20480 + so0, Wgh + woff0 + k0);
        cp16(base + 20480 + so1, Wgh + woff1 + k0);
        cp16(base + 30720 + so0, Wgl + woff0 + k0);
        cp16(base + 30720 + so1, Wgl + woff1 + k0);
        CP_COMMIT();
    };

    load_chunk(0, 0);

#pragma unroll 1
    for (int c = 0; c < NCHUNK; c++) {
        CP_WAIT0();
        __syncthreads();
        if (c + 1 < NCHUNK) load_chunk(c + 1, (c + 1) & 1);

        char* st = sm + OFF_TILES + (c & 1) * STAGE_BYTES;
        __nv_bfloat16* Ahs = (__nv_bfloat16*)(st);
        __nv_bfloat16* Als = (__nv_bfloat16*)(st + 10240);
        __nv_bfloat16* Bhs = (__nv_bfloat16*)(st + 20480);
        __nv_bfloat16* Bls = (__nv_bfloat16*)(st + 30720);

#pragma unroll
        for (int kk = 0; kk < 32; kk += 16) {
            wmma::fragment<wmma::matrix_a, 16, 16, 16, __nv_bfloat16, wmma::row_major> ah[2], al[2];
#pragma unroll
            for (int i = 0; i < 2; i++) {
                wmma::load_matrix_sync(ah[i], Ahs + (wm0 + i * 16) * TSTRIDE + kk, TSTRIDE);
                wmma::load_matrix_sync(al[i], Als + (wm0 + i * 16) * TSTRIDE + kk, TSTRIDE);
            }
#pragma unroll
            for (int j = 0; j < 4; j++) {
                wmma::fragment<wmma::matrix_b, 16, 16, 16, __nv_bfloat16, wmma::col_major> bh, bl;
                wmma::load_matrix_sync(bh, Bhs + (wn0 + j * 16) * TSTRIDE + kk, TSTRIDE);
                wmma::load_matrix_sync(bl, Bls + (wn0 + j * 16) * TSTRIDE + kk, TSTRIDE);
#pragma unroll
                for (int i = 0; i < 2; i++) {
                    wmma::mma_sync(acc[i][j], ah[i], bh, acc[i][j]);
                    wmma::mma_sync(acc[i][j], ah[i], bl, acc[i][j]);
                    wmma::mma_sync(acc[i][j], al[i], bh, acc[i][j]);
                }
            }
        }
        __syncthreads();
    }

#pragma unroll
    for (int i = 0; i < 2; i++)
#pragma unroll
        for (int j = 0; j < 4; j++)
            wmma::store_matrix_sync(S + (wm0 + i * 16) * SSTRIDE + wn0 + j * 16,
                                    acc[i][j], SSTRIDE, wmma::mem_row_major);
    __syncthreads();

    if (MODE == 0) {
        for (int idx = tid; idx < 8192; idx += 256) {
            int mrow = idx >> 6, pair = idx & 63, col = pair * 2;
            int jj = n0 + col;
            int h = jj / 96, cch = jj - h * 96;
            int m = m0 + mrow;
            int b = m / Nn, n = m - b * Nn;
            float v0 = S[mrow * SSTRIDE + col]     * sInv[col]     + sSh[col];
            float v1 = S[mrow * SSTRIDE + col + 1] * sInv[col + 1] + sSh[col + 1];
            if (cch < KDc) {
                __nv_bfloat162 hv, lv;
                split2(v0, v1, hv, lv);
                size_t base = ((size_t)((b * Hh + h) * Nn + n)) * KDc + cch;
                *reinterpret_cast<__nv_bfloat162*>(g_kh + base) = hv;
                *reinterpret_cast<__nv_bfloat162*>(g_kl + base) = lv;
            } else {
                size_t base = ((size_t)((b * Hh + h) * Nn + n)) * VDc + (cch - KDc);
                *reinterpret_cast<__half2*>(g_vf + base) = __floats2half2_rn(v0, v1);
            }
        }
    } else {
        for (int idx = tid; idx < 8192; idx += 256) {
            int mrow = idx >> 6, pair = idx & 63, col = pair * 2;
            int jj = n0 + col;
            int h = jj >> 5, d = jj & 31;
            int m = m0 + mrow;
            int b = m / Qq, qq = m - b * Qq;
            float v0 = S[mrow * SSTRIDE + col]     * sInv[col]     + sSh[col];
            float v1 = S[mrow * SSTRIDE + col + 1] * sInv[col + 1] + sSh[col + 1];
            __nv_bfloat162 hv, lv;
            split2(v0, v1, hv, lv);
            size_t base = ((size_t)((b * Hh + h) * Qq + qq)) * KDc + d;
            *reinterpret_cast<__nv_bfloat162*>(g_qh + base) = hv;
            *reinterpret_cast<__nv_bfloat162*>(g_ql + base) = lv;
        }
    }
}

// ---------------------------------------------------------------------------
// proj GEMM: single-term fp16. M=12544, N=384, K=512, grid (N, M).
// ---------------------------------------------------------------------------
#define P_STAGE_BYTES 20480
#define PGEMM_SMEM_BYTES 69632   // 2048 + 128*132*4 (epilogue); tiles fit inside

__global__ __launch_bounds__(256, 2)
void pgemm_kernel(const float* __restrict__ gg,
                  const float* __restrict__ bb,
                  const float* __restrict__ mm,
                  const float* __restrict__ vv,
                  float* __restrict__ Out)
{
    extern __shared__ char sm[];
    const uint32_t sb = smem_u32(sm);
    float* sInv = (float*)(sm + OFF_INV);
    float* sSh  = (float*)(sm + OFF_SH);
    float* S    = (float*)(sm + OFF_STAGE);

    const int tid = threadIdx.x;
    const int wid = tid >> 5;
    const int m0 = blockIdx.y * 128;
    const int n0 = blockIdx.x * 128;

    if (tid < 128) {
        int jj = n0 + tid;
        float inv = gg[jj] * rsqrtf(vv[jj] + EPSc);
        sInv[tid] = inv;
        sSh[tid]  = bb[jj] - mm[jj] * inv;
    }
    __syncthreads();

    const int r0 = tid >> 2,        k8 = (tid & 3) * 8;
    const int r1 = (tid + 256) >> 2;
    const int aoff0 = (m0 + r0) * 512 + k8;
    const int aoff1 = (m0 + r1) * 512 + k8;
    const int woff0 = (n0 + r0) * 512 + k8;
    const int woff1 = (n0 + r1) * 512 + k8;
    const uint32_t so0 = (uint32_t)(r0 * TSTRIDE + k8) * 2;
    const uint32_t so1 = (uint32_t)(r1 * TSTRIDE + k8) * 2;

    const int wm0 = (wid & 3) * 32;
    const int wn0 = (wid >> 2) * 64;

    wmma::fragment<wmma::accumulator, 16, 16, 16, float> acc[2][4];
#pragma unroll
    for (int i = 0; i < 2; i++)
#pragma unroll
        for (int j = 0; j < 4; j++) wmma::fill_fragment(acc[i][j], 0.0f);

    auto load_chunk = [&](int c, int stage) {
        const uint32_t base = sb + OFF_TILES + stage * P_STAGE_BYTES;
        const int k0 = c * 32;
        cp16(base + so0,         g_af + aoff0 + k0);
        cp16(base + so1,         g_af + aoff1 + k0);
        cp16(base + 10240 + so0, g_pwf + woff0 + k0);
        cp16(base + 10240 + so1, g_pwf + woff1 + k0);
        CP_COMMIT();
    };

    load_chunk(0, 0);

#pragma unroll 1
    for (int c = 0; c < 16; c++) {
        CP_WAIT0();
        __syncthreads();
        if (c + 1 < 16) load_chunk(c + 1, (c + 1) & 1);

        char* st = sm + OFF_TILES + (c & 1) * P_STAGE_BYTES;
        __half* Afs = (__half*)(st);
        __half* Wfs = (__half*)(st + 10240);

#pragma unroll
        for (int kk = 0; kk < 32; kk += 16) {
            wmma::fragment<wmma::matrix_a, 16, 16, 16, __half, wmma::row_major> af[2];
#pragma unroll
            for (int i = 0; i < 2; i++)
                wmma::load_matrix_sync(af[i], Afs + (wm0 + i * 16) * TSTRIDE + kk, TSTRIDE);
#pragma unroll
            for (int j = 0; j < 4; j++) {
                wmma::fragment<wmma::matrix_b, 16, 16, 16, __half, wmma::col_major> bf;
                wmma::load_matrix_sync(bf, Wfs + (wn0 + j * 16) * TSTRIDE + kk, TSTRIDE);
#pragma unroll
                for (int i = 0; i < 2; i++)
                    wmma::mma_sync(acc[i][j], af[i], bf, acc[i][j]);
            }
        }
        __syncthreads();
    }

#pragma unroll
    for (int i = 0; i < 2; i++)
#pragma unroll
        for (int j = 0; j < 4; j++)
            wmma::store_matrix_sync(S + (wm0 + i * 16) * SSTRIDE + wn0 + j * 16,
                                    acc[i][j], SSTRIDE, wmma::mem_row_major);
    __syncthreads();

    for (int idx = tid; idx < 4096; idx += 256) {
        int mrow = idx >> 5, col = (idx & 31) * 4;
        float4 o;
        o.x = S[mrow * SSTRIDE + col + 0] * sInv[col + 0] + sSh[col + 0];
        o.y = S[mrow * SSTRIDE + col + 1] * sInv[col + 1] + sSh[col + 1];
        o.z = S[mrow * SSTRIDE + col + 2] * sInv[col + 2] + sSh[col + 2];
        o.w = S[mrow * SSTRIDE + col + 3] * sInv[col + 3] + sSh[col + 3];
        *reinterpret_cast<float4*>(Out + (size_t)(m0 + mrow) * 384 + n0 + col) = o;
    }
}

// ---------------------------------------------------------------------------
// Attention: one block per (b,h), 512 threads, 110 KB smem -> 2 CTAs/SM.
// ---------------------------------------------------------------------------
#define AT_BIAS 0
#define AT_SC   832
#define AT_X    55104
#define AT_QH   (AT_X)
#define AT_QL   (AT_X + 5120)
#define AT_KH   (AT_X + 10240)
#define AT_KL   (AT_X + 26880)
#define AT_PH   (AT_X)
#define AT_VH   (AT_X + 27648)
#define ATTN_SMEM_BYTES 112704

__global__ __launch_bounds__(512, 2)
void attn_kernel(const float* __restrict__ attn_bias)
{
    extern __shared__ char smc[];
    const uint32_t sb = smem_u32(smc);
    float* bs = (float*)(smc + AT_BIAS);
    float* sc = (float*)(smc + AT_SC);                      // [64][212]
    __nv_bfloat16* qh = (__nv_bfloat16*)(smc + AT_QH);
    __nv_bfloat16* ql = (__nv_bfloat16*)(smc + AT_QL);
    __nv_bfloat16* kh = (__nv_bfloat16*)(smc + AT_KH);
    __nv_bfloat16* kl = (__nv_bfloat16*)(smc + AT_KL);
    __half* Ph = (__half*)(smc + AT_PH);                    // [64][216]
    __half* Vh = (__half*)(smc + AT_VH);                    // [208][72]

    const int blk = blockIdx.x;           // b*8 + h
    const int h = blk & 7;
    const int tid = threadIdx.x;
    const int wid = tid >> 5, lane = tid & 31;

    // phase 0: load q, k (split bf16); zero pads; bias
    {
        const uint4* qhg = (const uint4*)(g_qh + (size_t)blk * (Qq * KDc));
        const uint4* qlg = (const uint4*)(g_ql + (size_t)blk * (Qq * KDc));
        for (int i = tid; i < 196; i += 512) {
            uint32_t d = sb + AT_QH + (i >> 2) * 80 + (i & 3) * 16;
            cp16(d, qhg + i);
            cp16(d + (AT_QL - AT_QH), qlg + i);
        }
        const uint4* khg = (const uint4*)(g_kh + (size_t)blk * (Nn * KDc));
        const uint4* klg = (const uint4*)(g_kl + (size_t)blk * (Nn * KDc));
        for (int i = tid; i < 784; i += 512) {
            uint32_t d = sb + AT_KH + (i >> 2) * 80 + (i & 3) * 16;
            cp16(d, khg + i);
            cp16(d + (AT_KL - AT_KH), klg + i);
        }
        CP_COMMIT();
        uint4 z = {0u, 0u, 0u, 0u};
        for (int i = tid; i < 75; i += 512) {
            int row = 49 + i / 5, seg = i % 5;
            *(uint4*)(smc + AT_QH + row * 80 + seg * 16) = z;
            *(uint4*)(smc + AT_QL + row * 80 + seg * 16) = z;
        }
        for (int i = tid; i < 60; i += 512) {
            int row = 196 + i / 5, seg = i % 5;
            *(uint4*)(smc + AT_KH + row * 80 + seg * 16) = z;
            *(uint4*)(smc + AT_KL + row * 80 + seg * 16) = z;
        }
        for (int i = tid; i < 196; i += 512) bs[i] = attn_bias[h * Nn + i];
        CP_WAIT0();
    }
    __syncthreads();

    // phase 1: scores = (qh+ql)@(kh+kl)^T (3 terms); 13 warps x 16-col strip
    if (wid < 13) {
        const int n0 = wid * 16;
        wmma::fragment<wmma::accumulator, 16, 16, 16, float> acc[4];
#pragma unroll
        for (int mt = 0; mt < 4; mt++) wmma::fill_fragment(acc[mt], 0.0f);
#pragma unroll
        for (int kk = 0; kk < 2; kk++) {
            wmma::fragment<wmma::matrix_b, 16, 16, 16, __nv_bfloat16, wmma::col_major> bh, bl;
            wmma::load_matrix_sync(bh, kh + n0 * 40 + kk * 16, 40);
            wmma::load_matrix_sync(bl, kl + n0 * 40 + kk * 16, 40);
#pragma unroll
            for (int mt = 0; mt < 4; mt++) {
                wmma::fragment<wmma::matrix_a, 16, 16, 16, __nv_bfloat16, wmma::row_major> ah, al;
                wmma::load_matrix_sync(ah, qh + mt * 16 * 40 + kk * 16, 40);
                wmma::load_matrix_sync(al, ql + mt * 16 * 40 + kk * 16, 40);
                wmma::mma_sync(acc[mt], ah, bh, acc[mt]);
                wmma::mma_sync(acc[mt], ah, bl, acc[mt]);
                wmma::mma_sync(acc[mt], al, bh, acc[mt]);
            }
        }
#pragma unroll
        for (int mt = 0; mt < 4; mt++)
            wmma::store_matrix_sync(sc + mt * 16 * 212 + n0, acc[mt], 212, wmma::mem_row_major);
    }
    __syncthreads();

    // phase 2: prefetch V (fp16); zero pad rows + Ph pad rows
    {
        const uint4* vfg = (const uint4*)(g_vf + (size_t)blk * (Nn * VDc));
        for (int i = tid; i < 1568; i += 512) {
            uint32_t d = sb + AT_VH + (i >> 3) * 144 + (i & 7) * 16;
            cp16(d, vfg + i);
        }
        CP_COMMIT();
        uint4 z = {0u, 0u, 0u, 0u};
        for (int i = tid; i < 108; i += 512) {
            int row = 196 + i / 9, seg = i % 9;
            *(uint4*)(smc + AT_VH + row * 144 + seg * 16) = z;
        }
        for (int i = tid; i < 405; i += 512) {
            int row = 49 + i / 27, seg = i % 27;
            *(uint4*)(smc + AT_PH + row * 432 + seg * 16) = z;
        }
    }

    // phase 3: softmax (fp32) -> Ph fp16
    for (int row = wid; row < Qq; row += 16) {
        int qi2 = 2 * (row / 7), qj2 = 2 * (row % 7);
        float mx = -1e30f;
        for (int n = lane; n < Nn; n += 32) {
            int ki = n / 14, kj = n - ki * 14;
            float val = sc[row * 212 + n] * SCALEc + bs[abs(qi2 - ki) * 14 + abs(qj2 - kj)];
            sc[row * 212 + n] = val;
            mx = fmaxf(mx, val);
        }
#pragma unroll
        for (int o = 16; o > 0; o >>= 1)
            mx = fmaxf(mx, __shfl_xor_sync(0xffffffffu, mx, o));
        float sum = 0.0f;
        for (int n = lane; n < Nn; n += 32) {
            float e = __expf(sc[row * 212 + n] - mx);
            sc[row * 212 + n] = e;
            sum += e;
        }
#pragma unroll
        for (int o = 16; o > 0; o >>= 1)
            sum += __shfl_xor_sync(0xffffffffu, sum, o);
        float rinv = 1.0f / sum;
        for (int n = lane; n < 208; n += 32) {
            float p = (n < Nn) ? sc[row * 212 + n] * rinv : 0.0f;
            Ph[row * 216 + n] = __float2half_rn(p);
        }
    }
    CP_WAIT0();
    __syncthreads();

    // phase 4: AV = Ph @ Vh; 16 warps, one 16x16 tile each
    {
        const int mi = wid >> 2, ni = wid & 3;
        wmma::fragment<wmma::accumulator, 16, 16, 16, float> acc;
        wmma::fill_fragment(acc, 0.0f);
#pragma unroll
        for (int kk = 0; kk < 13; kk++) {
            wmma::fragment<wmma::matrix_a, 16, 16, 16, __half, wmma::row_major> pf;
            wmma::fragment<wmma::matrix_b, 16, 16, 16, __half, wmma::row_major> vf;
            wmma::load_matrix_sync(pf, Ph + mi * 16 * 216 + kk * 16, 216);
            wmma::load_matrix_sync(vf, Vh + kk * 16 * 72 + ni * 16, 72);
            wmma::mma_sync(acc, pf, vf, acc);
        }
        wmma::store_matrix_sync(sc + mi * 16 * 68 + ni * 16, acc, 68, wmma::mem_row_major);
    }
    __syncthreads();

    // phase 5: hardswish + fp16 store to g_af
    {
        const int b = blk >> 3;
        for (int i = tid; i < 1568; i += 512) {
            int qr = i >> 5, vd = (i & 31) * 2;
            float t0 = sc[qr * 68 + vd];
            float t1 = sc[qr * 68 + vd + 1];
            float o0 = t0 * fminf(fmaxf(t0 + 3.0f, 0.0f), 6.0f) * (1.0f / 6.0f);
            float o1 = t1 * fminf(fmaxf(t1 + 3.0f, 0.0f), 6.0f) * (1.0f / 6.0f);
            size_t off = ((size_t)(b * Qq + qr)) * 512 + h * VDc + vd;
            *reinterpret_cast<__half2*>(g_af + off) = __floats2half2_rn(o0, o1);
        }
    }
}

// ---------------------------------------------------------------------------
extern "C" void kernel_launch(void* const* d_in, const int* in_sizes, int n_in,
                              void* d_out, int out_size)
{
    const float* x      = (const float*)d_in[0];
    const float* kv_w   = (const float*)d_in[1];
    const float* kv_g   = (const float*)d_in[2];
    const float* kv_b   = (const float*)d_in[3];
    const float* kv_m   = (const float*)d_in[4];
    const float* kv_v   = (const float*)d_in[5];
    const float* q_w    = (const float*)d_in[6];
    const float* q_g    = (const float*)d_in[7];
    const float* q_b    = (const float*)d_in[8];
    const float* q_m    = (const float*)d_in[9];
    const float* q_v    = (const float*)d_in[10];
    const float* proj_w = (const float*)d_in[11];
    const float* proj_g = (const float*)d_in[12];
    const float* proj_b = (const float*)d_in[13];
    const float* proj_m = (const float*)d_in[14];
    const float* proj_v = (const float*)d_in[15];
    const float* attn_bias = (const float*)d_in[16];
    float* out = (float*)d_out;

    split_x_kernel<<<(Bc*Nn*256/4 + 255) / 256, 256>>>(x, Bc*Nn*256/4);
    split_w_kernel<<<(NW1 + NW2 + NW3 + 255) / 256, 256>>>(kv_w, q_w, proj_w);

    cudaFuncSetAttribute(tgemm_kernel<256, 0>, cudaFuncAttributeMaxDynamicSharedMemorySize, GEMM_SMEM_BYTES);
    cudaFuncSetAttribute(tgemm_kernel<256, 1>, cudaFuncAttributeMaxDynamicSharedMemorySize, GEMM_SMEM_BYTES);
    cudaFuncSetAttribute(pgemm_kernel, cudaFuncAttributeMaxDynamicSharedMemorySize, PGEMM_SMEM_BYTES);
    cudaFuncSetAttribute(attn_kernel, cudaFuncAttributeMaxDynamicSharedMemorySize, ATTN_SMEM_BYTES);

    // kv GEMM: M=50176, N=768, K=256 — grid (N, M)
    tgemm_kernel<256, 0><<<dim3(6, 392), 256, GEMM_SMEM_BYTES>>>(kv_g, kv_b, kv_m, kv_v);
    // q GEMM: M=12544, N=256, K=256 (gathered rows)
    tgemm_kernel<256, 1><<<dim3(2, 98), 256, GEMM_SMEM_BYTES>>>(q_g, q_b, q_m, q_v);

    // attention (wmma, 2 CTAs/SM)
    attn_kernel<<<Bc * Hh, 512, ATTN_SMEM_BYTES>>>(attn_bias);

    // proj GEMM: single-term fp16, M=12544, N=384, K=512 — grid (N, M)
    pgemm_kernel<<<dim3(3, 98), 256, PGEMM_SMEM_BYTES>>>(proj_g, proj_b, proj_m, proj_v, out);
}

// round 10
// speedup vs baseline: 3.1968x; 1.0547x over previous
#include <cuda_runtime.h>
#include <cuda_bf16.h>
#include <cuda_fp16.h>
#include <mma.h>
#include <cstdint>

using namespace nvcuda;

// ---------------- problem constants ----------------
#define Bc   256
#define Nn   196
#define Hh   8
#define KDc  32
#define VDc  64
#define Qq   49
#define EPSc 1e-5f
#define SCALEc 0.17677669529663689f  // 32^-0.5

// ---------------- device scratch ----------------
__device__ __nv_bfloat16 g_xh[Bc*Nn*256],  g_xl[Bc*Nn*256];
__device__ __nv_bfloat16 g_kvwh[768*256],  g_kvwl[768*256];
__device__ __nv_bfloat16 g_qwh[256*256],   g_qwl[256*256];
__device__ __half        g_pwf[384*512];                            // proj W fp16
__device__ __half        g_af[Bc*Qq*512];                           // attn out fp16
__device__ __nv_bfloat16 g_kh[Bc*Hh*Nn*KDc], g_kl[Bc*Hh*Nn*KDc];   // [bh,n,d] split bf16
__device__ __half        g_vf[Bc*Hh*Nn*VDc];                        // [bh,n,d] fp16
__device__ __nv_bfloat16 g_qh[Bc*Hh*Qq*KDc], g_ql[Bc*Hh*Qq*KDc];   // [bh,q,d] split bf16

// ---------------- cp.async helpers ----------------
__device__ __forceinline__ void cp16(uint32_t dst, const void* src) {
    asm volatile("cp.async.cg.shared.global [%0], [%1], 16;" :: "r"(dst), "l"(src));
}
#define CP_COMMIT() asm volatile("cp.async.commit_group;" ::: "memory")
#define CP_WAIT0()  asm volatile("cp.async.wait_group 0;" ::: "memory")

__device__ __forceinline__ uint32_t smem_u32(const void* p) {
    uint32_t a;
    asm("{ .reg .u64 t; cvta.to.shared.u64 t, %1; cvt.u32.u64 %0, t; }" : "=r"(a) : "l"(p));
    return a;
}

__device__ __forceinline__ void split2(float v0, float v1,
                                       __nv_bfloat162& hv, __nv_bfloat162& lv) {
    __nv_bfloat16 h0 = __float2bfloat16_rn(v0);
    __nv_bfloat16 h1 = __float2bfloat16_rn(v1);
    hv.x = h0; hv.y = h1;
    lv.x = __float2bfloat16_rn(v0 - __bfloat162float(h0));
    lv.y = __float2bfloat16_rn(v1 - __bfloat162float(h1));
}

__device__ __forceinline__ void split_store4(__nv_bfloat16* hi, __nv_bfloat16* lo,
                                             int i, float4 t) {
    __nv_bfloat162 h01, l01, h23, l23;
    split2(t.x, t.y, h01, l01);
    split2(t.z, t.w, h23, l23);
    reinterpret_cast<__nv_bfloat162*>(hi)[i*2]   = h01;
    reinterpret_cast<__nv_bfloat162*>(hi)[i*2+1] = h23;
    reinterpret_cast<__nv_bfloat162*>(lo)[i*2]   = l01;
    reinterpret_cast<__nv_bfloat162*>(lo)[i*2+1] = l23;
}

// ---------------- fused precompute: x split, kv_w/q_w split, proj_w fp16 ----
#define NX  (Bc*Nn*256/4)      // 3,211,264
#define NW1 (768*256/4)
#define NW2 (256*256/4)
#define NW3 (384*512/4)
__global__ void split_all_kernel(const float* __restrict__ x,
                                 const float* __restrict__ kv_w,
                                 const float* __restrict__ q_w,
                                 const float* __restrict__ proj_w)
{
    int i = blockIdx.x * blockDim.x + threadIdx.x;
    if (i < NX) {
        split_store4(g_xh, g_xl, i, reinterpret_cast<const float4*>(x)[i]);
    } else if (i < NX + NW1) {
        int j = i - NX;
        split_store4(g_kvwh, g_kvwl, j, reinterpret_cast<const float4*>(kv_w)[j]);
    } else if (i < NX + NW1 + NW2) {
        int j = i - NX - NW1;
        split_store4(g_qwh, g_qwl, j, reinterpret_cast<const float4*>(q_w)[j]);
    } else if (i < NX + NW1 + NW2 + NW3) {
        int j = i - NX - NW1 - NW2;
        float4 t = reinterpret_cast<const float4*>(proj_w)[j];
        reinterpret_cast<__half2*>(g_pwf)[j*2]   = __floats2half2_rn(t.x, t.y);
        reinterpret_cast<__half2*>(g_pwf)[j*2+1] = __floats2half2_rn(t.z, t.w);
    }
}

// ---------------- GEMM smem layout ----------------
#define TSTRIDE 40
#define OFF_ROW   64
#define OFF_INV   576
#define OFF_SH    1088
#define OFF_TILES 2048
#define STAGE_BYTES 40960
#define OFF_STAGE 2048
#define SSTRIDE   132
#define GEMM_SMEM_BYTES (2048 + 2*STAGE_BYTES)

#define KV_BLOCKS 2352    // 6 N-blocks x 392 M-blocks
#define Q_BLOCKS  196     // 2 N-blocks x 98 M-blocks

// ---------------------------------------------------------------------------
// Fused kv + q GEMM (3-term split bf16), cp.async double-buffered.
// blocks [0, 2352): kv   — n0=(bx%6)*128, m0=(bx/6)*128  -> g_kh/g_kl/g_vf
// blocks [2352, 2548): q — n0=(i%2)*128,  m0=(i/2)*128   -> g_qh/g_ql
// ---------------------------------------------------------------------------
__global__ __launch_bounds__(256, 2)
void kvq_gemm_kernel(const float* __restrict__ kv_g, const float* __restrict__ kv_b,
                     const float* __restrict__ kv_m, const float* __restrict__ kv_v,
                     const float* __restrict__ q_g,  const float* __restrict__ q_b,
                     const float* __restrict__ q_m,  const float* __restrict__ q_v)
{
    extern __shared__ char sm[];
    const uint32_t sb = smem_u32(sm);
    int*   rowoff = (int*)(sm + OFF_ROW);
    float* sInv   = (float*)(sm + OFF_INV);
    float* sSh    = (float*)(sm + OFF_SH);
    float* S      = (float*)(sm + OFF_STAGE);

    const int bx = blockIdx.x;
    const bool isq = bx >= KV_BLOCKS;
    int n0, m0;
    const float *gg, *bb, *mm, *vv;
    const __nv_bfloat16 *Wgh, *Wgl;
    if (!isq) {
        n0 = (bx % 6) * 128;  m0 = (bx / 6) * 128;
        gg = kv_g; bb = kv_b; mm = kv_m; vv = kv_v;
        Wgh = g_kvwh; Wgl = g_kvwl;
    } else {
        int i = bx - KV_BLOCKS;
        n0 = (i % 2) * 128;   m0 = (i / 2) * 128;
        gg = q_g; bb = q_b; mm = q_m; vv = q_v;
        Wgh = g_qwh; Wgl = g_qwl;
    }

    const int tid = threadIdx.x;
    const int wid = tid >> 5;

    if (tid < 128) {
        int m = m0 + tid;
        int off;
        if (isq) {
            int b = m / Qq, qq = m % Qq;
            int n = (qq / 7) * 28 + (qq % 7) * 2;
            off = (b * Nn + n) * 256;
        } else {
            off = m * 256;
        }
        rowoff[tid] = off;
        int jj = n0 + tid;
        float inv = gg[jj] * rsqrtf(vv[jj] + EPSc);
        sInv[tid] = inv;
        sSh[tid]  = bb[jj] - mm[jj] * inv;
    }
    __syncthreads();

    const int r0 = tid >> 2,        k8 = (tid & 3) * 8;
    const int r1 = (tid + 256) >> 2;
    const int aoff0 = rowoff[r0] + k8;
    const int aoff1 = rowoff[r1] + k8;
    const int woff0 = (n0 + r0) * 256 + k8;
    const int woff1 = (n0 + r1) * 256 + k8;
    const uint32_t so0 = (uint32_t)(r0 * TSTRIDE + k8) * 2;
    const uint32_t so1 = (uint32_t)(r1 * TSTRIDE + k8) * 2;

    const int wm0 = (wid & 3) * 32;
    const int wn0 = (wid >> 2) * 64;

    wmma::fragment<wmma::accumulator, 16, 16, 16, float> acc[2][4];
#pragma unroll
    for (int i = 0; i < 2; i++)
#pragma unroll
        for (int j = 0; j < 4; j++) wmma::fill_fragment(acc[i][j], 0.0f);

    auto load_chunk = [&](int c, int stage) {
        const uint32_t base = sb + OFF_TILES + stage * STAGE_BYTES;
        const int k0 = c * 32;
        cp16(base + so0,         g_xh + aoff0 + k0);
        cp16(base + so1,         g_xh + aoff1 + k0);
        cp16(base + 10240 + so0, g_xl + aoff0 + k0);
        cp16(base + 10240 + so1, g_xl + aoff1 + k0);
        cp16(base + 20480 + so0, Wgh + woff0 + k0);
        cp16(base + 20480 + so1, Wgh + woff1 + k0);
        cp16(base + 30720 + so0, Wgl + woff0 + k0);
        cp16(base + 30720 + so1, Wgl + woff1 + k0);
        CP_COMMIT();
    };

    load_chunk(0, 0);

#pragma unroll 1
    for (int c = 0; c < 8; c++) {
        CP_WAIT0();
        __syncthreads();
        if (c + 1 < 8) load_chunk(c + 1, (c + 1) & 1);

        char* st = sm + OFF_TILES + (c & 1) * STAGE_BYTES;
        __nv_bfloat16* Ahs = (__nv_bfloat16*)(st);
        __nv_bfloat16* Als = (__nv_bfloat16*)(st + 10240);
        __nv_bfloat16* Bhs = (__nv_bfloat16*)(st + 20480);
        __nv_bfloat16* Bls = (__nv_bfloat16*)(st + 30720);

#pragma unroll
        for (int kk = 0; kk < 32; kk += 16) {
            wmma::fragment<wmma::matrix_a, 16, 16, 16, __nv_bfloat16, wmma::row_major> ah[2], al[2];
#pragma unroll
            for (int i = 0; i < 2; i++) {
                wmma::load_matrix_sync(ah[i], Ahs + (wm0 + i * 16) * TSTRIDE + kk, TSTRIDE);
                wmma::load_matrix_sync(al[i], Als + (wm0 + i * 16) * TSTRIDE + kk, TSTRIDE);
            }
#pragma unroll
            for (int j = 0; j < 4; j++) {
                wmma::fragment<wmma::matrix_b, 16, 16, 16, __nv_bfloat16, wmma::col_major> bh, bl;
                wmma::load_matrix_sync(bh, Bhs + (wn0 + j * 16) * TSTRIDE + kk, TSTRIDE);
                wmma::load_matrix_sync(bl, Bls + (wn0 + j * 16) * TSTRIDE + kk, TSTRIDE);
#pragma unroll
                for (int i = 0; i < 2; i++) {
                    wmma::mma_sync(acc[i][j], ah[i], bh, acc[i][j]);
                    wmma::mma_sync(acc[i][j], ah[i], bl, acc[i][j]);
                    wmma::mma_sync(acc[i][j], al[i], bh, acc[i][j]);
                }
            }
        }
        __syncthreads();
    }

#pragma unroll
    for (int i = 0; i < 2; i++)
#pragma unroll
        for (int j = 0; j < 4; j++)
            wmma::store_matrix_sync(S + (wm0 + i * 16) * SSTRIDE + wn0 + j * 16,
                                    acc[i][j], SSTRIDE, wmma::mem_row_major);
    __syncthreads();

    if (!isq) {
        for (int idx = tid; idx < 8192; idx += 256) {
            int mrow = idx >> 6, pair = idx & 63, col = pair * 2;
            int jj = n0 + col;
            int h = jj / 96, cch = jj - h * 96;
            int m = m0 + mrow;
            int b = m / Nn, n = m - b * Nn;
            float v0 = S[mrow * SSTRIDE + col]     * sInv[col]     + sSh[col];
            float v1 = S[mrow * SSTRIDE + col + 1] * sInv[col + 1] + sSh[col + 1];
            if (cch < KDc) {
                __nv_bfloat162 hv, lv;
                split2(v0, v1, hv, lv);
                size_t base = ((size_t)((b * Hh + h) * Nn + n)) * KDc + cch;
                *reinterpret_cast<__nv_bfloat162*>(g_kh + base) = hv;
                *reinterpret_cast<__nv_bfloat162*>(g_kl + base) = lv;
            } else {
                size_t base = ((size_t)((b * Hh + h) * Nn + n)) * VDc + (cch - KDc);
                *reinterpret_cast<__half2*>(g_vf + base) = __floats2half2_rn(v0, v1);
            }
        }
    } else {
        for (int idx = tid; idx < 8192; idx += 256) {
            int mrow = idx >> 6, pair = idx & 63, col = pair * 2;
            int jj = n0 + col;
            int h = jj >> 5, d = jj & 31;
            int m = m0 + mrow;
            int b = m / Qq, qq = m - b * Qq;
            float v0 = S[mrow * SSTRIDE + col]     * sInv[col]     + sSh[col];
            float v1 = S[mrow * SSTRIDE + col + 1] * sInv[col + 1] + sSh[col + 1];
            __nv_bfloat162 hv, lv;
            split2(v0, v1, hv, lv);
            size_t base = ((size_t)((b * Hh + h) * Qq + qq)) * KDc + d;
            *reinterpret_cast<__nv_bfloat162*>(g_qh + base) = hv;
            *reinterpret_cast<__nv_bfloat162*>(g_ql + base) = lv;
        }
    }
}

// ---------------------------------------------------------------------------
// proj GEMM: single-term fp16. M=12544, N=384, K=512, grid (N, M).
// ---------------------------------------------------------------------------
#define P_STAGE_BYTES 20480
#define PGEMM_SMEM_BYTES 69632

__global__ __launch_bounds__(256, 2)
void pgemm_kernel(const float* __restrict__ gg,
                  const float* __restrict__ bb,
                  const float* __restrict__ mm,
                  const float* __restrict__ vv,
                  float* __restrict__ Out)
{
    extern __shared__ char sm[];
    const uint32_t sb = smem_u32(sm);
    float* sInv = (float*)(sm + OFF_INV);
    float* sSh  = (float*)(sm + OFF_SH);
    float* S    = (float*)(sm + OFF_STAGE);

    const int tid = threadIdx.x;
    const int wid = tid >> 5;
    const int m0 = blockIdx.y * 128;
    const int n0 = blockIdx.x * 128;

    if (tid < 128) {
        int jj = n0 + tid;
        float inv = gg[jj] * rsqrtf(vv[jj] + EPSc);
        sInv[tid] = inv;
        sSh[tid]  = bb[jj] - mm[jj] * inv;
    }
    __syncthreads();

    const int r0 = tid >> 2,        k8 = (tid & 3) * 8;
    const int r1 = (tid + 256) >> 2;
    const int aoff0 = (m0 + r0) * 512 + k8;
    const int aoff1 = (m0 + r1) * 512 + k8;
    const int woff0 = (n0 + r0) * 512 + k8;
    const int woff1 = (n0 + r1) * 512 + k8;
    const uint32_t so0 = (uint32_t)(r0 * TSTRIDE + k8) * 2;
    const uint32_t so1 = (uint32_t)(r1 * TSTRIDE + k8) * 2;

    const int wm0 = (wid & 3) * 32;
    const int wn0 = (wid >> 2) * 64;

    wmma::fragment<wmma::accumulator, 16, 16, 16, float> acc[2][4];
#pragma unroll
    for (int i = 0; i < 2; i++)
#pragma unroll
        for (int j = 0; j < 4; j++) wmma::fill_fragment(acc[i][j], 0.0f);

    auto load_chunk = [&](int c, int stage) {
        const uint32_t base = sb + OFF_TILES + stage * P_STAGE_BYTES;
        const int k0 = c * 32;
        cp16(base + so0,         g_af + aoff0 + k0);
        cp16(base + so1,         g_af + aoff1 + k0);
        cp16(base + 10240 + so0, g_pwf + woff0 + k0);
        cp16(base + 10240 + so1, g_pwf + woff1 + k0);
        CP_COMMIT();
    };

    load_chunk(0, 0);

#pragma unroll 1
    for (int c = 0; c < 16; c++) {
        CP_WAIT0();
        __syncthreads();
        if (c + 1 < 16) load_chunk(c + 1, (c + 1) & 1);

        char* st = sm + OFF_TILES + (c & 1) * P_STAGE_BYTES;
        __half* Afs = (__half*)(st);
        __half* Wfs = (__half*)(st + 10240);

#pragma unroll
        for (int kk = 0; kk < 32; kk += 16) {
            wmma::fragment<wmma::matrix_a, 16, 16, 16, __half, wmma::row_major> af[2];
#pragma unroll
            for (int i = 0; i < 2; i++)
                wmma::load_matrix_sync(af[i], Afs + (wm0 + i * 16) * TSTRIDE + kk, TSTRIDE);
#pragma unroll
            for (int j = 0; j < 4; j++) {
                wmma::fragment<wmma::matrix_b, 16, 16, 16, __half, wmma::col_major> bf;
                wmma::load_matrix_sync(bf, Wfs + (wn0 + j * 16) * TSTRIDE + kk, TSTRIDE);
#pragma unroll
                for (int i = 0; i < 2; i++)
                    wmma::mma_sync(acc[i][j], af[i], bf, acc[i][j]);
            }
        }
        __syncthreads();
    }

#pragma unroll
    for (int i = 0; i < 2; i++)
#pragma unroll
        for (int j = 0; j < 4; j++)
            wmma::store_matrix_sync(S + (wm0 + i * 16) * SSTRIDE + wn0 + j * 16,
                                    acc[i][j], SSTRIDE, wmma::mem_row_major);
    __syncthreads();

    for (int idx = tid; idx < 4096; idx += 256) {
        int mrow = idx >> 5, col = (idx & 31) * 4;
        float4 o;
        o.x = S[mrow * SSTRIDE + col + 0] * sInv[col + 0] + sSh[col + 0];
        o.y = S[mrow * SSTRIDE + col + 1] * sInv[col + 1] + sSh[col + 1];
        o.z = S[mrow * SSTRIDE + col + 2] * sInv[col + 2] + sSh[col + 2];
        o.w = S[mrow * SSTRIDE + col + 3] * sInv[col + 3] + sSh[col + 3];
        *reinterpret_cast<float4*>(Out + (size_t)(m0 + mrow) * 384 + n0 + col) = o;
    }
}

// ---------------------------------------------------------------------------
// Attention: one block per (b,h), 512 threads, 110 KB smem -> 2 CTAs/SM.
// ---------------------------------------------------------------------------
#define AT_BIAS 0
#define AT_SC   832
#define AT_X    55104
#define AT_QH   (AT_X)
#define AT_QL   (AT_X + 5120)
#define AT_KH   (AT_X + 10240)
#define AT_KL   (AT_X + 26880)
#define AT_PH   (AT_X)
#define AT_VH   (AT_X + 27648)
#define ATTN_SMEM_BYTES 112704

__global__ __launch_bounds__(512, 2)
void attn_kernel(const float* __restrict__ attn_bias)
{
    extern __shared__ char smc[];
    const uint32_t sb = smem_u32(smc);
    float* bs = (float*)(smc + AT_BIAS);
    float* sc = (float*)(smc + AT_SC);                      // [64][212]
    __nv_bfloat16* qh = (__nv_bfloat16*)(smc + AT_QH);
    __nv_bfloat16* ql = (__nv_bfloat16*)(smc + AT_QL);
    __nv_bfloat16* kh = (__nv_bfloat16*)(smc + AT_KH);
    __nv_bfloat16* kl = (__nv_bfloat16*)(smc + AT_KL);
    __half* Ph = (__half*)(smc + AT_PH);                    // [64][216]
    __half* Vh = (__half*)(smc + AT_VH);                    // [208][72]

    const int blk = blockIdx.x;           // b*8 + h
    const int h = blk & 7;
    const int tid = threadIdx.x;
    const int wid = tid >> 5, lane = tid & 31;

    // phase 0: load q, k (split bf16); zero pads; bias
    {
        const uint4* qhg = (const uint4*)(g_qh + (size_t)blk * (Qq * KDc));
        const uint4* qlg = (const uint4*)(g_ql + (size_t)blk * (Qq * KDc));
        for (int i = tid; i < 196; i += 512) {
            uint32_t d = sb + AT_QH + (i >> 2) * 80 + (i & 3) * 16;
            cp16(d, qhg + i);
            cp16(d + (AT_QL - AT_QH), qlg + i);
        }
        const uint4* khg = (const uint4*)(g_kh + (size_t)blk * (Nn * KDc));
        const uint4* klg = (const uint4*)(g_kl + (size_t)blk * (Nn * KDc));
        for (int i = tid; i < 784; i += 512) {
            uint32_t d = sb + AT_KH + (i >> 2) * 80 + (i & 3) * 16;
            cp16(d, khg + i);
            cp16(d + (AT_KL - AT_KH), klg + i);
        }
        CP_COMMIT();
        uint4 z = {0u, 0u, 0u, 0u};
        for (int i = tid; i < 75; i += 512) {
            int row = 49 + i / 5, seg = i % 5;
            *(uint4*)(smc + AT_QH + row * 80 + seg * 16) = z;
            *(uint4*)(smc + AT_QL + row * 80 + seg * 16) = z;
        }
        for (int i = tid; i < 60; i += 512) {
            int row = 196 + i / 5, seg = i % 5;
            *(uint4*)(smc + AT_KH + row * 80 + seg * 16) = z;
            *(uint4*)(smc + AT_KL + row * 80 + seg * 16) = z;
        }
        for (int i = tid; i < 196; i += 512) bs[i] = attn_bias[h * Nn + i];
        CP_WAIT0();
    }
    __syncthreads();

    // phase 1: scores = (qh+ql)@(kh+kl)^T (3 terms); 13 warps x 16-col strip
    if (wid < 13) {
        const int n0 = wid * 16;
        wmma::fragment<wmma::accumulator, 16, 16, 16, float> acc[4];
#pragma unroll
        for (int mt = 0; mt < 4; mt++) wmma::fill_fragment(acc[mt], 0.0f);
#pragma unroll
        for (int kk = 0; kk < 2; kk++) {
            wmma::fragment<wmma::matrix_b, 16, 16, 16, __nv_bfloat16, wmma::col_major> bh, bl;
            wmma::load_matrix_sync(bh, kh + n0 * 40 + kk * 16, 40);
            wmma::load_matrix_sync(bl, kl + n0 * 40 + kk * 16, 40);
#pragma unroll
            for (int mt = 0; mt < 4; mt++) {
                wmma::fragment<wmma::matrix_a, 16, 16, 16, __nv_bfloat16, wmma::row_major> ah, al;
                wmma::load_matrix_sync(ah, qh + mt * 16 * 40 + kk * 16, 40);
                wmma::load_matrix_sync(al, ql + mt * 16 * 40 + kk * 16, 40);
                wmma::mma_sync(acc[mt], ah, bh, acc[mt]);
                wmma::mma_sync(acc[mt], ah, bl, acc[mt]);
                wmma::mma_sync(acc[mt], al, bh, acc[mt]);
            }
        }
#pragma unroll
        for (int mt = 0; mt < 4; mt++)
            wmma::store_matrix_sync(sc + mt * 16 * 212 + n0, acc[mt], 212, wmma::mem_row_major);
    }
    __syncthreads();

    // phase 2: prefetch V (fp16); zero pad rows + Ph pad rows
    {
        const uint4* vfg = (const uint4*)(g_vf + (size_t)blk * (Nn * VDc));
        for (int i = tid; i < 1568; i += 512) {
            uint32_t d = sb + AT_VH + (i >> 3) * 144 + (i & 7) * 16;
            cp16(d, vfg + i);
        }
        CP_COMMIT();
        uint4 z = {0u, 0u, 0u, 0u};
        for (int i = tid; i < 108; i += 512) {
            int row = 196 + i / 9, seg = i % 9;
            *(uint4*)(smc + AT_VH + row * 144 + seg * 16) = z;
        }
        for (int i = tid; i < 405; i += 512) {
            int row = 49 + i / 27, seg = i % 27;
            *(uint4*)(smc + AT_PH + row * 432 + seg * 16) = z;
        }
    }

    // phase 3: softmax (fp32) -> Ph fp16
    for (int row = wid; row < Qq; row += 16) {
        int qi2 = 2 * (row / 7), qj2 = 2 * (row % 7);
        float mx = -1e30f;
        for (int n = lane; n < Nn; n += 32) {
            int ki = n / 14, kj = n - ki * 14;
            float val = sc[row * 212 + n] * SCALEc + bs[abs(qi2 - ki) * 14 + abs(qj2 - kj)];
            sc[row * 212 + n] = val;
            mx = fmaxf(mx, val);
        }
#pragma unroll
        for (int o = 16; o > 0; o >>= 1)
            mx = fmaxf(mx, __shfl_xor_sync(0xffffffffu, mx, o));
        float sum = 0.0f;
        for (int n = lane; n < Nn; n += 32) {
            float e = __expf(sc[row * 212 + n] - mx);
            sc[row * 212 + n] = e;
            sum += e;
        }
#pragma unroll
        for (int o = 16; o > 0; o >>= 1)
            sum += __shfl_xor_sync(0xffffffffu, sum, o);
        float rinv = 1.0f / sum;
        for (int n = lane; n < 208; n += 32) {
            float p = (n < Nn) ? sc[row * 212 + n] * rinv : 0.0f;
            Ph[row * 216 + n] = __float2half_rn(p);
        }
    }
    CP_WAIT0();
    __syncthreads();

    // phase 4: AV = Ph @ Vh; 16 warps, one 16x16 tile each
    {
        const int mi = wid >> 2, ni = wid & 3;
        wmma::fragment<wmma::accumulator, 16, 16, 16, float> acc;
        wmma::fill_fragment(acc, 0.0f);
#pragma unroll
        for (int kk = 0; kk < 13; kk++) {
            wmma::fragment<wmma::matrix_a, 16, 16, 16, __half, wmma::row_major> pf;
            wmma::fragment<wmma::matrix_b, 16, 16, 16, __half, wmma::row_major> vf;
            wmma::load_matrix_sync(pf, Ph + mi * 16 * 216 + kk * 16, 216);
            wmma::load_matrix_sync(vf, Vh + kk * 16 * 72 + ni * 16, 72);
            wmma::mma_sync(acc, pf, vf, acc);
        }
        wmma::store_matrix_sync(sc + mi * 16 * 68 + ni * 16, acc, 68, wmma::mem_row_major);
    }
    __syncthreads();

    // phase 5: hardswish + fp16 store to g_af
    {
        const int b = blk >> 3;
        for (int i = tid; i < 1568; i += 512) {
            int qr = i >> 5, vd = (i & 31) * 2;
            float t0 = sc[qr * 68 + vd];
            float t1 = sc[qr * 68 + vd + 1];
            float o0 = t0 * fminf(fmaxf(t0 + 3.0f, 0.0f), 6.0f) * (1.0f / 6.0f);
            float o1 = t1 * fminf(fmaxf(t1 + 3.0f, 0.0f), 6.0f) * (1.0f / 6.0f);
            size_t off = ((size_t)(b * Qq + qr)) * 512 + h * VDc + vd;
            *reinterpret_cast<__half2*>(g_af + off) = __floats2half2_rn(o0, o1);
        }
    }
}

// ---------------------------------------------------------------------------
extern "C" void kernel_launch(void* const* d_in, const int* in_sizes, int n_in,
                              void* d_out, int out_size)
{
    const float* x      = (const float*)d_in[0];
    const float* kv_w   = (const float*)d_in[1];
    const float* kv_g   = (const float*)d_in[2];
    const float* kv_b   = (const float*)d_in[3];
    const float* kv_m   = (const float*)d_in[4];
    const float* kv_v   = (const float*)d_in[5];
    const float* q_w    = (const float*)d_in[6];
    const float* q_g    = (const float*)d_in[7];
    const float* q_b    = (const float*)d_in[8];
    const float* q_m    = (const float*)d_in[9];
    const float* q_v    = (const float*)d_in[10];
    const float* proj_w = (const float*)d_in[11];
    const float* proj_g = (const float*)d_in[12];
    const float* proj_b = (const float*)d_in[13];
    const float* proj_m = (const float*)d_in[14];
    const float* proj_v = (const float*)d_in[15];
    const float* attn_bias = (const float*)d_in[16];
    float* out = (float*)d_out;

    // 1: all precompute in one launch
    split_all_kernel<<<(NX + NW1 + NW2 + NW3 + 255) / 256, 256>>>(x, kv_w, q_w, proj_w);

    cudaFuncSetAttribute(kvq_gemm_kernel, cudaFuncAttributeMaxDynamicSharedMemorySize, GEMM_SMEM_BYTES);
    cudaFuncSetAttribute(pgemm_kernel, cudaFuncAttributeMaxDynamicSharedMemorySize, PGEMM_SMEM_BYTES);
    cudaFuncSetAttribute(attn_kernel, cudaFuncAttributeMaxDynamicSharedMemorySize, ATTN_SMEM_BYTES);

    // 2: fused kv + q GEMM
    kvq_gemm_kernel<<<KV_BLOCKS + Q_BLOCKS, 256, GEMM_SMEM_BYTES>>>(
        kv_g, kv_b, kv_m, kv_v, q_g, q_b, q_m, q_v);

    // 3: attention (wmma, 2 CTAs/SM)
    attn_kernel<<<Bc * Hh, 512, ATTN_SMEM_BYTES>>>(attn_bias);

    // 4: proj GEMM (single-term fp16)
    pgemm_kernel<<<dim3(3, 98), 256, PGEMM_SMEM_BYTES>>>(proj_g, proj_b, proj_m, proj_v, out);
}

// round 11
// speedup vs baseline: 4.0749x; 1.2747x over previous
#include <cuda_runtime.h>
#include <cuda_bf16.h>
#include <cuda_fp16.h>
#include <mma.h>
#include <cstdint>

using namespace nvcuda;

// ---------------- problem constants ----------------
#define Bc   256
#define Nn   196
#define Hh   8
#define KDc  32
#define VDc  64
#define Qq   49
#define EPSc 1e-5f
#define SCALEc 0.17677669529663689f  // 32^-0.5

// ---------------- device scratch ----------------
__device__ __half g_xh[Bc*Nn*256],  g_xl[Bc*Nn*256];   // x fp16 split
__device__ __half g_kwh[256*256],   g_kwl[256*256];    // kv_w K-part, reordered, fp16 split
__device__ __half g_vwf[512*256];                      // kv_w V-part, reordered, fp16
__device__ __half g_qwh[256*256],   g_qwl[256*256];    // q_w fp16 split
__device__ __half g_pwf[384*512];                      // proj W fp16
__device__ __half g_af[Bc*Qq*512];                     // attn out fp16
__device__ __nv_bfloat16 g_kh[Bc*Hh*Nn*KDc], g_kl[Bc*Hh*Nn*KDc];   // [bh,n,d] split bf16
__device__ __half        g_vf[Bc*Hh*Nn*VDc];                        // [bh,n,d] fp16
__device__ __nv_bfloat16 g_qh[Bc*Hh*Qq*KDc], g_ql[Bc*Hh*Qq*KDc];   // [bh,q,d] split bf16

// ---------------- cp.async helpers ----------------
__device__ __forceinline__ void cp16(uint32_t dst, const void* src) {
    asm volatile("cp.async.cg.shared.global [%0], [%1], 16;" :: "r"(dst), "l"(src));
}
#define CP_COMMIT() asm volatile("cp.async.commit_group;" ::: "memory")
#define CP_WAIT0()  asm volatile("cp.async.wait_group 0;" ::: "memory")

__device__ __forceinline__ uint32_t smem_u32(const void* p) {
    uint32_t a;
    asm("{ .reg .u64 t; cvta.to.shared.u64 t, %1; cvt.u32.u64 %0, t; }" : "=r"(a) : "l"(p));
    return a;
}

__device__ __forceinline__ void split2(float v0, float v1,
                                       __nv_bfloat162& hv, __nv_bfloat162& lv) {
    __nv_bfloat16 h0 = __float2bfloat16_rn(v0);
    __nv_bfloat16 h1 = __float2bfloat16_rn(v1);
    hv.x = h0; hv.y = h1;
    lv.x = __float2bfloat16_rn(v0 - __bfloat162float(h0));
    lv.y = __float2bfloat16_rn(v1 - __bfloat162float(h1));
}

__device__ __forceinline__ void fsplit_store4(__half* hi, __half* lo, int i, float4 t) {
    __half h0 = __float2half_rn(t.x), h1 = __float2half_rn(t.y);
    __half h2 = __float2half_rn(t.z), h3 = __float2half_rn(t.w);
    reinterpret_cast<__half2*>(hi)[i*2]   = __halves2half2(h0, h1);
    reinterpret_cast<__half2*>(hi)[i*2+1] = __halves2half2(h2, h3);
    reinterpret_cast<__half2*>(lo)[i*2]   = __halves2half2(
        __float2half_rn(t.x - __half2float(h0)), __float2half_rn(t.y - __half2float(h1)));
    reinterpret_cast<__half2*>(lo)[i*2+1] = __halves2half2(
        __float2half_rn(t.z - __half2float(h2)), __float2half_rn(t.w - __half2float(h3)));
}

// ---------------- fused precompute ----------------
#define NX  (Bc*Nn*256/4)
#define NW1 (768*256/4)
#define NW2 (256*256/4)
#define NW3 (384*512/4)
__global__ void split_all_kernel(const float* __restrict__ x,
                                 const float* __restrict__ kv_w,
                                 const float* __restrict__ q_w,
                                 const float* __restrict__ proj_w)
{
    int i = blockIdx.x * blockDim.x + threadIdx.x;
    if (i < NX) {
        fsplit_store4(g_xh, g_xl, i, reinterpret_cast<const float4*>(x)[i]);
    } else if (i < NX + NW1) {
        int j = i - NX;
        int r = j >> 6;          // kv_w row (64 float4 per 256-col row)
        int c4 = j & 63;
        float4 t = reinterpret_cast<const float4*>(kv_w)[j];
        int h = r / 96, c = r - h * 96;
        if (c < KDc) {
            int di = (h * 32 + c) * 64 + c4;
            fsplit_store4(g_kwh, g_kwl, di, t);
        } else {
            int di = (h * 64 + (c - KDc)) * 64 + c4;
            reinterpret_cast<__half2*>(g_vwf)[di*2]   = __floats2half2_rn(t.x, t.y);
            reinterpret_cast<__half2*>(g_vwf)[di*2+1] = __floats2half2_rn(t.z, t.w);
        }
    } else if (i < NX + NW1 + NW2) {
        int j = i - NX - NW1;
        fsplit_store4(g_qwh, g_qwl, j, reinterpret_cast<const float4*>(q_w)[j]);
    } else if (i < NX + NW1 + NW2 + NW3) {
        int j = i - NX - NW1 - NW2;
        float4 t = reinterpret_cast<const float4*>(proj_w)[j];
        reinterpret_cast<__half2*>(g_pwf)[j*2]   = __floats2half2_rn(t.x, t.y);
        reinterpret_cast<__half2*>(g_pwf)[j*2+1] = __floats2half2_rn(t.z, t.w);
    }
}

// ---------------- GEMM smem layout ----------------
#define TSTRIDE 40
#define OFF_ROW   64
#define OFF_INV   576
#define OFF_SH    1088
#define OFF_TILES 2048
#define STAGE_BYTES 40960      // 3-term path (4 tiles)
#define V_STAGE_BYTES 20480    // 1-term path (2 tiles)
#define OFF_STAGE 2048
#define SSTRIDE   132
#define GEMM_SMEM_BYTES (2048 + 2*STAGE_BYTES)

#define KB 784                 // K-part blocks: 2 n-tiles x 392
#define VB 2352                // + V-part: 4 n-tiles x 392 = 1568
#define TOTAL_B 2548           // + q: 2 n-tiles x 98 = 196

// ---------------------------------------------------------------------------
// Fused K/V/q GEMM. K & q: 3-term fp16-split. V: single-term fp16.
// ---------------------------------------------------------------------------
__global__ __launch_bounds__(256, 2)
void kvq_gemm_kernel(const float* __restrict__ kv_g, const float* __restrict__ kv_b,
                     const float* __restrict__ kv_m, const float* __restrict__ kv_v,
                     const float* __restrict__ q_g,  const float* __restrict__ q_b,
                     const float* __restrict__ q_m,  const float* __restrict__ q_v)
{
    extern __shared__ char sm[];
    const uint32_t sb = smem_u32(sm);
    int*   rowoff = (int*)(sm + OFF_ROW);
    float* sInv   = (float*)(sm + OFF_INV);
    float* sSh    = (float*)(sm + OFF_SH);
    float* S      = (float*)(sm + OFF_STAGE);

    const int bx = blockIdx.x;
    int mode, n0, m0;
    if (bx < KB)      { mode = 0; n0 = (bx & 1) * 128;  m0 = (bx >> 1) * 128; }
    else if (bx < VB) { int i = bx - KB; mode = 1; n0 = (i & 3) * 128; m0 = (i >> 2) * 128; }
    else              { int i = bx - VB; mode = 2; n0 = (i & 1) * 128; m0 = (i >> 1) * 128; }

    const __half *Wh, *Wl;
    if (mode == 0)      { Wh = g_kwh; Wl = g_kwl; }
    else if (mode == 1) { Wh = g_vwf; Wl = g_vwf; }
    else                { Wh = g_qwh; Wl = g_qwl; }

    const int tid = threadIdx.x;
    const int wid = tid >> 5;

    if (tid < 128) {
        int m = m0 + tid;
        int off;
        if (mode == 2) {
            int b = m / Qq, qq = m % Qq;
            int n = (qq / 7) * 28 + (qq % 7) * 2;
            off = (b * Nn + n) * 256;
        } else {
            off = m * 256;
        }
        rowoff[tid] = off;
        int jj = n0 + tid;
        int jo;
        const float *gg, *bb, *mm, *vv;
        if (mode == 0)      { jo = (jj >> 5) * 96 + (jj & 31);        gg = kv_g; bb = kv_b; mm = kv_m; vv = kv_v; }
        else if (mode == 1) { jo = (jj >> 6) * 96 + KDc + (jj & 63);  gg = kv_g; bb = kv_b; mm = kv_m; vv = kv_v; }
        else                { jo = jj;                                 gg = q_g;  bb = q_b;  mm = q_m;  vv = q_v;  }
        float inv = gg[jo] * rsqrtf(vv[jo] + EPSc);
        sInv[tid] = inv;
        sSh[tid]  = bb[jo] - mm[jo] * inv;
    }
    __syncthreads();

    const int r0 = tid >> 2,        k8 = (tid & 3) * 8;
    const int r1 = (tid + 256) >> 2;
    const int aoff0 = rowoff[r0] + k8;
    const int aoff1 = rowoff[r1] + k8;
    const int woff0 = (n0 + r0) * 256 + k8;
    const int woff1 = (n0 + r1) * 256 + k8;
    const uint32_t so0 = (uint32_t)(r0 * TSTRIDE + k8) * 2;
    const uint32_t so1 = (uint32_t)(r1 * TSTRIDE + k8) * 2;

    const int wm0 = (wid & 3) * 32;
    const int wn0 = (wid >> 2) * 64;

    wmma::fragment<wmma::accumulator, 16, 16, 16, float> acc[2][4];
#pragma unroll
    for (int i = 0; i < 2; i++)
#pragma unroll
        for (int j = 0; j < 4; j++) wmma::fill_fragment(acc[i][j], 0.0f);

    if (mode == 1) {
        // -------- single-term fp16: tiles Ah | Wf --------
        auto load1 = [&](int c, int stage) {
            const uint32_t base = sb + OFF_TILES + stage * V_STAGE_BYTES;
            const int k0 = c * 32;
            cp16(base + so0,         g_xh + aoff0 + k0);
            cp16(base + so1,         g_xh + aoff1 + k0);
            cp16(base + 10240 + so0, Wh + woff0 + k0);
            cp16(base + 10240 + so1, Wh + woff1 + k0);
            CP_COMMIT();
        };
        load1(0, 0);
#pragma unroll 1
        for (int c = 0; c < 8; c++) {
            CP_WAIT0();
            __syncthreads();
            if (c + 1 < 8) load1(c + 1, (c + 1) & 1);
            char* st = sm + OFF_TILES + (c & 1) * V_STAGE_BYTES;
            __half* Ahs = (__half*)(st);
            __half* Wfs = (__half*)(st + 10240);
#pragma unroll
            for (int kk = 0; kk < 32; kk += 16) {
                wmma::fragment<wmma::matrix_a, 16, 16, 16, __half, wmma::row_major> af[2];
#pragma unroll
                for (int i = 0; i < 2; i++)
                    wmma::load_matrix_sync(af[i], Ahs + (wm0 + i * 16) * TSTRIDE + kk, TSTRIDE);
#pragma unroll
                for (int j = 0; j < 4; j++) {
                    wmma::fragment<wmma::matrix_b, 16, 16, 16, __half, wmma::col_major> bf;
                    wmma::load_matrix_sync(bf, Wfs + (wn0 + j * 16) * TSTRIDE + kk, TSTRIDE);
#pragma unroll
                    for (int i = 0; i < 2; i++)
                        wmma::mma_sync(acc[i][j], af[i], bf, acc[i][j]);
                }
            }
            __syncthreads();
        }
    } else {
        // -------- 3-term fp16-split: tiles Ah | Al | Wh | Wl --------
        auto load3 = [&](int c, int stage) {
            const uint32_t base = sb + OFF_TILES + stage * STAGE_BYTES;
            const int k0 = c * 32;
            cp16(base + so0,         g_xh + aoff0 + k0);
            cp16(base + so1,         g_xh + aoff1 + k0);
            cp16(base + 10240 + so0, g_xl + aoff0 + k0);
            cp16(base + 10240 + so1, g_xl + aoff1 + k0);
            cp16(base + 20480 + so0, Wh + woff0 + k0);
            cp16(base + 20480 + so1, Wh + woff1 + k0);
            cp16(base + 30720 + so0, Wl + woff0 + k0);
            cp16(base + 30720 + so1, Wl + woff1 + k0);
            CP_COMMIT();
        };
        load3(0, 0);
#pragma unroll 1
        for (int c = 0; c < 8; c++) {
            CP_WAIT0();
            __syncthreads();
            if (c + 1 < 8) load3(c + 1, (c + 1) & 1);
            char* st = sm + OFF_TILES + (c & 1) * STAGE_BYTES;
            __half* Ahs = (__half*)(st);
            __half* Als = (__half*)(st + 10240);
            __half* Bhs = (__half*)(st + 20480);
            __half* Bls = (__half*)(st + 30720);
#pragma unroll
            for (int kk = 0; kk < 32; kk += 16) {
                wmma::fragment<wmma::matrix_a, 16, 16, 16, __half, wmma::row_major> ah[2], al[2];
#pragma unroll
                for (int i = 0; i < 2; i++) {
                    wmma::load_matrix_sync(ah[i], Ahs + (wm0 + i * 16) * TSTRIDE + kk, TSTRIDE);
                    wmma::load_matrix_sync(al[i], Als + (wm0 + i * 16) * TSTRIDE + kk, TSTRIDE);
                }
#pragma unroll
                for (int j = 0; j < 4; j++) {
                    wmma::fragment<wmma::matrix_b, 16, 16, 16, __half, wmma::col_major> bh, bl;
                    wmma::load_matrix_sync(bh, Bhs + (wn0 + j * 16) * TSTRIDE + kk, TSTRIDE);
                    wmma::load_matrix_sync(bl, Bls + (wn0 + j * 16) * TSTRIDE + kk, TSTRIDE);
#pragma unroll
                    for (int i = 0; i < 2; i++) {
                        wmma::mma_sync(acc[i][j], ah[i], bh, acc[i][j]);
                        wmma::mma_sync(acc[i][j], ah[i], bl, acc[i][j]);
                        wmma::mma_sync(acc[i][j], al[i], bh, acc[i][j]);
                    }
                }
            }
            __syncthreads();
        }
    }

#pragma unroll
    for (int i = 0; i < 2; i++)
#pragma unroll
        for (int j = 0; j < 4; j++)
            wmma::store_matrix_sync(S + (wm0 + i * 16) * SSTRIDE + wn0 + j * 16,
                                    acc[i][j], SSTRIDE, wmma::mem_row_major);
    __syncthreads();

    for (int idx = tid; idx < 8192; idx += 256) {
        int mrow = idx >> 6, pair = idx & 63, col = pair * 2;
        int jj = n0 + col;
        int m = m0 + mrow;
        float v0 = S[mrow * SSTRIDE + col]     * sInv[col]     + sSh[col];
        float v1 = S[mrow * SSTRIDE + col + 1] * sInv[col + 1] + sSh[col + 1];
        if (mode == 0) {
            int h = jj >> 5, d = jj & 31;
            int b = m / Nn, n = m - b * Nn;
            __nv_bfloat162 hv, lv;
            split2(v0, v1, hv, lv);
            size_t base = ((size_t)((b * Hh + h) * Nn + n)) * KDc + d;
            *reinterpret_cast<__nv_bfloat162*>(g_kh + base) = hv;
            *reinterpret_cast<__nv_bfloat162*>(g_kl + base) = lv;
        } else if (mode == 1) {
            int h = jj >> 6, d = jj & 63;
            int b = m / Nn, n = m - b * Nn;
            size_t base = ((size_t)((b * Hh + h) * Nn + n)) * VDc + d;
            *reinterpret_cast<__half2*>(g_vf + base) = __floats2half2_rn(v0, v1);
        } else {
            int h = jj >> 5, d = jj & 31;
            int b = m / Qq, qq = m - b * Qq;
            __nv_bfloat162 hv, lv;
            split2(v0, v1, hv, lv);
            size_t base = ((size_t)((b * Hh + h) * Qq + qq)) * KDc + d;
            *reinterpret_cast<__nv_bfloat162*>(g_qh + base) = hv;
            *reinterpret_cast<__nv_bfloat162*>(g_ql + base) = lv;
        }
    }
}

// ---------------------------------------------------------------------------
// proj GEMM: single-term fp16. M=12544, N=384, K=512, grid (N, M).
// ---------------------------------------------------------------------------
#define P_STAGE_BYTES 20480
#define PGEMM_SMEM_BYTES 69632

__global__ __launch_bounds__(256, 2)
void pgemm_kernel(const float* __restrict__ gg,
                  const float* __restrict__ bb,
                  const float* __restrict__ mm,
                  const float* __restrict__ vv,
                  float* __restrict__ Out)
{
    extern __shared__ char sm[];
    const uint32_t sb = smem_u32(sm);
    float* sInv = (float*)(sm + OFF_INV);
    float* sSh  = (float*)(sm + OFF_SH);
    float* S    = (float*)(sm + OFF_STAGE);

    const int tid = threadIdx.x;
    const int wid = tid >> 5;
    const int m0 = blockIdx.y * 128;
    const int n0 = blockIdx.x * 128;

    if (tid < 128) {
        int jj = n0 + tid;
        float inv = gg[jj] * rsqrtf(vv[jj] + EPSc);
        sInv[tid] = inv;
        sSh[tid]  = bb[jj] - mm[jj] * inv;
    }
    __syncthreads();

    const int r0 = tid >> 2,        k8 = (tid & 3) * 8;
    const int r1 = (tid + 256) >> 2;
    const int aoff0 = (m0 + r0) * 512 + k8;
    const int aoff1 = (m0 + r1) * 512 + k8;
    const int woff0 = (n0 + r0) * 512 + k8;
    const int woff1 = (n0 + r1) * 512 + k8;
    const uint32_t so0 = (uint32_t)(r0 * TSTRIDE + k8) * 2;
    const uint32_t so1 = (uint32_t)(r1 * TSTRIDE + k8) * 2;

    const int wm0 = (wid & 3) * 32;
    const int wn0 = (wid >> 2) * 64;

    wmma::fragment<wmma::accumulator, 16, 16, 16, float> acc[2][4];
#pragma unroll
    for (int i = 0; i < 2; i++)
#pragma unroll
        for (int j = 0; j < 4; j++) wmma::fill_fragment(acc[i][j], 0.0f);

    auto load_chunk = [&](int c, int stage) {
        const uint32_t base = sb + OFF_TILES + stage * P_STAGE_BYTES;
        const int k0 = c * 32;
        cp16(base + so0,         g_af + aoff0 + k0);
        cp16(base + so1,         g_af + aoff1 + k0);
        cp16(base + 10240 + so0, g_pwf + woff0 + k0);
        cp16(base + 10240 + so1, g_pwf + woff1 + k0);
        CP_COMMIT();
    };

    load_chunk(0, 0);

#pragma unroll 1
    for (int c = 0; c < 16; c++) {
        CP_WAIT0();
        __syncthreads();
        if (c + 1 < 16) load_chunk(c + 1, (c + 1) & 1);

        char* st = sm + OFF_TILES + (c & 1) * P_STAGE_BYTES;
        __half* Afs = (__half*)(st);
        __half* Wfs = (__half*)(st + 10240);

#pragma unroll
        for (int kk = 0; kk < 32; kk += 16) {
            wmma::fragment<wmma::matrix_a, 16, 16, 16, __half, wmma::row_major> af[2];
#pragma unroll
            for (int i = 0; i < 2; i++)
                wmma::load_matrix_sync(af[i], Afs + (wm0 + i * 16) * TSTRIDE + kk, TSTRIDE);
#pragma unroll
            for (int j = 0; j < 4; j++) {
                wmma::fragment<wmma::matrix_b, 16, 16, 16, __half, wmma::col_major> bf;
                wmma::load_matrix_sync(bf, Wfs + (wn0 + j * 16) * TSTRIDE + kk, TSTRIDE);
#pragma unroll
                for (int i = 0; i < 2; i++)
                    wmma::mma_sync(acc[i][j], af[i], bf, acc[i][j]);
            }
        }
        __syncthreads();
    }

#pragma unroll
    for (int i = 0; i < 2; i++)
#pragma unroll
        for (int j = 0; j < 4; j++)
            wmma::store_matrix_sync(S + (wm0 + i * 16) * SSTRIDE + wn0 + j * 16,
                                    acc[i][j], SSTRIDE, wmma::mem_row_major);
    __syncthreads();

    for (int idx = tid; idx < 4096; idx += 256) {
        int mrow = idx >> 5, col = (idx & 31) * 4;
        float4 o;
        o.x = S[mrow * SSTRIDE + col + 0] * sInv[col + 0] + sSh[col + 0];
        o.y = S[mrow * SSTRIDE + col + 1] * sInv[col + 1] + sSh[col + 1];
        o.z = S[mrow * SSTRIDE + col + 2] * sInv[col + 2] + sSh[col + 2];
        o.w = S[mrow * SSTRIDE + col + 3] * sInv[col + 3] + sSh[col + 3];
        *reinterpret_cast<float4*>(Out + (size_t)(m0 + mrow) * 384 + n0 + col) = o;
    }
}

// ---------------------------------------------------------------------------
// Attention: one block per (b,h), 512 threads, 110 KB smem -> 2 CTAs/SM.
// ---------------------------------------------------------------------------
#define AT_BIAS 0
#define AT_SC   832
#define AT_X    55104
#define AT_QH   (AT_X)
#define AT_QL   (AT_X + 5120)
#define AT_KH   (AT_X + 10240)
#define AT_KL   (AT_X + 26880)
#define AT_PH   (AT_X)
#define AT_VH   (AT_X + 27648)
#define ATTN_SMEM_BYTES 112704

__global__ __launch_bounds__(512, 2)
void attn_kernel(const float* __restrict__ attn_bias)
{
    extern __shared__ char smc[];
    const uint32_t sb = smem_u32(smc);
    float* bs = (float*)(smc + AT_BIAS);
    float* sc = (float*)(smc + AT_SC);                      // [64][212]
    __nv_bfloat16* qh = (__nv_bfloat16*)(smc + AT_QH);
    __nv_bfloat16* ql = (__nv_bfloat16*)(smc + AT_QL);
    __nv_bfloat16* kh = (__nv_bfloat16*)(smc + AT_KH);
    __nv_bfloat16* kl = (__nv_bfloat16*)(smc + AT_KL);
    __half* Ph = (__half*)(smc + AT_PH);                    // [64][216]
    __half* Vh = (__half*)(smc + AT_VH);                    // [208][72]

    const int blk = blockIdx.x;           // b*8 + h
    const int h = blk & 7;
    const int tid = threadIdx.x;
    const int wid = tid >> 5, lane = tid & 31;

    // phase 0: load q, k (split bf16); zero pads; bias
    {
        const uint4* qhg = (const uint4*)(g_qh + (size_t)blk * (Qq * KDc));
        const uint4* qlg = (const uint4*)(g_ql + (size_t)blk * (Qq * KDc));
        for (int i = tid; i < 196; i += 512) {
            uint32_t d = sb + AT_QH + (i >> 2) * 80 + (i & 3) * 16;
            cp16(d, qhg + i);
            cp16(d + (AT_QL - AT_QH), qlg + i);
        }
        const uint4* khg = (const uint4*)(g_kh + (size_t)blk * (Nn * KDc));
        const uint4* klg = (const uint4*)(g_kl + (size_t)blk * (Nn * KDc));
        for (int i = tid; i < 784; i += 512) {
            uint32_t d = sb + AT_KH + (i >> 2) * 80 + (i & 3) * 16;
            cp16(d, khg + i);
            cp16(d + (AT_KL - AT_KH), klg + i);
        }
        CP_COMMIT();
        uint4 z = {0u, 0u, 0u, 0u};
        for (int i = tid; i < 75; i += 512) {
            int row = 49 + i / 5, seg = i % 5;
            *(uint4*)(smc + AT_QH + row * 80 + seg * 16) = z;
            *(uint4*)(smc + AT_QL + row * 80 + seg * 16) = z;
        }
        for (int i = tid; i < 60; i += 512) {
            int row = 196 + i / 5, seg = i % 5;
            *(uint4*)(smc + AT_KH + row * 80 + seg * 16) = z;
            *(uint4*)(smc + AT_KL + row * 80 + seg * 16) = z;
        }
        for (int i = tid; i < 196; i += 512) bs[i] = attn_bias[h * Nn + i];
        CP_WAIT0();
    }
    __syncthreads();

    // phase 1: scores = (qh+ql)@(kh+kl)^T (3 terms); 13 warps x 16-col strip
    if (wid < 13) {
        const int n0 = wid * 16;
        wmma::fragment<wmma::accumulator, 16, 16, 16, float> acc[4];
#pragma unroll
        for (int mt = 0; mt < 4; mt++) wmma::fill_fragment(acc[mt], 0.0f);
#pragma unroll
        for (int kk = 0; kk < 2; kk++) {
            wmma::fragment<wmma::matrix_b, 16, 16, 16, __nv_bfloat16, wmma::col_major> bh, bl;
            wmma::load_matrix_sync(bh, kh + n0 * 40 + kk * 16, 40);
            wmma::load_matrix_sync(bl, kl + n0 * 40 + kk * 16, 40);
#pragma unroll
            for (int mt = 0; mt < 4; mt++) {
                wmma::fragment<wmma::matrix_a, 16, 16, 16, __nv_bfloat16, wmma::row_major> ah, al;
                wmma::load_matrix_sync(ah, qh + mt * 16 * 40 + kk * 16, 40);
                wmma::load_matrix_sync(al, ql + mt * 16 * 40 + kk * 16, 40);
                wmma::mma_sync(acc[mt], ah, bh, acc[mt]);
                wmma::mma_sync(acc[mt], ah, bl, acc[mt]);
                wmma::mma_sync(acc[mt], al, bh, acc[mt]);
            }
        }
#pragma unroll
        for (int mt = 0; mt < 4; mt++)
            wmma::store_matrix_sync(sc + mt * 16 * 212 + n0, acc[mt], 212, wmma::mem_row_major);
    }
    __syncthreads();

    // phase 2: prefetch V (fp16); zero pad rows + Ph pad rows
    {
        const uint4* vfg = (const uint4*)(g_vf + (size_t)blk * (Nn * VDc));
        for (int i = tid; i < 1568; i += 512) {
            uint32_t d = sb + AT_VH + (i >> 3) * 144 + (i & 7) * 16;
            cp16(d, vfg + i);
        }
        CP_COMMIT();
        uint4 z = {0u, 0u, 0u, 0u};
        for (int i = tid; i < 108; i += 512) {
            int row = 196 + i / 9, seg = i % 9;
            *(uint4*)(smc + AT_VH + row * 144 + seg * 16) = z;
        }
        for (int i = tid; i < 405; i += 512) {
            int row = 49 + i / 27, seg = i % 27;
            *(uint4*)(smc + AT_PH + row * 432 + seg * 16) = z;
        }
    }

    // phase 3: softmax (fp32) -> Ph fp16
    for (int row = wid; row < Qq; row += 16) {
        int qi2 = 2 * (row / 7), qj2 = 2 * (row % 7);
        float mx = -1e30f;
        for (int n = lane; n < Nn; n += 32) {
            int ki = n / 14, kj = n - ki * 14;
            float val = sc[row * 212 + n] * SCALEc + bs[abs(qi2 - ki) * 14 + abs(qj2 - kj)];
            sc[row * 212 + n] = val;
            mx = fmaxf(mx, val);
        }
#pragma unroll
        for (int o = 16; o > 0; o >>= 1)
            mx = fmaxf(mx, __shfl_xor_sync(0xffffffffu, mx, o));
        float sum = 0.0f;
        for (int n = lane; n < Nn; n += 32) {
            float e = __expf(sc[row * 212 + n] - mx);
            sc[row * 212 + n] = e;
            sum += e;
        }
#pragma unroll
        for (int o = 16; o > 0; o >>= 1)
            sum += __shfl_xor_sync(0xffffffffu, sum, o);
        float rinv = 1.0f / sum;
        for (int n = lane; n < 208; n += 32) {
            float p = (n < Nn) ? sc[row * 212 + n] * rinv : 0.0f;
            Ph[row * 216 + n] = __float2half_rn(p);
        }
    }
    CP_WAIT0();
    __syncthreads();

    // phase 4: AV = Ph @ Vh; 16 warps, one 16x16 tile each
    {
        const int mi = wid >> 2, ni = wid & 3;
        wmma::fragment<wmma::accumulator, 16, 16, 16, float> acc;
        wmma::fill_fragment(acc, 0.0f);
#pragma unroll
        for (int kk = 0; kk < 13; kk++) {
            wmma::fragment<wmma::matrix_a, 16, 16, 16, __half, wmma::row_major> pf;
            wmma::fragment<wmma::matrix_b, 16, 16, 16, __half, wmma::row_major> vf;
            wmma::load_matrix_sync(pf, Ph + mi * 16 * 216 + kk * 16, 216);
            wmma::load_matrix_sync(vf, Vh + kk * 16 * 72 + ni * 16, 72);
            wmma::mma_sync(acc, pf, vf, acc);
        }
        wmma::store_matrix_sync(sc + mi * 16 * 68 + ni * 16, acc, 68, wmma::mem_row_major);
    }
    __syncthreads();

    // phase 5: hardswish + fp16 store to g_af
    {
        const int b = blk >> 3;
        for (int i = tid; i < 1568; i += 512) {
            int qr = i >> 5, vd = (i & 31) * 2;
            float t0 = sc[qr * 68 + vd];
            float t1 = sc[qr * 68 + vd + 1];
            float o0 = t0 * fminf(fmaxf(t0 + 3.0f, 0.0f), 6.0f) * (1.0f / 6.0f);
            float o1 = t1 * fminf(fmaxf(t1 + 3.0f, 0.0f), 6.0f) * (1.0f / 6.0f);
            size_t off = ((size_t)(b * Qq + qr)) * 512 + h * VDc + vd;
            *reinterpret_cast<__half2*>(g_af + off) = __floats2half2_rn(o0, o1);
        }
    }
}

// ---------------------------------------------------------------------------
extern "C" void kernel_launch(void* const* d_in, const int* in_sizes, int n_in,
                              void* d_out, int out_size)
{
    const float* x      = (const float*)d_in[0];
    const float* kv_w   = (const float*)d_in[1];
    const float* kv_g   = (const float*)d_in[2];
    const float* kv_b   = (const float*)d_in[3];
    const float* kv_m   = (const float*)d_in[4];
    const float* kv_v   = (const float*)d_in[5];
    const float* q_w    = (const float*)d_in[6];
    const float* q_g    = (const float*)d_in[7];
    const float* q_b    = (const float*)d_in[8];
    const float* q_m    = (const float*)d_in[9];
    const float* q_v    = (const float*)d_in[10];
    const float* proj_w = (const float*)d_in[11];
    const float* proj_g = (const float*)d_in[12];
    const float* proj_b = (const float*)d_in[13];
    const float* proj_m = (const float*)d_in[14];
    const float* proj_v = (const float*)d_in[15];
    const float* attn_bias = (const float*)d_in[16];
    float* out = (float*)d_out;

    split_all_kernel<<<(NX + NW1 + NW2 + NW3 + 255) / 256, 256>>>(x, kv_w, q_w, proj_w);

    cudaFuncSetAttribute(kvq_gemm_kernel, cudaFuncAttributeMaxDynamicSharedMemorySize, GEMM_SMEM_BYTES);
    cudaFuncSetAttribute(pgemm_kernel, cudaFuncAttributeMaxDynamicSharedMemorySize, PGEMM_SMEM_BYTES);
    cudaFuncSetAttribute(attn_kernel, cudaFuncAttributeMaxDynamicSharedMemorySize, ATTN_SMEM_BYTES);

    kvq_gemm_kernel<<<TOTAL_B, 256, GEMM_SMEM_BYTES>>>(
        kv_g, kv_b, kv_m, kv_v, q_g, q_b, q_m, q_v);

    attn_kernel<<<Bc * Hh, 512, ATTN_SMEM_BYTES>>>(attn_bias);

    pgemm_kernel<<<dim3(3, 98), 256, PGEMM_SMEM_BYTES>>>(proj_g, proj_b, proj_m, proj_v, out);
}

// round 12
// speedup vs baseline: 4.0872x; 1.0030x over previous
#include <cuda_runtime.h>
#include <cuda_bf16.h>
#include <cuda_fp16.h>
#include <mma.h>
#include <cstdint>

using namespace nvcuda;

// ---------------- problem constants ----------------
#define Bc   256
#define Nn   196
#define Hh   8
#define KDc  32
#define VDc  64
#define Qq   49
#define EPSc 1e-5f
#define SCALEc 0.17677669529663689f  // 32^-0.5

// ---------------- device scratch ----------------
__device__ __half g_xh[Bc*Nn*256],  g_xl[Bc*Nn*256];   // x fp16 split
__device__ __half g_kwh[256*256],   g_kwl[256*256];    // kv_w K-part, reordered, fp16 split
__device__ __half g_vwf[512*256];                      // kv_w V-part, reordered, fp16
__device__ __half g_qwh[256*256],   g_qwl[256*256];    // q_w fp16 split
__device__ __half g_pwf[384*512];                      // proj W fp16 (inv-scaled)
__device__ __half g_af[Bc*Qq*512];                     // attn out fp16
__device__ __half g_kh[Bc*Hh*Nn*KDc], g_kl[Bc*Hh*Nn*KDc];   // [bh,n,d] fp16 split
__device__ __half g_vf[Bc*Hh*Nn*VDc];                        // [bh,n,d] fp16
__device__ __half g_qh[Bc*Hh*Qq*KDc], g_ql[Bc*Hh*Qq*KDc];   // [bh,q,d] fp16 split

// ---------------- cp.async helpers ----------------
__device__ __forceinline__ void cp16(uint32_t dst, const void* src) {
    asm volatile("cp.async.cg.shared.global [%0], [%1], 16;" :: "r"(dst), "l"(src));
}
#define CP_COMMIT() asm volatile("cp.async.commit_group;" ::: "memory")
#define CP_WAIT0()  asm volatile("cp.async.wait_group 0;" ::: "memory")
#define CP_WAIT1()  asm volatile("cp.async.wait_group 1;" ::: "memory")

__device__ __forceinline__ uint32_t smem_u32(const void* p) {
    uint32_t a;
    asm("{ .reg .u64 t; cvta.to.shared.u64 t, %1; cvt.u32.u64 %0, t; }" : "=r"(a) : "l"(p));
    return a;
}

__device__ __forceinline__ void hsplit2(float v0, float v1, __half2& hv, __half2& lv) {
    __half h0 = __float2half_rn(v0);
    __half h1 = __float2half_rn(v1);
    hv = __halves2half2(h0, h1);
    lv = __halves2half2(__float2half_rn(v0 - __half2float(h0)),
                        __float2half_rn(v1 - __half2float(h1)));
}

__device__ __forceinline__ void fsplit_store4(__half* hi, __half* lo, int i, float4 t) {
    __half2 h01, l01, h23, l23;
    hsplit2(t.x, t.y, h01, l01);
    hsplit2(t.z, t.w, h23, l23);
    reinterpret_cast<__half2*>(hi)[i*2]   = h01;
    reinterpret_cast<__half2*>(hi)[i*2+1] = h23;
    reinterpret_cast<__half2*>(lo)[i*2]   = l01;
    reinterpret_cast<__half2*>(lo)[i*2+1] = l23;
}

// ---------------- fused precompute ----------------
#define NX  (Bc*Nn*256/4)
#define NW1 (768*256/4)
#define NW2 (256*256/4)
#define NW3 (384*512/4)
__global__ void split_all_kernel(const float* __restrict__ x,
                                 const float* __restrict__ kv_w,
                                 const float* __restrict__ q_w,
                                 const float* __restrict__ proj_w,
                                 const float* __restrict__ proj_g,
                                 const float* __restrict__ proj_v)
{
    int i = blockIdx.x * blockDim.x + threadIdx.x;
    if (i < NX) {
        fsplit_store4(g_xh, g_xl, i, reinterpret_cast<const float4*>(x)[i]);
    } else if (i < NX + NW1) {
        int j = i - NX;
        int r = j >> 6;          // kv_w row
        int c4 = j & 63;
        float4 t = reinterpret_cast<const float4*>(kv_w)[j];
        int h = r / 96, c = r - h * 96;
        if (c < KDc) {
            int di = (h * 32 + c) * 64 + c4;
            fsplit_store4(g_kwh, g_kwl, di, t);
        } else {
            int di = (h * 64 + (c - KDc)) * 64 + c4;
            reinterpret_cast<__half2*>(g_vwf)[di*2]   = __floats2half2_rn(t.x, t.y);
            reinterpret_cast<__half2*>(g_vwf)[di*2+1] = __floats2half2_rn(t.z, t.w);
        }
    } else if (i < NX + NW1 + NW2) {
        int j = i - NX - NW1;
        fsplit_store4(g_qwh, g_qwl, j, reinterpret_cast<const float4*>(q_w)[j]);
    } else if (i < NX + NW1 + NW2 + NW3) {
        int j = i - NX - NW1 - NW2;
        int row = j >> 7;        // 128 float4 per 512-col row
        float inv = proj_g[row] * rsqrtf(proj_v[row] + EPSc);
        float4 t = reinterpret_cast<const float4*>(proj_w)[j];
        t.x *= inv; t.y *= inv; t.z *= inv; t.w *= inv;
        reinterpret_cast<__half2*>(g_pwf)[j*2]   = __floats2half2_rn(t.x, t.y);
        reinterpret_cast<__half2*>(g_pwf)[j*2+1] = __floats2half2_rn(t.z, t.w);
    }
}

// ---------------- GEMM smem layout ----------------
#define TSTRIDE 40
#define OFF_ROW   64
#define OFF_INV   576
#define OFF_SH    1088
#define OFF_TILES 2048
#define STAGE_BYTES 40960      // 3-term path (4 tiles), 2 stages
#define V_STAGE_BYTES 20480    // 1-term path (2 tiles), 3 stages
#define OFF_STAGE 2048
#define SSTRIDE   132
#define GEMM_SMEM_BYTES (2048 + 2*STAGE_BYTES)

#define KB 784
#define VB 2352
#define TOTAL_B 2548

// ---------------------------------------------------------------------------
// Fused K/V/q GEMM. K & q: 3-term fp16-split (2-stage). V: 1-term fp16 (3-stage).
// ---------------------------------------------------------------------------
__global__ __launch_bounds__(256, 2)
void kvq_gemm_kernel(const float* __restrict__ kv_g, const float* __restrict__ kv_b,
                     const float* __restrict__ kv_m, const float* __restrict__ kv_v,
                     const float* __restrict__ q_g,  const float* __restrict__ q_b,
                     const float* __restrict__ q_m,  const float* __restrict__ q_v)
{
    extern __shared__ char sm[];
    const uint32_t sb = smem_u32(sm);
    int*   rowoff = (int*)(sm + OFF_ROW);
    float* sInv   = (float*)(sm + OFF_INV);
    float* sSh    = (float*)(sm + OFF_SH);
    float* S      = (float*)(sm + OFF_STAGE);

    const int bx = blockIdx.x;
    int mode, n0, m0;
    if (bx < KB)      { mode = 0; n0 = (bx & 1) * 128;  m0 = (bx >> 1) * 128; }
    else if (bx < VB) { int i = bx - KB; mode = 1; n0 = (i & 3) * 128; m0 = (i >> 2) * 128; }
    else              { int i = bx - VB; mode = 2; n0 = (i & 1) * 128; m0 = (i >> 1) * 128; }

    const __half *Wh, *Wl;
    if (mode == 0)      { Wh = g_kwh; Wl = g_kwl; }
    else if (mode == 1) { Wh = g_vwf; Wl = g_vwf; }
    else                { Wh = g_qwh; Wl = g_qwl; }

    const int tid = threadIdx.x;
    const int wid = tid >> 5;

    if (tid < 128) {
        int m = m0 + tid;
        int off;
        if (mode == 2) {
            int b = m / Qq, qq = m % Qq;
            int n = (qq / 7) * 28 + (qq % 7) * 2;
            off = (b * Nn + n) * 256;
        } else {
            off = m * 256;
        }
        rowoff[tid] = off;
        int jj = n0 + tid;
        int jo;
        const float *gg, *bb, *mm, *vv;
        if (mode == 0)      { jo = (jj >> 5) * 96 + (jj & 31);        gg = kv_g; bb = kv_b; mm = kv_m; vv = kv_v; }
        else if (mode == 1) { jo = (jj >> 6) * 96 + KDc + (jj & 63);  gg = kv_g; bb = kv_b; mm = kv_m; vv = kv_v; }
        else                { jo = jj;                                 gg = q_g;  bb = q_b;  mm = q_m;  vv = q_v;  }
        float inv = gg[jo] * rsqrtf(vv[jo] + EPSc);
        sInv[tid] = inv;
        sSh[tid]  = bb[jo] - mm[jo] * inv;
    }
    __syncthreads();

    const int r0 = tid >> 2,        k8 = (tid & 3) * 8;
    const int r1 = (tid + 256) >> 2;
    const int aoff0 = rowoff[r0] + k8;
    const int aoff1 = rowoff[r1] + k8;
    const int woff0 = (n0 + r0) * 256 + k8;
    const int woff1 = (n0 + r1) * 256 + k8;
    const uint32_t so0 = (uint32_t)(r0 * TSTRIDE + k8) * 2;
    const uint32_t so1 = (uint32_t)(r1 * TSTRIDE + k8) * 2;

    const int wm0 = (wid & 3) * 32;
    const int wn0 = (wid >> 2) * 64;

    wmma::fragment<wmma::accumulator, 16, 16, 16, float> acc[2][4];
#pragma unroll
    for (int i = 0; i < 2; i++)
#pragma unroll
        for (int j = 0; j < 4; j++) wmma::fill_fragment(acc[i][j], 0.0f);

    if (mode == 1) {
        // -------- 1-term fp16, 3-stage pipeline --------
        auto load1 = [&](int c, int stage) {
            const uint32_t base = sb + OFF_TILES + stage * V_STAGE_BYTES;
            const int k0 = c * 32;
            cp16(base + so0,         g_xh + aoff0 + k0);
            cp16(base + so1,         g_xh + aoff1 + k0);
            cp16(base + 10240 + so0, Wh + woff0 + k0);
            cp16(base + 10240 + so1, Wh + woff1 + k0);
            CP_COMMIT();
        };
        load1(0, 0);
        load1(1, 1);
#pragma unroll 1
        for (int c = 0; c < 8; c++) {
            if (c == 7) { CP_WAIT0(); } else { CP_WAIT1(); }
            __syncthreads();
            if (c + 2 < 8) load1(c + 2, (c + 2) % 3);
            char* st = sm + OFF_TILES + (c % 3) * V_STAGE_BYTES;
            __half* Ahs = (__half*)(st);
            __half* Wfs = (__half*)(st + 10240);
#pragma unroll
            for (int kk = 0; kk < 32; kk += 16) {
                wmma::fragment<wmma::matrix_a, 16, 16, 16, __half, wmma::row_major> af[2];
#pragma unroll
                for (int i = 0; i < 2; i++)
                    wmma::load_matrix_sync(af[i], Ahs + (wm0 + i * 16) * TSTRIDE + kk, TSTRIDE);
#pragma unroll
                for (int j = 0; j < 4; j++) {
                    wmma::fragment<wmma::matrix_b, 16, 16, 16, __half, wmma::col_major> bf;
                    wmma::load_matrix_sync(bf, Wfs + (wn0 + j * 16) * TSTRIDE + kk, TSTRIDE);
#pragma unroll
                    for (int i = 0; i < 2; i++)
                        wmma::mma_sync(acc[i][j], af[i], bf, acc[i][j]);
                }
            }
            __syncthreads();
        }
    } else {
        // -------- 3-term fp16-split, 2-stage pipeline --------
        auto load3 = [&](int c, int stage) {
            const uint32_t base = sb + OFF_TILES + stage * STAGE_BYTES;
            const int k0 = c * 32;
            cp16(base + so0,         g_xh + aoff0 + k0);
            cp16(base + so1,         g_xh + aoff1 + k0);
            cp16(base + 10240 + so0, g_xl + aoff0 + k0);
            cp16(base + 10240 + so1, g_xl + aoff1 + k0);
            cp16(base + 20480 + so0, Wh + woff0 + k0);
            cp16(base + 20480 + so1, Wh + woff1 + k0);
            cp16(base + 30720 + so0, Wl + woff0 + k0);
            cp16(base + 30720 + so1, Wl + woff1 + k0);
            CP_COMMIT();
        };
        load3(0, 0);
#pragma unroll 1
        for (int c = 0; c < 8; c++) {
            CP_WAIT0();
            __syncthreads();
            if (c + 1 < 8) load3(c + 1, (c + 1) & 1);
            char* st = sm + OFF_TILES + (c & 1) * STAGE_BYTES;
            __half* Ahs = (__half*)(st);
            __half* Als = (__half*)(st + 10240);
            __half* Bhs = (__half*)(st + 20480);
            __half* Bls = (__half*)(st + 30720);
#pragma unroll
            for (int kk = 0; kk < 32; kk += 16) {
                wmma::fragment<wmma::matrix_a, 16, 16, 16, __half, wmma::row_major> ah[2], al[2];
#pragma unroll
                for (int i = 0; i < 2; i++) {
                    wmma::load_matrix_sync(ah[i], Ahs + (wm0 + i * 16) * TSTRIDE + kk, TSTRIDE);
                    wmma::load_matrix_sync(al[i], Als + (wm0 + i * 16) * TSTRIDE + kk, TSTRIDE);
                }
#pragma unroll
                for (int j = 0; j < 4; j++) {
                    wmma::fragment<wmma::matrix_b, 16, 16, 16, __half, wmma::col_major> bh, bl;
                    wmma::load_matrix_sync(bh, Bhs + (wn0 + j * 16) * TSTRIDE + kk, TSTRIDE);
                    wmma::load_matrix_sync(bl, Bls + (wn0 + j * 16) * TSTRIDE + kk, TSTRIDE);
#pragma unroll
                    for (int i = 0; i < 2; i++) {
                        wmma::mma_sync(acc[i][j], ah[i], bh, acc[i][j]);
                        wmma::mma_sync(acc[i][j], ah[i], bl, acc[i][j]);
                        wmma::mma_sync(acc[i][j], al[i], bh, acc[i][j]);
                    }
                }
            }
            __syncthreads();
        }
    }

#pragma unroll
    for (int i = 0; i < 2; i++)
#pragma unroll
        for (int j = 0; j < 4; j++)
            wmma::store_matrix_sync(S + (wm0 + i * 16) * SSTRIDE + wn0 + j * 16,
                                    acc[i][j], SSTRIDE, wmma::mem_row_major);
    __syncthreads();

    for (int idx = tid; idx < 8192; idx += 256) {
        int mrow = idx >> 6, pair = idx & 63, col = pair * 2;
        int jj = n0 + col;
        int m = m0 + mrow;
        float v0 = S[mrow * SSTRIDE + col]     * sInv[col]     + sSh[col];
        float v1 = S[mrow * SSTRIDE + col + 1] * sInv[col + 1] + sSh[col + 1];
        if (mode == 0) {
            int h = jj >> 5, d = jj & 31;
            int b = m / Nn, n = m - b * Nn;
            __half2 hv, lv;
            hsplit2(v0, v1, hv, lv);
            size_t base = ((size_t)((b * Hh + h) * Nn + n)) * KDc + d;
            *reinterpret_cast<__half2*>(g_kh + base) = hv;
            *reinterpret_cast<__half2*>(g_kl + base) = lv;
        } else if (mode == 1) {
            int h = jj >> 6, d = jj & 63;
            int b = m / Nn, n = m - b * Nn;
            size_t base = ((size_t)((b * Hh + h) * Nn + n)) * VDc + d;
            *reinterpret_cast<__half2*>(g_vf + base) = __floats2half2_rn(v0, v1);
        } else {
            int h = jj >> 5, d = jj & 31;
            int b = m / Qq, qq = m - b * Qq;
            __half2 hv, lv;
            hsplit2(v0, v1, hv, lv);
            size_t base = ((size_t)((b * Hh + h) * Qq + qq)) * KDc + d;
            *reinterpret_cast<__half2*>(g_qh + base) = hv;
            *reinterpret_cast<__half2*>(g_ql + base) = lv;
        }
    }
}

// ---------------------------------------------------------------------------
// proj GEMM: single-term fp16, inv folded into W, 3-stage pipeline.
// ---------------------------------------------------------------------------
#define P_STAGE_BYTES 20480
#define PGEMM_SMEM_BYTES 69632

__global__ __launch_bounds__(256, 2)
void pgemm_kernel(const float* __restrict__ gg,
                  const float* __restrict__ bb,
                  const float* __restrict__ mm,
                  const float* __restrict__ vv,
                  float* __restrict__ Out)
{
    extern __shared__ char sm[];
    const uint32_t sb = smem_u32(sm);
    float* sSh  = (float*)(sm + OFF_SH);
    float* S    = (float*)(sm + OFF_STAGE);

    const int tid = threadIdx.x;
    const int wid = tid >> 5;
    const int m0 = blockIdx.y * 128;
    const int n0 = blockIdx.x * 128;

    if (tid < 128) {
        int jj = n0 + tid;
        float inv = gg[jj] * rsqrtf(vv[jj] + EPSc);
        sSh[tid]  = bb[jj] - mm[jj] * inv;
    }
    __syncthreads();

    const int r0 = tid >> 2,        k8 = (tid & 3) * 8;
    const int r1 = (tid + 256) >> 2;
    const int aoff0 = (m0 + r0) * 512 + k8;
    const int aoff1 = (m0 + r1) * 512 + k8;
    const int woff0 = (n0 + r0) * 512 + k8;
    const int woff1 = (n0 + r1) * 512 + k8;
    const uint32_t so0 = (uint32_t)(r0 * TSTRIDE + k8) * 2;
    const uint32_t so1 = (uint32_t)(r1 * TSTRIDE + k8) * 2;

    const int wm0 = (wid & 3) * 32;
    const int wn0 = (wid >> 2) * 64;

    wmma::fragment<wmma::accumulator, 16, 16, 16, float> acc[2][4];
#pragma unroll
    for (int i = 0; i < 2; i++)
#pragma unroll
        for (int j = 0; j < 4; j++) wmma::fill_fragment(acc[i][j], 0.0f);

    auto load_chunk = [&](int c, int stage) {
        const uint32_t base = sb + OFF_TILES + stage * P_STAGE_BYTES;
        const int k0 = c * 32;
        cp16(base + so0,         g_af + aoff0 + k0);
        cp16(base + so1,         g_af + aoff1 + k0);
        cp16(base + 10240 + so0, g_pwf + woff0 + k0);
        cp16(base + 10240 + so1, g_pwf + woff1 + k0);
        CP_COMMIT();
    };

    load_chunk(0, 0);
    load_chunk(1, 1);

#pragma unroll 1
    for (int c = 0; c < 16; c++) {
        if (c == 15) { CP_WAIT0(); } else { CP_WAIT1(); }
        __syncthreads();
        if (c + 2 < 16) load_chunk(c + 2, (c + 2) % 3);

        char* st = sm + OFF_TILES + (c % 3) * P_STAGE_BYTES;
        __half* Afs = (__half*)(st);
        __half* Wfs = (__half*)(st + 10240);

#pragma unroll
        for (int kk = 0; kk < 32; kk += 16) {
            wmma::fragment<wmma::matrix_a, 16, 16, 16, __half, wmma::row_major> af[2];
#pragma unroll
            for (int i = 0; i < 2; i++)
                wmma::load_matrix_sync(af[i], Afs + (wm0 + i * 16) * TSTRIDE + kk, TSTRIDE);
#pragma unroll
            for (int j = 0; j < 4; j++) {
                wmma::fragment<wmma::matrix_b, 16, 16, 16, __half, wmma::col_major> bf;
                wmma::load_matrix_sync(bf, Wfs + (wn0 + j * 16) * TSTRIDE + kk, TSTRIDE);
#pragma unroll
                for (int i = 0; i < 2; i++)
                    wmma::mma_sync(acc[i][j], af[i], bf, acc[i][j]);
            }
        }
        __syncthreads();
    }

#pragma unroll
    for (int i = 0; i < 2; i++)
#pragma unroll
        for (int j = 0; j < 4; j++)
            wmma::store_matrix_sync(S + (wm0 + i * 16) * SSTRIDE + wn0 + j * 16,
                                    acc[i][j], SSTRIDE, wmma::mem_row_major);
    __syncthreads();

    for (int idx = tid; idx < 4096; idx += 256) {
        int mrow = idx >> 5, col = (idx & 31) * 4;
        float4 o;
        o.x = S[mrow * SSTRIDE + col + 0] + sSh[col + 0];
        o.y = S[mrow * SSTRIDE + col + 1] + sSh[col + 1];
        o.z = S[mrow * SSTRIDE + col + 2] + sSh[col + 2];
        o.w = S[mrow * SSTRIDE + col + 3] + sSh[col + 3];
        *reinterpret_cast<float4*>(Out + (size_t)(m0 + mrow) * 384 + n0 + col) = o;
    }
}

// ---------------------------------------------------------------------------
// Attention: one block per (b,h), 512 threads, 110 KB smem -> 2 CTAs/SM.
// ---------------------------------------------------------------------------
#define AT_BIAS 0
#define AT_SC   832
#define AT_X    55104
#define AT_QH   (AT_X)
#define AT_QL   (AT_X + 5120)
#define AT_KH   (AT_X + 10240)
#define AT_KL   (AT_X + 26880)
#define AT_PH   (AT_X)
#define AT_VH   (AT_X + 27648)
#define ATTN_SMEM_BYTES 112704

__global__ __launch_bounds__(512, 2)
void attn_kernel(const float* __restrict__ attn_bias)
{
    extern __shared__ char smc[];
    const uint32_t sb = smem_u32(smc);
    float* bs = (float*)(smc + AT_BIAS);
    float* sc = (float*)(smc + AT_SC);                      // [64][212]
    __half* qh = (__half*)(smc + AT_QH);
    __half* ql = (__half*)(smc + AT_QL);
    __half* kh = (__half*)(smc + AT_KH);
    __half* kl = (__half*)(smc + AT_KL);
    __half* Ph = (__half*)(smc + AT_PH);                    // [64][216]
    __half* Vh = (__half*)(smc + AT_VH);                    // [208][72]

    const int blk = blockIdx.x;           // b*8 + h
    const int h = blk & 7;
    const int tid = threadIdx.x;
    const int wid = tid >> 5, lane = tid & 31;

    // phase 0: load q, k (fp16 split); zero pads; bias
    {
        const uint4* qhg = (const uint4*)(g_qh + (size_t)blk * (Qq * KDc));
        const uint4* qlg = (const uint4*)(g_ql + (size_t)blk * (Qq * KDc));
        for (int i = tid; i < 196; i += 512) {
            uint32_t d = sb + AT_QH + (i >> 2) * 80 + (i & 3) * 16;
            cp16(d, qhg + i);
            cp16(d + (AT_QL - AT_QH), qlg + i);
        }
        const uint4* khg = (const uint4*)(g_kh + (size_t)blk * (Nn * KDc));
        const uint4* klg = (const uint4*)(g_kl + (size_t)blk * (Nn * KDc));
        for (int i = tid; i < 784; i += 512) {
            uint32_t d = sb + AT_KH + (i >> 2) * 80 + (i & 3) * 16;
            cp16(d, khg + i);
            cp16(d + (AT_KL - AT_KH), klg + i);
        }
        CP_COMMIT();
        uint4 z = {0u, 0u, 0u, 0u};
        for (int i = tid; i < 75; i += 512) {
            int row = 49 + i / 5, seg = i % 5;
            *(uint4*)(smc + AT_QH + row * 80 + seg * 16) = z;
            *(uint4*)(smc + AT_QL + row * 80 + seg * 16) = z;
        }
        for (int i = tid; i < 60; i += 512) {
            int row = 196 + i / 5, seg = i % 5;
            *(uint4*)(smc + AT_KH + row * 80 + seg * 16) = z;
            *(uint4*)(smc + AT_KL + row * 80 + seg * 16) = z;
        }
        for (int i = tid; i < 196; i += 512) bs[i] = attn_bias[h * Nn + i];
        CP_WAIT0();
    }
    __syncthreads();

    // phase 1: scores = (qh+ql)@(kh+kl)^T (3 terms); 13 warps x 16-col strip
    if (wid < 13) {
        const int n0 = wid * 16;
        wmma::fragment<wmma::accumulator, 16, 16, 16, float> acc[4];
#pragma unroll
        for (int mt = 0; mt < 4; mt++) wmma::fill_fragment(acc[mt], 0.0f);
#pragma unroll
        for (int kk = 0; kk < 2; kk++) {
            wmma::fragment<wmma::matrix_b, 16, 16, 16, __half, wmma::col_major> bh, bl;
            wmma::load_matrix_sync(bh, kh + n0 * 40 + kk * 16, 40);
            wmma::load_matrix_sync(bl, kl + n0 * 40 + kk * 16, 40);
#pragma unroll
            for (int mt = 0; mt < 4; mt++) {
                wmma::fragment<wmma::matrix_a, 16, 16, 16, __half, wmma::row_major> ah, al;
                wmma::load_matrix_sync(ah, qh + mt * 16 * 40 + kk * 16, 40);
                wmma::load_matrix_sync(al, ql + mt * 16 * 40 + kk * 16, 40);
                wmma::mma_sync(acc[mt], ah, bh, acc[mt]);
                wmma::mma_sync(acc[mt], ah, bl, acc[mt]);
                wmma::mma_sync(acc[mt], al, bh, acc[mt]);
            }
        }
#pragma unroll
        for (int mt = 0; mt < 4; mt++)
            wmma::store_matrix_sync(sc + mt * 16 * 212 + n0, acc[mt], 212, wmma::mem_row_major);
    }
    __syncthreads();

    // phase 2: prefetch V (fp16); zero pad rows + Ph pad rows
    {
        const uint4* vfg = (const uint4*)(g_vf + (size_t)blk * (Nn * VDc));
        for (int i = tid; i < 1568; i += 512) {
            uint32_t d = sb + AT_VH + (i >> 3) * 144 + (i & 7) * 16;
            cp16(d, vfg + i);
        }
        CP_COMMIT();
        uint4 z = {0u, 0u, 0u, 0u};
        for (int i = tid; i < 108; i += 512) {
            int row = 196 + i / 9, seg = i % 9;
            *(uint4*)(smc + AT_VH + row * 144 + seg * 16) = z;
        }
        for (int i = tid; i < 405; i += 512) {
            int row = 49 + i / 27, seg = i % 27;
            *(uint4*)(smc + AT_PH + row * 432 + seg * 16) = z;
        }
    }

    // phase 3: softmax (fp32) -> Ph fp16
    for (int row = wid; row < Qq; row += 16) {
        int qi2 = 2 * (row / 7), qj2 = 2 * (row % 7);
        float mx = -1e30f;
        for (int n = lane; n < Nn; n += 32) {
            int ki = n / 14, kj = n - ki * 14;
            float val = sc[row * 212 + n] * SCALEc + bs[abs(qi2 - ki) * 14 + abs(qj2 - kj)];
            sc[row * 212 + n] = val;
            mx = fmaxf(mx, val);
        }
#pragma unroll
        for (int o = 16; o > 0; o >>= 1)
            mx = fmaxf(mx, __shfl_xor_sync(0xffffffffu, mx, o));
        float sum = 0.0f;
        for (int n = lane; n < Nn; n += 32) {
            float e = __expf(sc[row * 212 + n] - mx);
            sc[row * 212 + n] = e;
            sum += e;
        }
#pragma unroll
        for (int o = 16; o > 0; o >>= 1)
            sum += __shfl_xor_sync(0xffffffffu, sum, o);
        float rinv = 1.0f / sum;
        for (int n = lane; n < 208; n += 32) {
            float p = (n < Nn) ? sc[row * 212 + n] * rinv : 0.0f;
            Ph[row * 216 + n] = __float2half_rn(p);
        }
    }
    CP_WAIT0();
    __syncthreads();

    // phase 4: AV = Ph @ Vh; 16 warps, one 16x16 tile each
    {
        const int mi = wid >> 2, ni = wid & 3;
        wmma::fragment<wmma::accumulator, 16, 16, 16, float> acc;
        wmma::fill_fragment(acc, 0.0f);
#pragma unroll
        for (int kk = 0; kk < 13; kk++) {
            wmma::fragment<wmma::matrix_a, 16, 16, 16, __half, wmma::row_major> pf;
            wmma::fragment<wmma::matrix_b, 16, 16, 16, __half, wmma::row_major> vf;
            wmma::load_matrix_sync(pf, Ph + mi * 16 * 216 + kk * 16, 216);
            wmma::load_matrix_sync(vf, Vh + kk * 16 * 72 + ni * 16, 72);
            wmma::mma_sync(acc, pf, vf, acc);
        }
        wmma::store_matrix_sync(sc + mi * 16 * 68 + ni * 16, acc, 68, wmma::mem_row_major);
    }
    __syncthreads();

    // phase 5: hardswish + fp16 store to g_af
    {
        const int b = blk >> 3;
        for (int i = tid; i < 1568; i += 512) {
            int qr = i >> 5, vd = (i & 31) * 2;
            float t0 = sc[qr * 68 + vd];
            float t1 = sc[qr * 68 + vd + 1];
            float o0 = t0 * fminf(fmaxf(t0 + 3.0f, 0.0f), 6.0f) * (1.0f / 6.0f);
            float o1 = t1 * fminf(fmaxf(t1 + 3.0f, 0.0f), 6.0f) * (1.0f / 6.0f);
            size_t off = ((size_t)(b * Qq + qr)) * 512 + h * VDc + vd;
            *reinterpret_cast<__half2*>(g_af + off) = __floats2half2_rn(o0, o1);
        }
    }
}

// ---------------------------------------------------------------------------
extern "C" void kernel_launch(void* const* d_in, const int* in_sizes, int n_in,
                              void* d_out, int out_size)
{
    const float* x      = (const float*)d_in[0];
    const float* kv_w   = (const float*)d_in[1];
    const float* kv_g   = (const float*)d_in[2];
    const float* kv_b   = (const float*)d_in[3];
    const float* kv_m   = (const float*)d_in[4];
    const float* kv_v   = (const float*)d_in[5];
    const float* q_w    = (const float*)d_in[6];
    const float* q_g    = (const float*)d_in[7];
    const float* q_b    = (const float*)d_in[8];
    const float* q_m    = (const float*)d_in[9];
    const float* q_v    = (const float*)d_in[10];
    const float* proj_w = (const float*)d_in[11];
    const float* proj_g = (const float*)d_in[12];
    const float* proj_b = (const float*)d_in[13];
    const float* proj_m = (const float*)d_in[14];
    const float* proj_v = (const float*)d_in[15];
    const float* attn_bias = (const float*)d_in[16];
    float* out = (float*)d_out;

    split_all_kernel<<<(NX + NW1 + NW2 + NW3 + 255) / 256, 256>>>(
        x, kv_w, q_w, proj_w, proj_g, proj_v);

    cudaFuncSetAttribute(kvq_gemm_kernel, cudaFuncAttributeMaxDynamicSharedMemorySize, GEMM_SMEM_BYTES);
    cudaFuncSetAttribute(pgemm_kernel, cudaFuncAttributeMaxDynamicSharedMemorySize, PGEMM_SMEM_BYTES);
    cudaFuncSetAttribute(attn_kernel, cudaFuncAttributeMaxDynamicSharedMemorySize, ATTN_SMEM_BYTES);

    kvq_gemm_kernel<<<TOTAL_B, 256, GEMM_SMEM_BYTES>>>(
        kv_g, kv_b, kv_m, kv_v, q_g, q_b, q_m, q_v);

    attn_kernel<<<Bc * Hh, 512, ATTN_SMEM_BYTES>>>(attn_bias);

    pgemm_kernel<<<dim3(3, 98), 256, PGEMM_SMEM_BYTES>>>(proj_g, proj_b, proj_m, proj_v, out);
}

// round 13
// speedup vs baseline: 4.4400x; 1.0863x over previous
#include <cuda_runtime.h>
#include <cuda_bf16.h>
#include <cuda_fp16.h>
#include <mma.h>
#include <cstdint>

using namespace nvcuda;

// ---------------- problem constants ----------------
#define Bc   256
#define Nn   196
#define Hh   8
#define KDc  32
#define VDc  64
#define Qq   49
#define EPSc 1e-5f
#define SCALEc 0.17677669529663689f  // 32^-0.5

// ---------------- device scratch ----------------
__device__ __half g_xh[Bc*Nn*256];                     // x fp16 (single)
__device__ __half g_kwh[256*256],   g_kwl[256*256];    // kv_w K-part, reordered, fp16 split
__device__ __half g_vwf[512*256];                      // kv_w V-part, reordered, fp16
__device__ __half g_qwh[256*256],   g_qwl[256*256];    // q_w fp16 split
__device__ __half g_pwf[384*512];                      // proj W fp16 (inv-scaled)
__device__ __half g_af[Bc*Qq*512];                     // attn out fp16
__device__ __half g_kh[Bc*Hh*Nn*KDc], g_kl[Bc*Hh*Nn*KDc];   // [bh,n,d] fp16 split
__device__ __half g_vf[Bc*Hh*Nn*VDc];                        // [bh,n,d] fp16
__device__ __half g_qh[Bc*Hh*Qq*KDc], g_ql[Bc*Hh*Qq*KDc];   // [bh,q,d] fp16 split (SCALEc folded)

// ---------------- cp.async helpers ----------------
__device__ __forceinline__ void cp16(uint32_t dst, const void* src) {
    asm volatile("cp.async.cg.shared.global [%0], [%1], 16;" :: "r"(dst), "l"(src));
}
#define CP_COMMIT() asm volatile("cp.async.commit_group;" ::: "memory")
#define CP_WAIT0()  asm volatile("cp.async.wait_group 0;" ::: "memory")

__device__ __forceinline__ uint32_t smem_u32(const void* p) {
    uint32_t a;
    asm("{ .reg .u64 t; cvta.to.shared.u64 t, %1; cvt.u32.u64 %0, t; }" : "=r"(a) : "l"(p));
    return a;
}

__device__ __forceinline__ void hsplit2(float v0, float v1, __half2& hv, __half2& lv) {
    __half h0 = __float2half_rn(v0);
    __half h1 = __float2half_rn(v1);
    hv = __halves2half2(h0, h1);
    lv = __halves2half2(__float2half_rn(v0 - __half2float(h0)),
                        __float2half_rn(v1 - __half2float(h1)));
}

__device__ __forceinline__ void fsplit_store4(__half* hi, __half* lo, int i, float4 t) {
    __half2 h01, l01, h23, l23;
    hsplit2(t.x, t.y, h01, l01);
    hsplit2(t.z, t.w, h23, l23);
    reinterpret_cast<__half2*>(hi)[i*2]   = h01;
    reinterpret_cast<__half2*>(hi)[i*2+1] = h23;
    reinterpret_cast<__half2*>(lo)[i*2]   = l01;
    reinterpret_cast<__half2*>(lo)[i*2+1] = l23;
}

// ---------------- fused precompute ----------------
#define NX  (Bc*Nn*256/4)
#define NW1 (768*256/4)
#define NW2 (256*256/4)
#define NW3 (384*512/4)
__global__ void split_all_kernel(const float* __restrict__ x,
                                 const float* __restrict__ kv_w,
                                 const float* __restrict__ q_w,
                                 const float* __restrict__ proj_w,
                                 const float* __restrict__ proj_g,
                                 const float* __restrict__ proj_v)
{
    int i = blockIdx.x * blockDim.x + threadIdx.x;
    if (i < NX) {
        float4 t = reinterpret_cast<const float4*>(x)[i];
        reinterpret_cast<__half2*>(g_xh)[i*2]   = __floats2half2_rn(t.x, t.y);
        reinterpret_cast<__half2*>(g_xh)[i*2+1] = __floats2half2_rn(t.z, t.w);
    } else if (i < NX + NW1) {
        int j = i - NX;
        int r = j >> 6;          // kv_w row
        int c4 = j & 63;
        float4 t = reinterpret_cast<const float4*>(kv_w)[j];
        int h = r / 96, c = r - h * 96;
        if (c < KDc) {
            int di = (h * 32 + c) * 64 + c4;
            fsplit_store4(g_kwh, g_kwl, di, t);
        } else {
            int di = (h * 64 + (c - KDc)) * 64 + c4;
            reinterpret_cast<__half2*>(g_vwf)[di*2]   = __floats2half2_rn(t.x, t.y);
            reinterpret_cast<__half2*>(g_vwf)[di*2+1] = __floats2half2_rn(t.z, t.w);
        }
    } else if (i < NX + NW1 + NW2) {
        int j = i - NX - NW1;
        fsplit_store4(g_qwh, g_qwl, j, reinterpret_cast<const float4*>(q_w)[j]);
    } else if (i < NX + NW1 + NW2 + NW3) {
        int j = i - NX - NW1 - NW2;
        int row = j >> 7;        // 128 float4 per 512-col row
        float inv = proj_g[row] * rsqrtf(proj_v[row] + EPSc);
        float4 t = reinterpret_cast<const float4*>(proj_w)[j];
        t.x *= inv; t.y *= inv; t.z *= inv; t.w *= inv;
        reinterpret_cast<__half2*>(g_pwf)[j*2]   = __floats2half2_rn(t.x, t.y);
        reinterpret_cast<__half2*>(g_pwf)[j*2+1] = __floats2half2_rn(t.z, t.w);
    }
}

// ---------------- GEMM smem layout ----------------
#define TSTRIDE 40
#define OFF_ROW   64
#define OFF_INV   576
#define OFF_SH    1088
#define OFF_TILES 2048
#define KQ_STAGE_BYTES 30720   // 2-term: Ah | Bh | Bl
#define V_STAGE_BYTES  20480   // 1-term: Ah | Wf
#define OFF_STAGE 2048
#define SSTRIDE   132
#define GEMM_SMEM_BYTES 69632  // max(2048+2*30720, 2048+128*132*4)

#define KB 784
#define VB 2352
#define TOTAL_B 2548

// ---------------------------------------------------------------------------
// Fused K/V/q GEMM, 512 threads, 32x32 warp tiles (4x4 warp grid), 2 CTAs/SM.
// K & q: 2-term (Ah*Bh + Ah*Bl). V: 1-term fp16.
// ---------------------------------------------------------------------------
__global__ __launch_bounds__(512, 2)
void kvq_gemm_kernel(const float* __restrict__ kv_g, const float* __restrict__ kv_b,
                     const float* __restrict__ kv_m, const float* __restrict__ kv_v,
                     const float* __restrict__ q_g,  const float* __restrict__ q_b,
                     const float* __restrict__ q_m,  const float* __restrict__ q_v)
{
    extern __shared__ char sm[];
    const uint32_t sb = smem_u32(sm);
    int*   rowoff = (int*)(sm + OFF_ROW);
    float* sInv   = (float*)(sm + OFF_INV);
    float* sSh    = (float*)(sm + OFF_SH);
    float* S      = (float*)(sm + OFF_STAGE);

    const int bx = blockIdx.x;
    int mode, n0, m0;
    if (bx < KB)      { mode = 0; n0 = (bx & 1) * 128;  m0 = (bx >> 1) * 128; }
    else if (bx < VB) { int i = bx - KB; mode = 1; n0 = (i & 3) * 128; m0 = (i >> 2) * 128; }
    else              { int i = bx - VB; mode = 2; n0 = (i & 1) * 128; m0 = (i >> 1) * 128; }

    const __half *Wh, *Wl;
    if (mode == 0)      { Wh = g_kwh; Wl = g_kwl; }
    else if (mode == 1) { Wh = g_vwf; Wl = g_vwf; }
    else                { Wh = g_qwh; Wl = g_qwl; }

    const int tid = threadIdx.x;
    const int wid = tid >> 5;

    if (tid < 128) {
        int m = m0 + tid;
        int off;
        if (mode == 2) {
            int b = m / Qq, qq = m % Qq;
            int n = (qq / 7) * 28 + (qq % 7) * 2;
            off = (b * Nn + n) * 256;
        } else {
            off = m * 256;
        }
        rowoff[tid] = off;
        int jj = n0 + tid;
        int jo;
        const float *gg, *bb, *mm, *vv;
        if (mode == 0)      { jo = (jj >> 5) * 96 + (jj & 31);        gg = kv_g; bb = kv_b; mm = kv_m; vv = kv_v; }
        else if (mode == 1) { jo = (jj >> 6) * 96 + KDc + (jj & 63);  gg = kv_g; bb = kv_b; mm = kv_m; vv = kv_v; }
        else                { jo = jj;                                 gg = q_g;  bb = q_b;  mm = q_m;  vv = q_v;  }
        float inv = gg[jo] * rsqrtf(vv[jo] + EPSc);
        float sh  = bb[jo] - mm[jo] * inv;
        if (mode == 2) { inv *= SCALEc; sh *= SCALEc; }   // fold attention scale into q
        sInv[tid] = inv;
        sSh[tid]  = sh;
    }
    __syncthreads();

    // loader: one float4 segment per thread per matrix (128 rows x 4 segs = 512)
    const int r = tid >> 2, k8 = (tid & 3) * 8;
    const int aoff = rowoff[r] + k8;
    const int woff = (n0 + r) * 256 + k8;
    const uint32_t so = (uint32_t)(r * TSTRIDE + k8) * 2;

    const int wm0 = (wid & 3) * 32;
    const int wn0 = (wid >> 2) * 32;

    wmma::fragment<wmma::accumulator, 16, 16, 16, float> acc[2][2];
#pragma unroll
    for (int i = 0; i < 2; i++)
#pragma unroll
        for (int j = 0; j < 2; j++) wmma::fill_fragment(acc[i][j], 0.0f);

    if (mode == 1) {
        // -------- 1-term fp16 --------
        auto load1 = [&](int c, int stage) {
            const uint32_t base = sb + OFF_TILES + stage * V_STAGE_BYTES;
            const int k0 = c * 32;
            cp16(base + so,         g_xh + aoff + k0);
            cp16(base + 10240 + so, Wh + woff + k0);
            CP_COMMIT();
        };
        load1(0, 0);
#pragma unroll 1
        for (int c = 0; c < 8; c++) {
            CP_WAIT0();
            __syncthreads();
            if (c + 1 < 8) load1(c + 1, (c + 1) & 1);
            char* st = sm + OFF_TILES + (c & 1) * V_STAGE_BYTES;
            __half* Ahs = (__half*)(st);
            __half* Wfs = (__half*)(st + 10240);
#pragma unroll
            for (int kk = 0; kk < 32; kk += 16) {
#pragma unroll
                for (int j = 0; j < 2; j++) {
                    wmma::fragment<wmma::matrix_b, 16, 16, 16, __half, wmma::col_major> bf;
                    wmma::load_matrix_sync(bf, Wfs + (wn0 + j * 16) * TSTRIDE + kk, TSTRIDE);
#pragma unroll
                    for (int i = 0; i < 2; i++) {
                        wmma::fragment<wmma::matrix_a, 16, 16, 16, __half, wmma::row_major> af;
                        wmma::load_matrix_sync(af, Ahs + (wm0 + i * 16) * TSTRIDE + kk, TSTRIDE);
                        wmma::mma_sync(acc[i][j], af, bf, acc[i][j]);
                    }
                }
            }
            __syncthreads();
        }
    } else {
        // -------- 2-term: Ah*Bh + Ah*Bl --------
        auto load2 = [&](int c, int stage) {
            const uint32_t base = sb + OFF_TILES + stage * KQ_STAGE_BYTES;
            const int k0 = c * 32;
            cp16(base + so,         g_xh + aoff + k0);
            cp16(base + 10240 + so, Wh + woff + k0);
            cp16(base + 20480 + so, Wl + woff + k0);
            CP_COMMIT();
        };
        load2(0, 0);
#pragma unroll 1
        for (int c = 0; c < 8; c++) {
            CP_WAIT0();
            __syncthreads();
            if (c + 1 < 8) load2(c + 1, (c + 1) & 1);
            char* st = sm + OFF_TILES + (c & 1) * KQ_STAGE_BYTES;
            __half* Ahs = (__half*)(st);
            __half* Bhs = (__half*)(st + 10240);
            __half* Bls = (__half*)(st + 20480);
#pragma unroll
            for (int kk = 0; kk < 32; kk += 16) {
#pragma unroll
                for (int j = 0; j < 2; j++) {
                    wmma::fragment<wmma::matrix_b, 16, 16, 16, __half, wmma::col_major> bh, bl;
                    wmma::load_matrix_sync(bh, Bhs + (wn0 + j * 16) * TSTRIDE + kk, TSTRIDE);
                    wmma::load_matrix_sync(bl, Bls + (wn0 + j * 16) * TSTRIDE + kk, TSTRIDE);
#pragma unroll
                    for (int i = 0; i < 2; i++) {
                        wmma::fragment<wmma::matrix_a, 16, 16, 16, __half, wmma::row_major> af;
                        wmma::load_matrix_sync(af, Ahs + (wm0 + i * 16) * TSTRIDE + kk, TSTRIDE);
                        wmma::mma_sync(acc[i][j], af, bh, acc[i][j]);
                        wmma::mma_sync(acc[i][j], af, bl, acc[i][j]);
                    }
                }
            }
            __syncthreads();
        }
    }

#pragma unroll
    for (int i = 0; i < 2; i++)
#pragma unroll
        for (int j = 0; j < 2; j++)
            wmma::store_matrix_sync(S + (wm0 + i * 16) * SSTRIDE + wn0 + j * 16,
                                    acc[i][j], SSTRIDE, wmma::mem_row_major);
    __syncthreads();

    for (int idx = tid; idx < 8192; idx += 512) {
        int mrow = idx >> 6, pair = idx & 63, col = pair * 2;
        int jj = n0 + col;
        int m = m0 + mrow;
        float v0 = S[mrow * SSTRIDE + col]     * sInv[col]     + sSh[col];
        float v1 = S[mrow * SSTRIDE + col + 1] * sInv[col + 1] + sSh[col + 1];
        if (mode == 0) {
            int h = jj >> 5, d = jj & 31;
            int b = m / Nn, n = m - b * Nn;
            __half2 hv, lv;
            hsplit2(v0, v1, hv, lv);
            size_t base = ((size_t)((b * Hh + h) * Nn + n)) * KDc + d;
            *reinterpret_cast<__half2*>(g_kh + base) = hv;
            *reinterpret_cast<__half2*>(g_kl + base) = lv;
        } else if (mode == 1) {
            int h = jj >> 6, d = jj & 63;
            int b = m / Nn, n = m - b * Nn;
            size_t base = ((size_t)((b * Hh + h) * Nn + n)) * VDc + d;
            *reinterpret_cast<__half2*>(g_vf + base) = __floats2half2_rn(v0, v1);
        } else {
            int h = jj >> 5, d = jj & 31;
            int b = m / Qq, qq = m - b * Qq;
            __half2 hv, lv;
            hsplit2(v0, v1, hv, lv);
            size_t base = ((size_t)((b * Hh + h) * Qq + qq)) * KDc + d;
            *reinterpret_cast<__half2*>(g_qh + base) = hv;
            *reinterpret_cast<__half2*>(g_ql + base) = lv;
        }
    }
}

// ---------------------------------------------------------------------------
// proj GEMM: single-term fp16, 512 threads, 32x32 warp tiles, inv folded into W.
// ---------------------------------------------------------------------------
#define P_STAGE_BYTES 20480
#define PGEMM_SMEM_BYTES 69632

__global__ __launch_bounds__(512, 2)
void pgemm_kernel(const float* __restrict__ gg,
                  const float* __restrict__ bb,
                  const float* __restrict__ mm,
                  const float* __restrict__ vv,
                  float* __restrict__ Out)
{
    extern __shared__ char sm[];
    const uint32_t sb = smem_u32(sm);
    float* sSh  = (float*)(sm + OFF_SH);
    float* S    = (float*)(sm + OFF_STAGE);

    const int tid = threadIdx.x;
    const int wid = tid >> 5;
    const int m0 = blockIdx.y * 128;
    const int n0 = blockIdx.x * 128;

    if (tid < 128) {
        int jj = n0 + tid;
        float inv = gg[jj] * rsqrtf(vv[jj] + EPSc);
        sSh[tid]  = bb[jj] - mm[jj] * inv;
    }
    __syncthreads();

    const int r = tid >> 2, k8 = (tid & 3) * 8;
    const int aoff = (m0 + r) * 512 + k8;
    const int woff = (n0 + r) * 512 + k8;
    const uint32_t so = (uint32_t)(r * TSTRIDE + k8) * 2;

    const int wm0 = (wid & 3) * 32;
    const int wn0 = (wid >> 2) * 32;

    wmma::fragment<wmma::accumulator, 16, 16, 16, float> acc[2][2];
#pragma unroll
    for (int i = 0; i < 2; i++)
#pragma unroll
        for (int j = 0; j < 2; j++) wmma::fill_fragment(acc[i][j], 0.0f);

    auto load_chunk = [&](int c, int stage) {
        const uint32_t base = sb + OFF_TILES + stage * P_STAGE_BYTES;
        const int k0 = c * 32;
        cp16(base + so,         g_af + aoff + k0);
        cp16(base + 10240 + so, g_pwf + woff + k0);
        CP_COMMIT();
    };

    load_chunk(0, 0);

#pragma unroll 1
    for (int c = 0; c < 16; c++) {
        CP_WAIT0();
        __syncthreads();
        if (c + 1 < 16) load_chunk(c + 1, (c + 1) & 1);

        char* st = sm + OFF_TILES + (c & 1) * P_STAGE_BYTES;
        __half* Afs = (__half*)(st);
        __half* Wfs = (__half*)(st + 10240);

#pragma unroll
        for (int kk = 0; kk < 32; kk += 16) {
#pragma unroll
            for (int j = 0; j < 2; j++) {
                wmma::fragment<wmma::matrix_b, 16, 16, 16, __half, wmma::col_major> bf;
                wmma::load_matrix_sync(bf, Wfs + (wn0 + j * 16) * TSTRIDE + kk, TSTRIDE);
#pragma unroll
                for (int i = 0; i < 2; i++) {
                    wmma::fragment<wmma::matrix_a, 16, 16, 16, __half, wmma::row_major> af;
                    wmma::load_matrix_sync(af, Afs + (wm0 + i * 16) * TSTRIDE + kk, TSTRIDE);
                    wmma::mma_sync(acc[i][j], af, bf, acc[i][j]);
                }
            }
        }
        __syncthreads();
    }

#pragma unroll
    for (int i = 0; i < 2; i++)
#pragma unroll
        for (int j = 0; j < 2; j++)
            wmma::store_matrix_sync(S + (wm0 + i * 16) * SSTRIDE + wn0 + j * 16,
                                    acc[i][j], SSTRIDE, wmma::mem_row_major);
    __syncthreads();

    for (int idx = tid; idx < 4096; idx += 512) {
        int mrow = idx >> 5, col = (idx & 31) * 4;
        float4 o;
        o.x = S[mrow * SSTRIDE + col + 0] + sSh[col + 0];
        o.y = S[mrow * SSTRIDE + col + 1] + sSh[col + 1];
        o.z = S[mrow * SSTRIDE + col + 2] + sSh[col + 2];
        o.w = S[mrow * SSTRIDE + col + 3] + sSh[col + 3];
        *reinterpret_cast<float4*>(Out + (size_t)(m0 + mrow) * 384 + n0 + col) = o;
    }
}

// ---------------------------------------------------------------------------
// Attention: one block per (b,h), 512 threads, 110 KB smem -> 2 CTAs/SM.
// (q pre-scaled by SCALEc in kvq epilogue.)
// ---------------------------------------------------------------------------
#define AT_BIAS 0
#define AT_SC   832
#define AT_X    55104
#define AT_QH   (AT_X)
#define AT_QL   (AT_X + 5120)
#define AT_KH   (AT_X + 10240)
#define AT_KL   (AT_X + 26880)
#define AT_PH   (AT_X)
#define AT_VH   (AT_X + 27648)
#define ATTN_SMEM_BYTES 112704

__global__ __launch_bounds__(512, 2)
void attn_kernel(const float* __restrict__ attn_bias)
{
    extern __shared__ char smc[];
    const uint32_t sb = smem_u32(smc);
    float* bs = (float*)(smc + AT_BIAS);
    float* sc = (float*)(smc + AT_SC);                      // [64][212]
    __half* qh = (__half*)(smc + AT_QH);
    __half* ql = (__half*)(smc + AT_QL);
    __half* kh = (__half*)(smc + AT_KH);
    __half* kl = (__half*)(smc + AT_KL);
    __half* Ph = (__half*)(smc + AT_PH);                    // [64][216]
    __half* Vh = (__half*)(smc + AT_VH);                    // [208][72]

    const int blk = blockIdx.x;           // b*8 + h
    const int h = blk & 7;
    const int tid = threadIdx.x;
    const int wid = tid >> 5, lane = tid & 31;

    // phase 0: load q, k (fp16 split); zero pads; bias
    {
        const uint4* qhg = (const uint4*)(g_qh + (size_t)blk * (Qq * KDc));
        const uint4* qlg = (const uint4*)(g_ql + (size_t)blk * (Qq * KDc));
        for (int i = tid; i < 196; i += 512) {
            uint32_t d = sb + AT_QH + (i >> 2) * 80 + (i & 3) * 16;
            cp16(d, qhg + i);
            cp16(d + (AT_QL - AT_QH), qlg + i);
        }
        const uint4* khg = (const uint4*)(g_kh + (size_t)blk * (Nn * KDc));
        const uint4* klg = (const uint4*)(g_kl + (size_t)blk * (Nn * KDc));
        for (int i = tid; i < 784; i += 512) {
            uint32_t d = sb + AT_KH + (i >> 2) * 80 + (i & 3) * 16;
            cp16(d, khg + i);
            cp16(d + (AT_KL - AT_KH), klg + i);
        }
        CP_COMMIT();
        uint4 z = {0u, 0u, 0u, 0u};
        for (int i = tid; i < 75; i += 512) {
            int row = 49 + i / 5, seg = i % 5;
            *(uint4*)(smc + AT_QH + row * 80 + seg * 16) = z;
            *(uint4*)(smc + AT_QL + row * 80 + seg * 16) = z;
        }
        for (int i = tid; i < 60; i += 512) {
            int row = 196 + i / 5, seg = i % 5;
            *(uint4*)(smc + AT_KH + row * 80 + seg * 16) = z;
            *(uint4*)(smc + AT_KL + row * 80 + seg * 16) = z;
        }
        for (int i = tid; i < 196; i += 512) bs[i] = attn_bias[h * Nn + i];
        CP_WAIT0();
    }
    __syncthreads();

    // phase 1: scores = (qh+ql)@(kh+kl)^T (3 terms); 13 warps x 16-col strip
    if (wid < 13) {
        const int n0 = wid * 16;
        wmma::fragment<wmma::accumulator, 16, 16, 16, float> acc[4];
#pragma unroll
        for (int mt = 0; mt < 4; mt++) wmma::fill_fragment(acc[mt], 0.0f);
#pragma unroll
        for (int kk = 0; kk < 2; kk++) {
            wmma::fragment<wmma::matrix_b, 16, 16, 16, __half, wmma::col_major> bh, bl;
            wmma::load_matrix_sync(bh, kh + n0 * 40 + kk * 16, 40);
            wmma::load_matrix_sync(bl, kl + n0 * 40 + kk * 16, 40);
#pragma unroll
            for (int mt = 0; mt < 4; mt++) {
                wmma::fragment<wmma::matrix_a, 16, 16, 16, __half, wmma::row_major> ah, al;
                wmma::load_matrix_sync(ah, qh + mt * 16 * 40 + kk * 16, 40);
                wmma::load_matrix_sync(al, ql + mt * 16 * 40 + kk * 16, 40);
                wmma::mma_sync(acc[mt], ah, bh, acc[mt]);
                wmma::mma_sync(acc[mt], ah, bl, acc[mt]);
                wmma::mma_sync(acc[mt], al, bh, acc[mt]);
            }
        }
#pragma unroll
        for (int mt = 0; mt < 4; mt++)
            wmma::store_matrix_sync(sc + mt * 16 * 212 + n0, acc[mt], 212, wmma::mem_row_major);
    }
    __syncthreads();

    // phase 2: prefetch V (fp16); zero pad rows + Ph pad rows
    {
        const uint4* vfg = (const uint4*)(g_vf + (size_t)blk * (Nn * VDc));
        for (int i = tid; i < 1568; i += 512) {
            uint32_t d = sb + AT_VH + (i >> 3) * 144 + (i & 7) * 16;
            cp16(d, vfg + i);
        }
        CP_COMMIT();
        uint4 z = {0u, 0u, 0u, 0u};
        for (int i = tid; i < 108; i += 512) {
            int row = 196 + i / 9, seg = i % 9;
            *(uint4*)(smc + AT_VH + row * 144 + seg * 16) = z;
        }
        for (int i = tid; i < 405; i += 512) {
            int row = 49 + i / 27, seg = i % 27;
            *(uint4*)(smc + AT_PH + row * 432 + seg * 16) = z;
        }
    }

    // phase 3: softmax (fp32) -> Ph fp16 (SCALEc already folded into q)
    for (int row = wid; row < Qq; row += 16) {
        int qi2 = 2 * (row / 7), qj2 = 2 * (row % 7);
        float mx = -1e30f;
        for (int n = lane; n < Nn; n += 32) {
            int ki = n / 14, kj = n - ki * 14;
            float val = sc[row * 212 + n] + bs[abs(qi2 - ki) * 14 + abs(qj2 - kj)];
            sc[row * 212 + n] = val;
            mx = fmaxf(mx, val);
        }
#pragma unroll
        for (int o = 16; o > 0; o >>= 1)
            mx = fmaxf(mx, __shfl_xor_sync(0xffffffffu, mx, o));
        float sum = 0.0f;
        for (int n = lane; n < Nn; n += 32) {
            float e = __expf(sc[row * 212 + n] - mx);
            sc[row * 212 + n] = e;
            sum += e;
        }
#pragma unroll
        for (int o = 16; o > 0; o >>= 1)
            sum += __shfl_xor_sync(0xffffffffu, sum, o);
        float rinv = 1.0f / sum;
        for (int n = lane; n < 208; n += 32) {
            float p = (n < Nn) ? sc[row * 212 + n] * rinv : 0.0f;
            Ph[row * 216 + n] = __float2half_rn(p);
        }
    }
    CP_WAIT0();
    __syncthreads();

    // phase 4: AV = Ph @ Vh; 16 warps, one 16x16 tile each
    {
        const int mi = wid >> 2, ni = wid & 3;
        wmma::fragment<wmma::accumulator, 16, 16, 16, float> acc;
        wmma::fill_fragment(acc, 0.0f);
#pragma unroll
        for (int kk = 0; kk < 13; kk++) {
            wmma::fragment<wmma::matrix_a, 16, 16, 16, __half, wmma::row_major> pf;
            wmma::fragment<wmma::matrix_b, 16, 16, 16, __half, wmma::row_major> vf;
            wmma::load_matrix_sync(pf, Ph + mi * 16 * 216 + kk * 16, 216);
            wmma::load_matrix_sync(vf, Vh + kk * 16 * 72 + ni * 16, 72);
            wmma::mma_sync(acc, pf, vf, acc);
        }
        wmma::store_matrix_sync(sc + mi * 16 * 68 + ni * 16, acc, 68, wmma::mem_row_major);
    }
    __syncthreads();

    // phase 5: hardswish + fp16 store to g_af
    {
        const int b = blk >> 3;
        for (int i = tid; i < 1568; i += 512) {
            int qr = i >> 5, vd = (i & 31) * 2;
            float t0 = sc[qr * 68 + vd];
            float t1 = sc[qr * 68 + vd + 1];
            float o0 = t0 * fminf(fmaxf(t0 + 3.0f, 0.0f), 6.0f) * (1.0f / 6.0f);
            float o1 = t1 * fminf(fmaxf(t1 + 3.0f, 0.0f), 6.0f) * (1.0f / 6.0f);
            size_t off = ((size_t)(b * Qq + qr)) * 512 + h * VDc + vd;
            *reinterpret_cast<__half2*>(g_af + off) = __floats2half2_rn(o0, o1);
        }
    }
}

// ---------------------------------------------------------------------------
extern "C" void kernel_launch(void* const* d_in, const int* in_sizes, int n_in,
                              void* d_out, int out_size)
{
    const float* x      = (const float*)d_in[0];
    const float* kv_w   = (const float*)d_in[1];
    const float* kv_g   = (const float*)d_in[2];
    const float* kv_b   = (const float*)d_in[3];
    const float* kv_m   = (const float*)d_in[4];
    const float* kv_v   = (const float*)d_in[5];
    const float* q_w    = (const float*)d_in[6];
    const float* q_g    = (const float*)d_in[7];
    const float* q_b    = (const float*)d_in[8];
    const float* q_m    = (const float*)d_in[9];
    const float* q_v    = (const float*)d_in[10];
    const float* proj_w = (const float*)d_in[11];
    const float* proj_g = (const float*)d_in[12];
    const float* proj_b = (const float*)d_in[13];
    const float* proj_m = (const float*)d_in[14];
    const float* proj_v = (const float*)d_in[15];
    const float* attn_bias = (const float*)d_in[16];
    float* out = (float*)d_out;

    split_all_kernel<<<(NX + NW1 + NW2 + NW3 + 255) / 256, 256>>>(
        x, kv_w, q_w, proj_w, proj_g, proj_v);

    cudaFuncSetAttribute(kvq_gemm_kernel, cudaFuncAttributeMaxDynamicSharedMemorySize, GEMM_SMEM_BYTES);
    cudaFuncSetAttribute(pgemm_kernel, cudaFuncAttributeMaxDynamicSharedMemorySize, PGEMM_SMEM_BYTES);
    cudaFuncSetAttribute(attn_kernel, cudaFuncAttributeMaxDynamicSharedMemorySize, ATTN_SMEM_BYTES);

    kvq_gemm_kernel<<<TOTAL_B, 512, GEMM_SMEM_BYTES>>>(
        kv_g, kv_b, kv_m, kv_v, q_g, q_b, q_m, q_v);

    attn_kernel<<<Bc * Hh, 512, ATTN_SMEM_BYTES>>>(attn_bias);

    pgemm_kernel<<<dim3(3, 98), 512, PGEMM_SMEM_BYTES>>>(proj_g, proj_b, proj_m, proj_v, out);
}